// round 8
// baseline (speedup 1.0000x reference)
#include <cuda_runtime.h>
#include <cuda_bf16.h>
#include <math.h>
#include <stdint.h>

typedef __nv_bfloat16 bf16;

#define SEQ 2048
#define DM  4096
#define NH  16
#define DH  256
#define DFF 16384

// GEMM tiling: CTA 128x256, BK=32, 8 warps (2x4), warp tile 64x64, 4-stage
#define BM 128
#define BN 256
#define BK 32
#define A_TILE_B 8192                 // 128 rows x 64B (one component)
#define B_TILE_B 16384                // 256 rows x 64B
#define STAGE_B  (2 * A_TILE_B + 2 * B_TILE_B)   // 48KB
#define GEMM_SMEM (4 * STAGE_B)                  // 192KB

// ---------------------------------------------------------------------------
// Device-global scratch
// ---------------------------------------------------------------------------
__device__ bf16 g_xnh[SEQ*DM], g_xnl[SEQ*DM];
__device__ bf16 g_qh[SEQ*DM], g_ql[SEQ*DM], g_kh[SEQ*DM], g_kl[SEQ*DM];
__device__ bf16 g_vth[(size_t)DM*SEQ], g_vtl[(size_t)DM*SEQ];
__device__ float g_logits[(size_t)NH*SEQ*SEQ];
__device__ bf16 g_wgh[(size_t)NH*SEQ*SEQ], g_wgl[(size_t)NH*SEQ*SEQ];
__device__ bf16 g_avh[SEQ*DM], g_avl[SEQ*DM];
__device__ float g_attnout[SEQ*DM];
__device__ bf16 g_ffh[(size_t)SEQ*DFF], g_ffl[(size_t)SEQ*DFF];
__device__ float g_ropetab[SEQ * 64];
__device__ bf16 g_wqth[(size_t)DM*DM],  g_wqtl[(size_t)DM*DM];
__device__ bf16 g_wkth[(size_t)DM*DM],  g_wktl[(size_t)DM*DM];
__device__ bf16 g_wvth[(size_t)DM*DM],  g_wvtl[(size_t)DM*DM];
__device__ bf16 g_woth[(size_t)DM*DM],  g_wotl[(size_t)DM*DM];
__device__ bf16 g_w1th[(size_t)DFF*DM], g_w1tl[(size_t)DFF*DM];
__device__ bf16 g_w2th[(size_t)DM*DFF], g_w2tl[(size_t)DM*DFF];

// ---------------------------------------------------------------------------
// PTX helpers
// ---------------------------------------------------------------------------
__device__ __forceinline__ uint32_t smem_u32(const void* p) {
    uint32_t r;
    asm("{ .reg .u64 t; cvta.to.shared.u64 t, %1; cvt.u32.u64 %0, t; }" : "=r"(r) : "l"(p));
    return r;
}
__device__ __forceinline__ void cp16(uint32_t dst, const void* src) {
    asm volatile("cp.async.cg.shared.global [%0], [%1], 16;" :: "r"(dst), "l"(src));
}
#define CP_COMMIT() asm volatile("cp.async.commit_group;")
#define CP_WAIT(n)  asm volatile("cp.async.wait_group %0;" :: "n"(n))

#define LDMX4(r, a) \
    asm volatile("ldmatrix.sync.aligned.m8n8.x4.shared.b16 {%0,%1,%2,%3}, [%4];" \
        : "=r"((r)[0]), "=r"((r)[1]), "=r"((r)[2]), "=r"((r)[3]) : "r"(a))

#define MMA16816(c, a, b0, b1) \
    asm volatile("mma.sync.aligned.m16n8k16.row.col.f32.bf16.bf16.f32 " \
        "{%0,%1,%2,%3}, {%4,%5,%6,%7}, {%8,%9}, {%0,%1,%2,%3};" \
        : "+f"((c)[0]), "+f"((c)[1]), "+f"((c)[2]), "+f"((c)[3]) \
        : "r"((a)[0]), "r"((a)[1]), "r"((a)[2]), "r"((a)[3]), \
          "r"(b0), "r"(b1))

__device__ __forceinline__ void split_store(float v, bf16* ph, bf16* pl, size_t idx) {
    bf16 h = __float2bfloat16(v);
    ph[idx] = h;
    pl[idx] = __float2bfloat16(v - __bfloat162float(h));
}

// Epilogues (compile-time)
#define EPI_F32       0
#define EPI_SCALE     1
#define EPI_HILO      2
#define EPI_GELU_HILO 3
#define EPI_BIAS_ADD  4
#define EPI_ROPE_HILO 5
// Causal modes (compile-time)
#define CM_NONE   0
#define CM_LOGITS 1
#define CM_AV     2

__device__ __forceinline__ float gelu_tanh(float v) {
    const float c = 0.7978845608028654f;
    float t = tanhf(c * (v + 0.044715f * v * v * v));
    return 0.5f * v * (1.0f + t);
}

// ---------------------------------------------------------------------------
// Split-bf16 tensor-core GEMM: C[M,N] = A @ B^T, template-specialized epilogue
// A[M,K] row-major hi/lo bf16; B[N,K] row-major hi/lo bf16; fp32 accumulate.
// 4-stage cp.async pipeline, one __syncthreads per K-chunk.
// ---------------------------------------------------------------------------
template<int EPI, int CMODE>
__global__ void __launch_bounds__(256, 1) gemm_bf16x3(
    const bf16* __restrict__ Ah, const bf16* __restrict__ Al, int lda, unsigned long long sA,
    const bf16* __restrict__ Bh, const bf16* __restrict__ Bl, int ldb, unsigned long long sB,
    int K,
    float* __restrict__ Cf, bf16* __restrict__ Ch, bf16* __restrict__ Cl,
    int ldc, unsigned long long sC,
    const float* __restrict__ bias, const float* __restrict__ addv, float scale,
    const float* __restrict__ ropetab)
{
    int bm = blockIdx.y * BM;
    int bn = blockIdx.x * BN;
    if (CMODE == CM_LOGITS && bn >= bm + BM) return;

    Ah += (size_t)blockIdx.z * sA;  Al += (size_t)blockIdx.z * sA;
    Bh += (size_t)blockIdx.z * sB;  Bl += (size_t)blockIdx.z * sB;
    size_t coff = (size_t)blockIdx.z * sC;

    extern __shared__ char smem[];
    uint32_t sb = smem_u32(smem);
    int tid = threadIdx.x;
    int wid = tid >> 5, lane = tid & 31;
    int warp_m = wid >> 2, warp_n = wid & 3;

    int a_r  = ((lane >> 3) & 1) * 8 + (lane & 7);
    int a_cb = (lane >> 4) * 16;
    int b_r  = (lane >> 4) * 8 + (lane & 7);
    int b_cb = ((lane >> 3) & 1) * 16;

    float acc[4][8][4];
    #pragma unroll
    for (int i = 0; i < 4; i++)
        #pragma unroll
        for (int j = 0; j < 8; j++)
            #pragma unroll
            for (int e = 0; e < 4; e++) acc[i][j][e] = 0.f;

    // 64B rows, SW64 swizzle: off = row*64 + ((c*16) ^ ((row*8)&0x30))
#define LOAD_CHUNK(k0, bufb) do {                                              \
        _Pragma("unroll")                                                      \
        for (int t = 0; t < 2; t++) {                                          \
            int ch = tid + t * 256;                                            \
            int row = ch >> 2, c = ch & 3;                                     \
            uint32_t off = row * 64 + ((c * 16) ^ ((row * 8) & 0x30));         \
            cp16((bufb) + off,            Ah + (size_t)(bm + row) * lda + (k0) + c * 8); \
            cp16((bufb) + A_TILE_B + off, Al + (size_t)(bm + row) * lda + (k0) + c * 8); \
        }                                                                      \
        _Pragma("unroll")                                                      \
        for (int t = 0; t < 4; t++) {                                          \
            int ch = tid + t * 256;                                            \
            int row = ch >> 2, c = ch & 3;                                     \
            uint32_t off = row * 64 + ((c * 16) ^ ((row * 8) & 0x30));         \
            cp16((bufb) + 2*A_TILE_B + off,            Bh + (size_t)(bn + row) * ldb + (k0) + c * 8); \
            cp16((bufb) + 2*A_TILE_B + B_TILE_B + off, Bl + (size_t)(bn + row) * ldb + (k0) + c * 8); \
        }                                                                      \
    } while (0)

    int Keff = (CMODE == CM_AV) ? (bm + BM) : K;
    int nk = Keff / BK;     // >= 4 for all our shapes

    LOAD_CHUNK(0,      sb);               CP_COMMIT();
    LOAD_CHUNK(BK,     sb + STAGE_B);     CP_COMMIT();
    LOAD_CHUNK(2 * BK, sb + 2 * STAGE_B); CP_COMMIT();

    for (int i = 0; i < nk; i++) {
        CP_WAIT(2);
        __syncthreads();   // stage i ready; all warps done with stage (i-1)
        uint32_t bufb = sb + (uint32_t)(i & 3) * STAGE_B;
        if (i + 3 < nk)
            LOAD_CHUNK((i + 3) * BK, sb + (uint32_t)((i + 3) & 3) * STAGE_B);
        CP_COMMIT();

        #pragma unroll
        for (int ks = 0; ks < 2; ks++) {
            uint32_t ahf[4][4], alf[4][4];
            #pragma unroll
            for (int mt = 0; mt < 4; mt++) {
                int row = warp_m * 64 + mt * 16 + a_r;
                uint32_t cb = ks * 32 + a_cb;
                uint32_t off = row * 64 + (cb ^ ((row * 8) & 0x30));
                LDMX4(ahf[mt], bufb + off);
                LDMX4(alf[mt], bufb + A_TILE_B + off);
            }
            uint32_t bhf[8][2], blf[8][2];
            #pragma unroll
            for (int p = 0; p < 4; p++) {
                int row = warp_n * 64 + p * 16 + b_r;
                uint32_t cb = ks * 32 + b_cb;
                uint32_t off = row * 64 + (cb ^ ((row * 8) & 0x30));
                uint32_t r[4];
                LDMX4(r, bufb + 2 * A_TILE_B + off);
                bhf[2*p][0] = r[0]; bhf[2*p][1] = r[1];
                bhf[2*p+1][0] = r[2]; bhf[2*p+1][1] = r[3];
                LDMX4(r, bufb + 2 * A_TILE_B + B_TILE_B + off);
                blf[2*p][0] = r[0]; blf[2*p][1] = r[1];
                blf[2*p+1][0] = r[2]; blf[2*p+1][1] = r[3];
            }
            #pragma unroll
            for (int mt = 0; mt < 4; mt++)
                #pragma unroll
                for (int nt = 0; nt < 8; nt++) {
                    MMA16816(acc[mt][nt], ahf[mt], bhf[nt][0], bhf[nt][1]);
                    MMA16816(acc[mt][nt], ahf[mt], blf[nt][0], blf[nt][1]);
                    MMA16816(acc[mt][nt], alf[mt], bhf[nt][0], bhf[nt][1]);
                }
        }
    }
#undef LOAD_CHUNK

    // Epilogue (template-pruned)
    int g = lane >> 2, tg = lane & 3;
    #pragma unroll
    for (int mt = 0; mt < 4; mt++) {
        #pragma unroll
        for (int nt = 0; nt < 8; nt++) {
            int row0 = bm + warp_m * 64 + mt * 16 + g;
            int col  = bn + warp_n * 64 + nt * 8 + tg * 2;
            float* a = acc[mt][nt];
            #pragma unroll
            for (int half = 0; half < 2; half++) {
                int row = row0 + half * 8;
                float v0 = a[half * 2 + 0], v1 = a[half * 2 + 1];
                size_t idx = coff + (size_t)row * ldc + col;
                if (EPI == EPI_F32) {
                    *(float2*)(Cf + idx) = make_float2(v0, v1);
                } else if (EPI == EPI_SCALE) {
                    *(float2*)(Cf + idx) = make_float2(v0 * scale, v1 * scale);
                } else if (EPI == EPI_HILO) {
                    bf16 h0 = __float2bfloat16(v0), h1 = __float2bfloat16(v1);
                    __nv_bfloat162 hp; hp.x = h0; hp.y = h1;
                    __nv_bfloat162 lp;
                    lp.x = __float2bfloat16(v0 - __bfloat162float(h0));
                    lp.y = __float2bfloat16(v1 - __bfloat162float(h1));
                    *(__nv_bfloat162*)(Ch + idx) = hp;
                    *(__nv_bfloat162*)(Cl + idx) = lp;
                } else if (EPI == EPI_GELU_HILO) {
                    float g0 = gelu_tanh(v0 + bias[col]);
                    float g1 = gelu_tanh(v1 + bias[col + 1]);
                    bf16 h0 = __float2bfloat16(g0), h1 = __float2bfloat16(g1);
                    __nv_bfloat162 hp; hp.x = h0; hp.y = h1;
                    __nv_bfloat162 lp;
                    lp.x = __float2bfloat16(g0 - __bfloat162float(h0));
                    lp.y = __float2bfloat16(g1 - __bfloat162float(h1));
                    *(__nv_bfloat162*)(Ch + idx) = hp;
                    *(__nv_bfloat162*)(Cl + idx) = lp;
                } else if (EPI == EPI_ROPE_HILO) {
                    int d = col & (DH - 1);
                    if (d < 64) {
                        float s = ropetab[row * 64 + d];
                        float c = ropetab[row * 64 + d + 1];
                        float n0 = v0 * c - v1 * s;
                        float n1 = v1 * c + v0 * s;
                        v0 = n0; v1 = n1;
                    }
                    bf16 h0 = __float2bfloat16(v0), h1 = __float2bfloat16(v1);
                    __nv_bfloat162 hp; hp.x = h0; hp.y = h1;
                    __nv_bfloat162 lp;
                    lp.x = __float2bfloat16(v0 - __bfloat162float(h0));
                    lp.y = __float2bfloat16(v1 - __bfloat162float(h1));
                    *(__nv_bfloat162*)(Ch + idx) = hp;
                    *(__nv_bfloat162*)(Cl + idx) = lp;
                } else { // EPI_BIAS_ADD
                    float2 av = *(const float2*)(addv + idx);
                    *(float2*)(Cf + idx) = make_float2(v0 + bias[col] + av.x,
                                                       v1 + bias[col + 1] + av.y);
                }
            }
        }
    }
}

// ---------------------------------------------------------------------------
// RoPE sin/cos table (fp64): tab[t*64+2i]=sin, tab[t*64+2i+1]=cos
// ---------------------------------------------------------------------------
__global__ void ropetab_kernel(float* __restrict__ tab)
{
    int idx = blockIdx.x * 256 + threadIdx.x;
    if (idx >= SEQ * 32) return;
    int i = idx & 31, t = idx >> 5;
    double inv = exp(-(double)i * (9.210340371976184 / 32.0));
    double s, c;
    sincos((double)t * inv, &s, &c);
    tab[t * 64 + 2 * i]     = (float)s;
    tab[t * 64 + 2 * i + 1] = (float)c;
}

// ---------------------------------------------------------------------------
// LayerNorm -> hi/lo bf16
// ---------------------------------------------------------------------------
__global__ void ln_kernel(const float* __restrict__ x,
                          const float* __restrict__ scale,
                          const float* __restrict__ offset,
                          bf16* __restrict__ xh, bf16* __restrict__ xl)
{
    __shared__ float red[256];
    int row = blockIdx.x;
    int tid = threadIdx.x;
    const float* xr = x + (size_t)row * DM;

    float s = 0.f;
    for (int i = tid; i < DM; i += 256) s += xr[i];
    red[tid] = s; __syncthreads();
    for (int o = 128; o > 0; o >>= 1) { if (tid < o) red[tid] += red[tid + o]; __syncthreads(); }
    float mean = red[0] / (float)DM;
    __syncthreads();

    float v = 0.f;
    for (int i = tid; i < DM; i += 256) { float d = xr[i] - mean; v += d * d; }
    red[tid] = v; __syncthreads();
    for (int o = 128; o > 0; o >>= 1) { if (tid < o) red[tid] += red[tid + o]; __syncthreads(); }
    float r = rsqrtf(red[0] / (float)DM + 1e-5f);

    for (int i = tid; i < DM; i += 256) {
        float y = scale[i] * r * (xr[i] - mean) + offset[i];
        split_store(y, xh, xl, (size_t)row * DM + i);
    }
}

// ---------------------------------------------------------------------------
// Transpose + hi/lo convert: 64x64 tiles, float4 loads, bf162 stores
// ---------------------------------------------------------------------------
__global__ void transcvt_kernel(const float* __restrict__ in, int R, int C,
                                bf16* __restrict__ oh, bf16* __restrict__ ol)
{
    __shared__ float t[64][65];
    int c0 = blockIdx.x * 64;
    int r0 = blockIdx.y * 64;
    int tid = threadIdx.x;
    #pragma unroll
    for (int p = 0; p < 4; p++) {
        int f = tid + p * 256;
        int row = f >> 4, c4 = (f & 15) * 4;
        float4 v = *(const float4*)(in + (size_t)(r0 + row) * C + c0 + c4);
        t[row][c4 + 0] = v.x; t[row][c4 + 1] = v.y;
        t[row][c4 + 2] = v.z; t[row][c4 + 3] = v.w;
    }
    __syncthreads();
    #pragma unroll
    for (int p = 0; p < 8; p++) {
        int w = tid + p * 256;
        int c = w >> 5, rp = (w & 31) * 2;
        float v0 = t[rp][c], v1 = t[rp + 1][c];
        size_t idx = (size_t)(c0 + c) * R + r0 + rp;
        bf16 h0 = __float2bfloat16(v0), h1 = __float2bfloat16(v1);
        __nv_bfloat162 hp; hp.x = h0; hp.y = h1;
        __nv_bfloat162 lp;
        lp.x = __float2bfloat16(v0 - __bfloat162float(h0));
        lp.y = __float2bfloat16(v1 - __bfloat162float(h1));
        *(__nv_bfloat162*)(oh + idx) = hp;
        *(__nv_bfloat162*)(ol + idx) = lp;
    }
}

// ---------------------------------------------------------------------------
// Causal softmax: row cached in smem, zero-fill to 128-block end
// ---------------------------------------------------------------------------
__global__ void softmax_kernel(const float* __restrict__ logits,
                               const float* __restrict__ attn_bias,
                               bf16* __restrict__ wh, bf16* __restrict__ wl)
{
    __shared__ float rowbuf[SEQ];
    __shared__ float red[256];
    int t = blockIdx.x;
    int h = blockIdx.y;
    int tid = threadIdx.x;
    size_t base = ((size_t)h * SEQ + t) * SEQ;
    const float* brow = attn_bias + (size_t)t * SEQ;
    int n = t + 1;
    int blockend = ((t >> 7) + 1) << 7;

    float m = -INFINITY;
    for (int T = tid; T < n; T += 256) {
        float l = logits[base + T] + brow[T];
        rowbuf[T] = l;
        m = fmaxf(m, l);
    }
    red[tid] = m; __syncthreads();
    for (int o = 128; o > 0; o >>= 1) { if (tid < o) red[tid] = fmaxf(red[tid], red[tid + o]); __syncthreads(); }
    m = red[0]; __syncthreads();

    float s = 0.f;
    for (int T = tid; T < n; T += 256) {
        float e = expf(rowbuf[T] - m);
        rowbuf[T] = e;
        s += e;
    }
    red[tid] = s; __syncthreads();
    for (int o = 128; o > 0; o >>= 1) { if (tid < o) red[tid] += red[tid + o]; __syncthreads(); }
    float inv = 1.0f / red[0];

    for (int T = tid; T < n; T += 256)
        split_store(rowbuf[T] * inv, wh, wl, base + T);
    for (int T = n + tid; T < blockend; T += 256) {
        wh[base + T] = __float2bfloat16(0.f);
        wl[base + T] = __float2bfloat16(0.f);
    }
}

// ---------------------------------------------------------------------------
// Launcher
// ---------------------------------------------------------------------------
extern "C" void kernel_launch(void* const* d_in, const int* in_sizes, int n_in,
                              void* d_out, int out_size)
{
    const float* x         = (const float*)d_in[0];
    const float* attn_bias = (const float*)d_in[1];
    const float* ln_scale  = (const float*)d_in[2];
    const float* ln_offset = (const float*)d_in[3];
    const float* wq        = (const float*)d_in[4];
    const float* wk        = (const float*)d_in[5];
    const float* wv        = (const float*)d_in[6];
    const float* wo        = (const float*)d_in[7];
    const float* w1        = (const float*)d_in[8];
    const float* b1        = (const float*)d_in[9];
    const float* w2        = (const float*)d_in[10];
    const float* b2        = (const float*)d_in[11];
    float* out = (float*)d_out;

    cudaFuncSetAttribute(gemm_bf16x3<EPI_F32, CM_NONE>,       cudaFuncAttributeMaxDynamicSharedMemorySize, GEMM_SMEM);
    cudaFuncSetAttribute(gemm_bf16x3<EPI_ROPE_HILO, CM_NONE>, cudaFuncAttributeMaxDynamicSharedMemorySize, GEMM_SMEM);
    cudaFuncSetAttribute(gemm_bf16x3<EPI_HILO, CM_NONE>,      cudaFuncAttributeMaxDynamicSharedMemorySize, GEMM_SMEM);
    cudaFuncSetAttribute(gemm_bf16x3<EPI_SCALE, CM_LOGITS>,   cudaFuncAttributeMaxDynamicSharedMemorySize, GEMM_SMEM);
    cudaFuncSetAttribute(gemm_bf16x3<EPI_HILO, CM_AV>,        cudaFuncAttributeMaxDynamicSharedMemorySize, GEMM_SMEM);
    cudaFuncSetAttribute(gemm_bf16x3<EPI_GELU_HILO, CM_NONE>, cudaFuncAttributeMaxDynamicSharedMemorySize, GEMM_SMEM);
    cudaFuncSetAttribute(gemm_bf16x3<EPI_BIAS_ADD, CM_NONE>,  cudaFuncAttributeMaxDynamicSharedMemorySize, GEMM_SMEM);

    bf16 *xnh, *xnl, *qh, *ql, *kh, *kl, *vth, *vtl, *wgh, *wgl, *avh, *avl, *ffh, *ffl;
    bf16 *wqth, *wqtl, *wkth, *wktl, *wvth, *wvtl, *woth, *wotl, *w1th, *w1tl, *w2th, *w2tl;
    float *logits, *attnout, *ropetab;
    cudaGetSymbolAddress((void**)&xnh, g_xnh);   cudaGetSymbolAddress((void**)&xnl, g_xnl);
    cudaGetSymbolAddress((void**)&qh, g_qh);     cudaGetSymbolAddress((void**)&ql, g_ql);
    cudaGetSymbolAddress((void**)&kh, g_kh);     cudaGetSymbolAddress((void**)&kl, g_kl);
    cudaGetSymbolAddress((void**)&vth, g_vth);   cudaGetSymbolAddress((void**)&vtl, g_vtl);
    cudaGetSymbolAddress((void**)&logits, g_logits);
    cudaGetSymbolAddress((void**)&wgh, g_wgh);   cudaGetSymbolAddress((void**)&wgl, g_wgl);
    cudaGetSymbolAddress((void**)&avh, g_avh);   cudaGetSymbolAddress((void**)&avl, g_avl);
    cudaGetSymbolAddress((void**)&attnout, g_attnout);
    cudaGetSymbolAddress((void**)&ffh, g_ffh);   cudaGetSymbolAddress((void**)&ffl, g_ffl);
    cudaGetSymbolAddress((void**)&ropetab, g_ropetab);
    cudaGetSymbolAddress((void**)&wqth, g_wqth); cudaGetSymbolAddress((void**)&wqtl, g_wqtl);
    cudaGetSymbolAddress((void**)&wkth, g_wkth); cudaGetSymbolAddress((void**)&wktl, g_wktl);
    cudaGetSymbolAddress((void**)&wvth, g_wvth); cudaGetSymbolAddress((void**)&wvtl, g_wvtl);
    cudaGetSymbolAddress((void**)&woth, g_woth); cudaGetSymbolAddress((void**)&wotl, g_wotl);
    cudaGetSymbolAddress((void**)&w1th, g_w1th); cudaGetSymbolAddress((void**)&w1tl, g_w1tl);
    cudaGetSymbolAddress((void**)&w2th, g_w2th); cudaGetSymbolAddress((void**)&w2tl, g_w2tl);

    // rope table + weight prep
    ropetab_kernel<<<(SEQ * 32 + 255) / 256, 256>>>(ropetab);
    transcvt_kernel<<<dim3(DM / 64, DM / 64), 256>>>(wq, DM, DM, wqth, wqtl);
    transcvt_kernel<<<dim3(DM / 64, DM / 64), 256>>>(wk, DM, DM, wkth, wktl);
    transcvt_kernel<<<dim3(DM / 64, DM / 64), 256>>>(wv, DM, DM, wvth, wvtl);
    transcvt_kernel<<<dim3(DM / 64, DM / 64), 256>>>(wo, DM, DM, woth, wotl);
    transcvt_kernel<<<dim3(DFF / 64, DM / 64), 256>>>(w1, DM, DFF, w1th, w1tl);
    transcvt_kernel<<<dim3(DM / 64, DFF / 64), 256>>>(w2, DFF, DM, w2th, w2tl);

    ln_kernel<<<SEQ, 256>>>(x, ln_scale, ln_offset, xnh, xnl);

    // Q, K (rope fused) projections
    dim3 gProj(DM / BN, SEQ / BM, 1);
    gemm_bf16x3<EPI_ROPE_HILO, CM_NONE><<<gProj, 256, GEMM_SMEM>>>(
        xnh, xnl, DM, 0, wqth, wqtl, DM, 0, DM,
        nullptr, qh, ql, DM, 0, nullptr, nullptr, 1.f, ropetab);
    gemm_bf16x3<EPI_ROPE_HILO, CM_NONE><<<gProj, 256, GEMM_SMEM>>>(
        xnh, xnl, DM, 0, wkth, wktl, DM, 0, DM,
        nullptr, kh, kl, DM, 0, nullptr, nullptr, 1.f, ropetab);

    // vt[DM,SEQ] = wv^T @ xn^T computed directly: A=wvt, B=xn
    dim3 gVT(SEQ / BN, DM / BM, 1);
    gemm_bf16x3<EPI_HILO, CM_NONE><<<gVT, 256, GEMM_SMEM>>>(
        wvth, wvtl, DM, 0, xnh, xnl, DM, 0, DM,
        nullptr, vth, vtl, SEQ, 0, nullptr, nullptr, 1.f, nullptr);

    // logits[h] = q_h @ k_h^T / 16 (skip fully masked tiles)
    dim3 gLog(SEQ / BN, SEQ / BM, NH);
    gemm_bf16x3<EPI_SCALE, CM_LOGITS><<<gLog, 256, GEMM_SMEM>>>(
        qh, ql, DM, DH, kh, kl, DM, DH, DH,
        logits, nullptr, nullptr, SEQ, (unsigned long long)SEQ * SEQ,
        nullptr, nullptr, 0.0625f, nullptr);

    softmax_kernel<<<dim3(SEQ, NH), 256>>>(logits, attn_bias, wgh, wgl);

    // attn_vec[h] = W_h @ v_h  (variable K)
    dim3 gAV(DH / BN, SEQ / BM, NH);
    gemm_bf16x3<EPI_HILO, CM_AV><<<gAV, 256, GEMM_SMEM>>>(
        wgh, wgl, SEQ, (unsigned long long)SEQ * SEQ,
        vth, vtl, SEQ, (unsigned long long)DH * SEQ, SEQ,
        nullptr, avh, avl, DM, DH, nullptr, nullptr, 1.f, nullptr);

    gemm_bf16x3<EPI_F32, CM_NONE><<<gProj, 256, GEMM_SMEM>>>(
        avh, avl, DM, 0, woth, wotl, DM, 0, DM,
        attnout, nullptr, nullptr, DM, 0, nullptr, nullptr, 1.f, nullptr);

    dim3 gFF1(DFF / BN, SEQ / BM, 1);
    gemm_bf16x3<EPI_GELU_HILO, CM_NONE><<<gFF1, 256, GEMM_SMEM>>>(
        xnh, xnl, DM, 0, w1th, w1tl, DM, 0, DM,
        nullptr, ffh, ffl, DFF, 0, b1, nullptr, 1.f, nullptr);

    dim3 gFF2(DM / BN, SEQ / BM, 1);
    gemm_bf16x3<EPI_BIAS_ADD, CM_NONE><<<gFF2, 256, GEMM_SMEM>>>(
        ffh, ffl, DFF, 0, w2th, w2tl, DFF, 0, DFF,
        out, nullptr, nullptr, DM, 0, b2, attnout, 1.f, nullptr);
}

// round 9
// speedup vs baseline: 1.0946x; 1.0946x over previous
#include <cuda_runtime.h>
#include <cuda_bf16.h>
#include <math.h>
#include <stdint.h>

typedef __nv_bfloat16 bf16;

#define SEQ 2048
#define DM  4096
#define NH  16
#define DH  256
#define DFF 16384

// GEMM tiling: CTA 128x256, BK=64, 8 warps (2x4), warp tile 64x64, 2-stage
#define BM 128
#define BN 256
#define BK 64
#define A_TILE_B 16384
#define B_TILE_B 32768
#define BUF_B    (2 * A_TILE_B + 2 * B_TILE_B)   // 96KB
#define GEMM_SMEM (2 * BUF_B)                    // 192KB

// ---------------------------------------------------------------------------
// Device-global scratch
// ---------------------------------------------------------------------------
__device__ bf16 g_xnh[SEQ*DM], g_xnl[SEQ*DM];
__device__ bf16 g_qh[SEQ*DM], g_ql[SEQ*DM], g_kh[SEQ*DM], g_kl[SEQ*DM];
__device__ bf16 g_vth[(size_t)DM*SEQ], g_vtl[(size_t)DM*SEQ];
__device__ float g_logits[(size_t)NH*SEQ*SEQ];
__device__ bf16 g_wgh[(size_t)NH*SEQ*SEQ], g_wgl[(size_t)NH*SEQ*SEQ];
__device__ bf16 g_avh[SEQ*DM], g_avl[SEQ*DM];
__device__ float g_attnout[SEQ*DM];
__device__ bf16 g_ffh[(size_t)SEQ*DFF], g_ffl[(size_t)SEQ*DFF];
__device__ float g_ropetab[SEQ * 64];
__device__ bf16 g_wqth[(size_t)DM*DM],  g_wqtl[(size_t)DM*DM];
__device__ bf16 g_wkth[(size_t)DM*DM],  g_wktl[(size_t)DM*DM];
__device__ bf16 g_wvth[(size_t)DM*DM],  g_wvtl[(size_t)DM*DM];
__device__ bf16 g_woth[(size_t)DM*DM],  g_wotl[(size_t)DM*DM];
__device__ bf16 g_w1th[(size_t)DFF*DM], g_w1tl[(size_t)DFF*DM];
__device__ bf16 g_w2th[(size_t)DM*DFF], g_w2tl[(size_t)DM*DFF];

// ---------------------------------------------------------------------------
// PTX helpers
// ---------------------------------------------------------------------------
__device__ __forceinline__ uint32_t smem_u32(const void* p) {
    uint32_t r;
    asm("{ .reg .u64 t; cvta.to.shared.u64 t, %1; cvt.u32.u64 %0, t; }" : "=r"(r) : "l"(p));
    return r;
}
__device__ __forceinline__ void cp16(uint32_t dst, const void* src) {
    asm volatile("cp.async.cg.shared.global [%0], [%1], 16;" :: "r"(dst), "l"(src));
}
#define CP_COMMIT() asm volatile("cp.async.commit_group;")
#define CP_WAIT(n)  asm volatile("cp.async.wait_group %0;" :: "n"(n))

#define LDMX4(r, a) \
    asm volatile("ldmatrix.sync.aligned.m8n8.x4.shared.b16 {%0,%1,%2,%3}, [%4];" \
        : "=r"((r)[0]), "=r"((r)[1]), "=r"((r)[2]), "=r"((r)[3]) : "r"(a))

#define MMA16816(c, a, b0, b1) \
    asm volatile("mma.sync.aligned.m16n8k16.row.col.f32.bf16.bf16.f32 " \
        "{%0,%1,%2,%3}, {%4,%5,%6,%7}, {%8,%9}, {%0,%1,%2,%3};" \
        : "+f"((c)[0]), "+f"((c)[1]), "+f"((c)[2]), "+f"((c)[3]) \
        : "r"((a)[0]), "r"((a)[1]), "r"((a)[2]), "r"((a)[3]), \
          "r"(b0), "r"(b1))

__device__ __forceinline__ void split_store(float v, bf16* ph, bf16* pl, size_t idx) {
    bf16 h = __float2bfloat16(v);
    ph[idx] = h;
    pl[idx] = __float2bfloat16(v - __bfloat162float(h));
}

// Epilogues (compile-time)
#define EPI_F32       0
#define EPI_SCALE     1
#define EPI_HILO      2
#define EPI_GELU_HILO 3
#define EPI_BIAS_ADD  4
#define EPI_ROPE_HILO 5
// Causal modes (compile-time)
#define CM_NONE   0
#define CM_LOGITS 1
#define CM_AV     2

__device__ __forceinline__ float gelu_tanh(float v) {
    const float c = 0.7978845608028654f;
    float t = tanhf(c * (v + 0.044715f * v * v * v));
    return 0.5f * v * (1.0f + t);
}

// ---------------------------------------------------------------------------
// Split-bf16 tensor-core GEMM: C[M,N] = A @ B^T, template-specialized epilogue
// A[M,K] row-major hi/lo bf16; B[N,K] row-major hi/lo bf16; fp32 accumulate.
// 2-stage cp.async double buffer, BK=64 (round-7 config).
// ---------------------------------------------------------------------------
template<int EPI, int CMODE>
__global__ void __launch_bounds__(256, 1) gemm_bf16x3(
    const bf16* __restrict__ Ah, const bf16* __restrict__ Al, int lda, unsigned long long sA,
    const bf16* __restrict__ Bh, const bf16* __restrict__ Bl, int ldb, unsigned long long sB,
    int K,
    float* __restrict__ Cf, bf16* __restrict__ Ch, bf16* __restrict__ Cl,
    int ldc, unsigned long long sC,
    const float* __restrict__ bias, const float* __restrict__ addv, float scale,
    const float* __restrict__ ropetab)
{
    int bm = blockIdx.y * BM;
    int bn = blockIdx.x * BN;
    if (CMODE == CM_LOGITS && bn >= bm + BM) return;

    Ah += (size_t)blockIdx.z * sA;  Al += (size_t)blockIdx.z * sA;
    Bh += (size_t)blockIdx.z * sB;  Bl += (size_t)blockIdx.z * sB;
    size_t coff = (size_t)blockIdx.z * sC;

    extern __shared__ char smem[];
    uint32_t sb = smem_u32(smem);
    int tid = threadIdx.x;
    int wid = tid >> 5, lane = tid & 31;
    int warp_m = wid >> 2, warp_n = wid & 3;

    int a_r  = ((lane >> 3) & 1) * 8 + (lane & 7);
    int a_cb = (lane >> 4) * 16;
    int b_r  = (lane >> 4) * 8 + (lane & 7);
    int b_cb = ((lane >> 3) & 1) * 16;

    float acc[4][8][4];
    #pragma unroll
    for (int i = 0; i < 4; i++)
        #pragma unroll
        for (int j = 0; j < 8; j++)
            #pragma unroll
            for (int e = 0; e < 4; e++) acc[i][j][e] = 0.f;

#define LOAD_CHUNK(k0, bufb) do {                                              \
        _Pragma("unroll")                                                      \
        for (int t = 0; t < 4; t++) {                                          \
            int ch = tid + t * 256;                                            \
            int row = ch >> 3, c = ch & 7;                                     \
            uint32_t off = row * 128 + ((c * 16) ^ ((row * 16) & 0x70));       \
            cp16((bufb) + off,            Ah + (size_t)(bm + row) * lda + (k0) + c * 8); \
            cp16((bufb) + A_TILE_B + off, Al + (size_t)(bm + row) * lda + (k0) + c * 8); \
        }                                                                      \
        _Pragma("unroll")                                                      \
        for (int t = 0; t < 8; t++) {                                          \
            int ch = tid + t * 256;                                            \
            int row = ch >> 3, c = ch & 7;                                     \
            uint32_t off = row * 128 + ((c * 16) ^ ((row * 16) & 0x70));       \
            cp16((bufb) + 2*A_TILE_B + off,            Bh + (size_t)(bn + row) * ldb + (k0) + c * 8); \
            cp16((bufb) + 2*A_TILE_B + B_TILE_B + off, Bl + (size_t)(bn + row) * ldb + (k0) + c * 8); \
        }                                                                      \
    } while (0)

    int Keff = (CMODE == CM_AV) ? (bm + BM) : K;
    int nk = Keff / BK;

    LOAD_CHUNK(0, sb);
    CP_COMMIT();

    for (int i = 0; i < nk; i++) {
        uint32_t bufb = sb + (uint32_t)(i & 1) * BUF_B;
        if (i + 1 < nk) {
            uint32_t nb = sb + (uint32_t)((i + 1) & 1) * BUF_B;
            LOAD_CHUNK((i + 1) * BK, nb);
            CP_COMMIT();
            CP_WAIT(1);
        } else {
            CP_WAIT(0);
        }
        __syncthreads();

        #pragma unroll
        for (int ks = 0; ks < 4; ks++) {
            uint32_t ahf[4][4], alf[4][4];
            #pragma unroll
            for (int mt = 0; mt < 4; mt++) {
                int row = warp_m * 64 + mt * 16 + a_r;
                uint32_t cb = ks * 32 + a_cb;
                uint32_t off = row * 128 + (cb ^ ((row * 16) & 0x70));
                LDMX4(ahf[mt], bufb + off);
                LDMX4(alf[mt], bufb + A_TILE_B + off);
            }
            uint32_t bhf[8][2], blf[8][2];
            #pragma unroll
            for (int p = 0; p < 4; p++) {
                int row = warp_n * 64 + p * 16 + b_r;
                uint32_t cb = ks * 32 + b_cb;
                uint32_t off = row * 128 + (cb ^ ((row * 16) & 0x70));
                uint32_t r[4];
                LDMX4(r, bufb + 2 * A_TILE_B + off);
                bhf[2*p][0] = r[0]; bhf[2*p][1] = r[1];
                bhf[2*p+1][0] = r[2]; bhf[2*p+1][1] = r[3];
                LDMX4(r, bufb + 2 * A_TILE_B + B_TILE_B + off);
                blf[2*p][0] = r[0]; blf[2*p][1] = r[1];
                blf[2*p+1][0] = r[2]; blf[2*p+1][1] = r[3];
            }
            #pragma unroll
            for (int mt = 0; mt < 4; mt++)
                #pragma unroll
                for (int nt = 0; nt < 8; nt++) {
                    MMA16816(acc[mt][nt], ahf[mt], bhf[nt][0], bhf[nt][1]);
                    MMA16816(acc[mt][nt], ahf[mt], blf[nt][0], blf[nt][1]);
                    MMA16816(acc[mt][nt], alf[mt], bhf[nt][0], bhf[nt][1]);
                }
        }
        __syncthreads();
    }
#undef LOAD_CHUNK

    // Epilogue (template-pruned)
    int g = lane >> 2, tg = lane & 3;
    #pragma unroll
    for (int mt = 0; mt < 4; mt++) {
        #pragma unroll
        for (int nt = 0; nt < 8; nt++) {
            int row0 = bm + warp_m * 64 + mt * 16 + g;
            int col  = bn + warp_n * 64 + nt * 8 + tg * 2;
            float* a = acc[mt][nt];
            #pragma unroll
            for (int half = 0; half < 2; half++) {
                int row = row0 + half * 8;
                float v0 = a[half * 2 + 0], v1 = a[half * 2 + 1];
                size_t idx = coff + (size_t)row * ldc + col;
                if (EPI == EPI_F32) {
                    *(float2*)(Cf + idx) = make_float2(v0, v1);
                } else if (EPI == EPI_SCALE) {
                    *(float2*)(Cf + idx) = make_float2(v0 * scale, v1 * scale);
                } else if (EPI == EPI_HILO) {
                    bf16 h0 = __float2bfloat16(v0), h1 = __float2bfloat16(v1);
                    __nv_bfloat162 hp; hp.x = h0; hp.y = h1;
                    __nv_bfloat162 lp;
                    lp.x = __float2bfloat16(v0 - __bfloat162float(h0));
                    lp.y = __float2bfloat16(v1 - __bfloat162float(h1));
                    *(__nv_bfloat162*)(Ch + idx) = hp;
                    *(__nv_bfloat162*)(Cl + idx) = lp;
                } else if (EPI == EPI_GELU_HILO) {
                    float g0 = gelu_tanh(v0 + bias[col]);
                    float g1 = gelu_tanh(v1 + bias[col + 1]);
                    bf16 h0 = __float2bfloat16(g0), h1 = __float2bfloat16(g1);
                    __nv_bfloat162 hp; hp.x = h0; hp.y = h1;
                    __nv_bfloat162 lp;
                    lp.x = __float2bfloat16(g0 - __bfloat162float(h0));
                    lp.y = __float2bfloat16(g1 - __bfloat162float(h1));
                    *(__nv_bfloat162*)(Ch + idx) = hp;
                    *(__nv_bfloat162*)(Cl + idx) = lp;
                } else if (EPI == EPI_ROPE_HILO) {
                    int d = col & (DH - 1);
                    if (d < 64) {
                        float s = ropetab[row * 64 + d];
                        float c = ropetab[row * 64 + d + 1];
                        float n0 = v0 * c - v1 * s;
                        float n1 = v1 * c + v0 * s;
                        v0 = n0; v1 = n1;
                    }
                    bf16 h0 = __float2bfloat16(v0), h1 = __float2bfloat16(v1);
                    __nv_bfloat162 hp; hp.x = h0; hp.y = h1;
                    __nv_bfloat162 lp;
                    lp.x = __float2bfloat16(v0 - __bfloat162float(h0));
                    lp.y = __float2bfloat16(v1 - __bfloat162float(h1));
                    *(__nv_bfloat162*)(Ch + idx) = hp;
                    *(__nv_bfloat162*)(Cl + idx) = lp;
                } else { // EPI_BIAS_ADD
                    float2 av = *(const float2*)(addv + idx);
                    *(float2*)(Cf + idx) = make_float2(v0 + bias[col] + av.x,
                                                       v1 + bias[col + 1] + av.y);
                }
            }
        }
    }
}

// ---------------------------------------------------------------------------
// RoPE sin/cos table (fp64): tab[t*64+2i]=sin, tab[t*64+2i+1]=cos
// ---------------------------------------------------------------------------
__global__ void ropetab_kernel(float* __restrict__ tab)
{
    int idx = blockIdx.x * 256 + threadIdx.x;
    if (idx >= SEQ * 32) return;
    int i = idx & 31, t = idx >> 5;
    double inv = exp(-(double)i * (9.210340371976184 / 32.0));
    double s, c;
    sincos((double)t * inv, &s, &c);
    tab[t * 64 + 2 * i]     = (float)s;
    tab[t * 64 + 2 * i + 1] = (float)c;
}

// ---------------------------------------------------------------------------
// LayerNorm -> hi/lo bf16
// ---------------------------------------------------------------------------
__global__ void ln_kernel(const float* __restrict__ x,
                          const float* __restrict__ scale,
                          const float* __restrict__ offset,
                          bf16* __restrict__ xh, bf16* __restrict__ xl)
{
    __shared__ float red[256];
    int row = blockIdx.x;
    int tid = threadIdx.x;
    const float* xr = x + (size_t)row * DM;

    float s = 0.f;
    for (int i = tid; i < DM; i += 256) s += xr[i];
    red[tid] = s; __syncthreads();
    for (int o = 128; o > 0; o >>= 1) { if (tid < o) red[tid] += red[tid + o]; __syncthreads(); }
    float mean = red[0] / (float)DM;
    __syncthreads();

    float v = 0.f;
    for (int i = tid; i < DM; i += 256) { float d = xr[i] - mean; v += d * d; }
    red[tid] = v; __syncthreads();
    for (int o = 128; o > 0; o >>= 1) { if (tid < o) red[tid] += red[tid + o]; __syncthreads(); }
    float r = rsqrtf(red[0] / (float)DM + 1e-5f);

    for (int i = tid; i < DM; i += 256) {
        float y = scale[i] * r * (xr[i] - mean) + offset[i];
        split_store(y, xh, xl, (size_t)row * DM + i);
    }
}

// ---------------------------------------------------------------------------
// Transpose + hi/lo convert: 64x64 tiles, float4 loads, bf162 stores
// ---------------------------------------------------------------------------
__global__ void transcvt_kernel(const float* __restrict__ in, int R, int C,
                                bf16* __restrict__ oh, bf16* __restrict__ ol)
{
    __shared__ float t[64][65];
    int c0 = blockIdx.x * 64;
    int r0 = blockIdx.y * 64;
    int tid = threadIdx.x;
    #pragma unroll
    for (int p = 0; p < 4; p++) {
        int f = tid + p * 256;
        int row = f >> 4, c4 = (f & 15) * 4;
        float4 v = *(const float4*)(in + (size_t)(r0 + row) * C + c0 + c4);
        t[row][c4 + 0] = v.x; t[row][c4 + 1] = v.y;
        t[row][c4 + 2] = v.z; t[row][c4 + 3] = v.w;
    }
    __syncthreads();
    #pragma unroll
    for (int p = 0; p < 8; p++) {
        int w = tid + p * 256;
        int c = w >> 5, rp = (w & 31) * 2;
        float v0 = t[rp][c], v1 = t[rp + 1][c];
        size_t idx = (size_t)(c0 + c) * R + r0 + rp;
        bf16 h0 = __float2bfloat16(v0), h1 = __float2bfloat16(v1);
        __nv_bfloat162 hp; hp.x = h0; hp.y = h1;
        __nv_bfloat162 lp;
        lp.x = __float2bfloat16(v0 - __bfloat162float(h0));
        lp.y = __float2bfloat16(v1 - __bfloat162float(h1));
        *(__nv_bfloat162*)(oh + idx) = hp;
        *(__nv_bfloat162*)(ol + idx) = lp;
    }
}

// ---------------------------------------------------------------------------
// Causal softmax: row cached in smem, zero-fill to 128-block end
// ---------------------------------------------------------------------------
__global__ void softmax_kernel(const float* __restrict__ logits,
                               const float* __restrict__ attn_bias,
                               bf16* __restrict__ wh, bf16* __restrict__ wl)
{
    __shared__ float rowbuf[SEQ];
    __shared__ float red[256];
    int t = blockIdx.x;
    int h = blockIdx.y;
    int tid = threadIdx.x;
    size_t base = ((size_t)h * SEQ + t) * SEQ;
    const float* brow = attn_bias + (size_t)t * SEQ;
    int n = t + 1;
    int blockend = ((t >> 7) + 1) << 7;

    float m = -INFINITY;
    for (int T = tid; T < n; T += 256) {
        float l = logits[base + T] + brow[T];
        rowbuf[T] = l;
        m = fmaxf(m, l);
    }
    red[tid] = m; __syncthreads();
    for (int o = 128; o > 0; o >>= 1) { if (tid < o) red[tid] = fmaxf(red[tid], red[tid + o]); __syncthreads(); }
    m = red[0]; __syncthreads();

    float s = 0.f;
    for (int T = tid; T < n; T += 256) {
        float e = expf(rowbuf[T] - m);
        rowbuf[T] = e;
        s += e;
    }
    red[tid] = s; __syncthreads();
    for (int o = 128; o > 0; o >>= 1) { if (tid < o) red[tid] += red[tid + o]; __syncthreads(); }
    float inv = 1.0f / red[0];

    for (int T = tid; T < n; T += 256)
        split_store(rowbuf[T] * inv, wh, wl, base + T);
    for (int T = n + tid; T < blockend; T += 256) {
        wh[base + T] = __float2bfloat16(0.f);
        wl[base + T] = __float2bfloat16(0.f);
    }
}

// ---------------------------------------------------------------------------
// Launcher
// ---------------------------------------------------------------------------
extern "C" void kernel_launch(void* const* d_in, const int* in_sizes, int n_in,
                              void* d_out, int out_size)
{
    const float* x         = (const float*)d_in[0];
    const float* attn_bias = (const float*)d_in[1];
    const float* ln_scale  = (const float*)d_in[2];
    const float* ln_offset = (const float*)d_in[3];
    const float* wq        = (const float*)d_in[4];
    const float* wk        = (const float*)d_in[5];
    const float* wv        = (const float*)d_in[6];
    const float* wo        = (const float*)d_in[7];
    const float* w1        = (const float*)d_in[8];
    const float* b1        = (const float*)d_in[9];
    const float* w2        = (const float*)d_in[10];
    const float* b2        = (const float*)d_in[11];
    float* out = (float*)d_out;

    cudaFuncSetAttribute(gemm_bf16x3<EPI_F32, CM_NONE>,       cudaFuncAttributeMaxDynamicSharedMemorySize, GEMM_SMEM);
    cudaFuncSetAttribute(gemm_bf16x3<EPI_ROPE_HILO, CM_NONE>, cudaFuncAttributeMaxDynamicSharedMemorySize, GEMM_SMEM);
    cudaFuncSetAttribute(gemm_bf16x3<EPI_HILO, CM_NONE>,      cudaFuncAttributeMaxDynamicSharedMemorySize, GEMM_SMEM);
    cudaFuncSetAttribute(gemm_bf16x3<EPI_SCALE, CM_LOGITS>,   cudaFuncAttributeMaxDynamicSharedMemorySize, GEMM_SMEM);
    cudaFuncSetAttribute(gemm_bf16x3<EPI_HILO, CM_AV>,        cudaFuncAttributeMaxDynamicSharedMemorySize, GEMM_SMEM);
    cudaFuncSetAttribute(gemm_bf16x3<EPI_GELU_HILO, CM_NONE>, cudaFuncAttributeMaxDynamicSharedMemorySize, GEMM_SMEM);
    cudaFuncSetAttribute(gemm_bf16x3<EPI_BIAS_ADD, CM_NONE>,  cudaFuncAttributeMaxDynamicSharedMemorySize, GEMM_SMEM);

    bf16 *xnh, *xnl, *qh, *ql, *kh, *kl, *vth, *vtl, *wgh, *wgl, *avh, *avl, *ffh, *ffl;
    bf16 *wqth, *wqtl, *wkth, *wktl, *wvth, *wvtl, *woth, *wotl, *w1th, *w1tl, *w2th, *w2tl;
    float *logits, *attnout, *ropetab;
    cudaGetSymbolAddress((void**)&xnh, g_xnh);   cudaGetSymbolAddress((void**)&xnl, g_xnl);
    cudaGetSymbolAddress((void**)&qh, g_qh);     cudaGetSymbolAddress((void**)&ql, g_ql);
    cudaGetSymbolAddress((void**)&kh, g_kh);     cudaGetSymbolAddress((void**)&kl, g_kl);
    cudaGetSymbolAddress((void**)&vth, g_vth);   cudaGetSymbolAddress((void**)&vtl, g_vtl);
    cudaGetSymbolAddress((void**)&logits, g_logits);
    cudaGetSymbolAddress((void**)&wgh, g_wgh);   cudaGetSymbolAddress((void**)&wgl, g_wgl);
    cudaGetSymbolAddress((void**)&avh, g_avh);   cudaGetSymbolAddress((void**)&avl, g_avl);
    cudaGetSymbolAddress((void**)&attnout, g_attnout);
    cudaGetSymbolAddress((void**)&ffh, g_ffh);   cudaGetSymbolAddress((void**)&ffl, g_ffl);
    cudaGetSymbolAddress((void**)&ropetab, g_ropetab);
    cudaGetSymbolAddress((void**)&wqth, g_wqth); cudaGetSymbolAddress((void**)&wqtl, g_wqtl);
    cudaGetSymbolAddress((void**)&wkth, g_wkth); cudaGetSymbolAddress((void**)&wktl, g_wktl);
    cudaGetSymbolAddress((void**)&wvth, g_wvth); cudaGetSymbolAddress((void**)&wvtl, g_wvtl);
    cudaGetSymbolAddress((void**)&woth, g_woth); cudaGetSymbolAddress((void**)&wotl, g_wotl);
    cudaGetSymbolAddress((void**)&w1th, g_w1th); cudaGetSymbolAddress((void**)&w1tl, g_w1tl);
    cudaGetSymbolAddress((void**)&w2th, g_w2th); cudaGetSymbolAddress((void**)&w2tl, g_w2tl);

    // rope table + weight prep
    ropetab_kernel<<<(SEQ * 32 + 255) / 256, 256>>>(ropetab);
    transcvt_kernel<<<dim3(DM / 64, DM / 64), 256>>>(wq, DM, DM, wqth, wqtl);
    transcvt_kernel<<<dim3(DM / 64, DM / 64), 256>>>(wk, DM, DM, wkth, wktl);
    transcvt_kernel<<<dim3(DM / 64, DM / 64), 256>>>(wv, DM, DM, wvth, wvtl);
    transcvt_kernel<<<dim3(DM / 64, DM / 64), 256>>>(wo, DM, DM, woth, wotl);
    transcvt_kernel<<<dim3(DFF / 64, DM / 64), 256>>>(w1, DM, DFF, w1th, w1tl);
    transcvt_kernel<<<dim3(DM / 64, DFF / 64), 256>>>(w2, DFF, DM, w2th, w2tl);

    ln_kernel<<<SEQ, 256>>>(x, ln_scale, ln_offset, xnh, xnl);

    // Q, K (rope fused) projections
    dim3 gProj(DM / BN, SEQ / BM, 1);
    gemm_bf16x3<EPI_ROPE_HILO, CM_NONE><<<gProj, 256, GEMM_SMEM>>>(
        xnh, xnl, DM, 0, wqth, wqtl, DM, 0, DM,
        nullptr, qh, ql, DM, 0, nullptr, nullptr, 1.f, ropetab);
    gemm_bf16x3<EPI_ROPE_HILO, CM_NONE><<<gProj, 256, GEMM_SMEM>>>(
        xnh, xnl, DM, 0, wkth, wktl, DM, 0, DM,
        nullptr, kh, kl, DM, 0, nullptr, nullptr, 1.f, ropetab);

    // vt[DM,SEQ] = wv^T @ xn^T computed directly: A=wvt, B=xn
    dim3 gVT(SEQ / BN, DM / BM, 1);
    gemm_bf16x3<EPI_HILO, CM_NONE><<<gVT, 256, GEMM_SMEM>>>(
        wvth, wvtl, DM, 0, xnh, xnl, DM, 0, DM,
        nullptr, vth, vtl, SEQ, 0, nullptr, nullptr, 1.f, nullptr);

    // logits[h] = q_h @ k_h^T / 16 (skip fully masked tiles)
    dim3 gLog(SEQ / BN, SEQ / BM, NH);
    gemm_bf16x3<EPI_SCALE, CM_LOGITS><<<gLog, 256, GEMM_SMEM>>>(
        qh, ql, DM, DH, kh, kl, DM, DH, DH,
        logits, nullptr, nullptr, SEQ, (unsigned long long)SEQ * SEQ,
        nullptr, nullptr, 0.0625f, nullptr);

    softmax_kernel<<<dim3(SEQ, NH), 256>>>(logits, attn_bias, wgh, wgl);

    // attn_vec[h] = W_h @ v_h  (variable K)
    dim3 gAV(DH / BN, SEQ / BM, NH);
    gemm_bf16x3<EPI_HILO, CM_AV><<<gAV, 256, GEMM_SMEM>>>(
        wgh, wgl, SEQ, (unsigned long long)SEQ * SEQ,
        vth, vtl, SEQ, (unsigned long long)DH * SEQ, SEQ,
        nullptr, avh, avl, DM, DH, nullptr, nullptr, 1.f, nullptr);

    gemm_bf16x3<EPI_F32, CM_NONE><<<gProj, 256, GEMM_SMEM>>>(
        avh, avl, DM, 0, woth, wotl, DM, 0, DM,
        attnout, nullptr, nullptr, DM, 0, nullptr, nullptr, 1.f, nullptr);

    dim3 gFF1(DFF / BN, SEQ / BM, 1);
    gemm_bf16x3<EPI_GELU_HILO, CM_NONE><<<gFF1, 256, GEMM_SMEM>>>(
        xnh, xnl, DM, 0, w1th, w1tl, DM, 0, DM,
        nullptr, ffh, ffl, DFF, 0, b1, nullptr, 1.f, nullptr);

    dim3 gFF2(DM / BN, SEQ / BM, 1);
    gemm_bf16x3<EPI_BIAS_ADD, CM_NONE><<<gFF2, 256, GEMM_SMEM>>>(
        ffh, ffl, DFF, 0, w2th, w2tl, DFF, 0, DFF,
        out, nullptr, nullptr, DM, 0, b2, attnout, 1.f, nullptr);
}

// round 10
// speedup vs baseline: 1.1347x; 1.0366x over previous
#include <cuda_runtime.h>
#include <cuda_bf16.h>
#include <math.h>
#include <stdint.h>

typedef __nv_bfloat16 bf16;

#define SEQ 2048
#define DM  4096
#define NH  16
#define DH  256
#define DFF 16384

// GEMM tiling: CTA 128x256, BK=64, 8 warps (2x4), warp tile 64x64, 2-stage
#define BM 128
#define BN 256
#define BK 64
#define A_TILE_B 16384
#define B_TILE_B 32768
#define BUF_B    (2 * A_TILE_B + 2 * B_TILE_B)   // 96KB
#define GEMM_SMEM (2 * BUF_B)                    // 192KB

// ---------------------------------------------------------------------------
// Device-global scratch
// ---------------------------------------------------------------------------
__device__ bf16 g_xnh[SEQ*DM], g_xnl[SEQ*DM];
__device__ bf16 g_qh[SEQ*DM], g_ql[SEQ*DM], g_kh[SEQ*DM], g_kl[SEQ*DM];
__device__ bf16 g_vth[(size_t)DM*SEQ], g_vtl[(size_t)DM*SEQ];
__device__ float g_logits[(size_t)NH*SEQ*SEQ];
__device__ bf16 g_wgh[(size_t)NH*SEQ*SEQ], g_wgl[(size_t)NH*SEQ*SEQ];
__device__ bf16 g_avh[SEQ*DM], g_avl[SEQ*DM];
__device__ float g_attnout[SEQ*DM];
__device__ bf16 g_ffh[(size_t)SEQ*DFF], g_ffl[(size_t)SEQ*DFF];
__device__ float g_ffpart[(size_t)4*SEQ*DM];     // split-K partials (128MB)
__device__ float g_ropetab[SEQ * 64];
__device__ bf16 g_wqth[(size_t)DM*DM],  g_wqtl[(size_t)DM*DM];
__device__ bf16 g_wkth[(size_t)DM*DM],  g_wktl[(size_t)DM*DM];
__device__ bf16 g_wvth[(size_t)DM*DM],  g_wvtl[(size_t)DM*DM];
__device__ bf16 g_woth[(size_t)DM*DM],  g_wotl[(size_t)DM*DM];
__device__ bf16 g_w1th[(size_t)DFF*DM], g_w1tl[(size_t)DFF*DM];
__device__ bf16 g_w2th[(size_t)DM*DFF], g_w2tl[(size_t)DM*DFF];

// ---------------------------------------------------------------------------
// PTX helpers
// ---------------------------------------------------------------------------
__device__ __forceinline__ uint32_t smem_u32(const void* p) {
    uint32_t r;
    asm("{ .reg .u64 t; cvta.to.shared.u64 t, %1; cvt.u32.u64 %0, t; }" : "=r"(r) : "l"(p));
    return r;
}
__device__ __forceinline__ void cp16(uint32_t dst, const void* src) {
    asm volatile("cp.async.cg.shared.global [%0], [%1], 16;" :: "r"(dst), "l"(src));
}
#define CP_COMMIT() asm volatile("cp.async.commit_group;")
#define CP_WAIT(n)  asm volatile("cp.async.wait_group %0;" :: "n"(n))

#define LDMX4(r, a) \
    asm volatile("ldmatrix.sync.aligned.m8n8.x4.shared.b16 {%0,%1,%2,%3}, [%4];" \
        : "=r"((r)[0]), "=r"((r)[1]), "=r"((r)[2]), "=r"((r)[3]) : "r"(a))

#define MMA16816(c, a, b0, b1) \
    asm volatile("mma.sync.aligned.m16n8k16.row.col.f32.bf16.bf16.f32 " \
        "{%0,%1,%2,%3}, {%4,%5,%6,%7}, {%8,%9}, {%0,%1,%2,%3};" \
        : "+f"((c)[0]), "+f"((c)[1]), "+f"((c)[2]), "+f"((c)[3]) \
        : "r"((a)[0]), "r"((a)[1]), "r"((a)[2]), "r"((a)[3]), \
          "r"(b0), "r"(b1))

__device__ __forceinline__ void split_store(float v, bf16* ph, bf16* pl, size_t idx) {
    bf16 h = __float2bfloat16(v);
    ph[idx] = h;
    pl[idx] = __float2bfloat16(v - __bfloat162float(h));
}

// Epilogues (compile-time)
#define EPI_F32       0
#define EPI_SCALE     1
#define EPI_HILO      2
#define EPI_GELU_HILO 3
#define EPI_BIAS_ADD  4
#define EPI_ROPE_HILO 5
// Causal modes (compile-time)
#define CM_NONE   0
#define CM_LOGITS 1
#define CM_AV     2

__device__ __forceinline__ float gelu_tanh(float v) {
    const float c = 0.7978845608028654f;
    float t = tanhf(c * (v + 0.044715f * v * v * v));
    return 0.5f * v * (1.0f + t);
}

// ---------------------------------------------------------------------------
// Split-bf16 tensor-core GEMM: C[M,N] = A @ B^T, template-specialized epilogue
// A[M,K] row-major hi/lo bf16; B[N,K] row-major hi/lo bf16; fp32 accumulate.
// 2-stage cp.async double buffer, BK=64.
// ---------------------------------------------------------------------------
template<int EPI, int CMODE>
__global__ void __launch_bounds__(256, 1) gemm_bf16x3(
    const bf16* __restrict__ Ah, const bf16* __restrict__ Al, int lda, unsigned long long sA,
    const bf16* __restrict__ Bh, const bf16* __restrict__ Bl, int ldb, unsigned long long sB,
    int K,
    float* __restrict__ Cf, bf16* __restrict__ Ch, bf16* __restrict__ Cl,
    int ldc, unsigned long long sC,
    const float* __restrict__ bias, const float* __restrict__ addv, float scale,
    const float* __restrict__ ropetab)
{
    // CM_AV: reverse bm order so longest-K CTAs launch first
    int bmi = (CMODE == CM_AV) ? ((int)gridDim.y - 1 - (int)blockIdx.y) : (int)blockIdx.y;
    int bm = bmi * BM;
    int bn = blockIdx.x * BN;
    if (CMODE == CM_LOGITS && bn >= bm + BM) return;

    Ah += (size_t)blockIdx.z * sA;  Al += (size_t)blockIdx.z * sA;
    Bh += (size_t)blockIdx.z * sB;  Bl += (size_t)blockIdx.z * sB;
    size_t coff = (size_t)blockIdx.z * sC;

    extern __shared__ char smem[];
    uint32_t sb = smem_u32(smem);
    int tid = threadIdx.x;
    int wid = tid >> 5, lane = tid & 31;
    int warp_m = wid >> 2, warp_n = wid & 3;

    int a_r  = ((lane >> 3) & 1) * 8 + (lane & 7);
    int a_cb = (lane >> 4) * 16;
    int b_r  = (lane >> 4) * 8 + (lane & 7);
    int b_cb = ((lane >> 3) & 1) * 16;

    float acc[4][8][4];
    #pragma unroll
    for (int i = 0; i < 4; i++)
        #pragma unroll
        for (int j = 0; j < 8; j++)
            #pragma unroll
            for (int e = 0; e < 4; e++) acc[i][j][e] = 0.f;

#define LOAD_CHUNK(k0, bufb) do {                                              \
        _Pragma("unroll")                                                      \
        for (int t = 0; t < 4; t++) {                                          \
            int ch = tid + t * 256;                                            \
            int row = ch >> 3, c = ch & 7;                                     \
            uint32_t off = row * 128 + ((c * 16) ^ ((row * 16) & 0x70));       \
            cp16((bufb) + off,            Ah + (size_t)(bm + row) * lda + (k0) + c * 8); \
            cp16((bufb) + A_TILE_B + off, Al + (size_t)(bm + row) * lda + (k0) + c * 8); \
        }                                                                      \
        _Pragma("unroll")                                                      \
        for (int t = 0; t < 8; t++) {                                          \
            int ch = tid + t * 256;                                            \
            int row = ch >> 3, c = ch & 7;                                     \
            uint32_t off = row * 128 + ((c * 16) ^ ((row * 16) & 0x70));       \
            cp16((bufb) + 2*A_TILE_B + off,            Bh + (size_t)(bn + row) * ldb + (k0) + c * 8); \
            cp16((bufb) + 2*A_TILE_B + B_TILE_B + off, Bl + (size_t)(bn + row) * ldb + (k0) + c * 8); \
        }                                                                      \
    } while (0)

    int Keff = (CMODE == CM_AV) ? (bm + BM) : K;
    int nk = Keff / BK;

    LOAD_CHUNK(0, sb);
    CP_COMMIT();

    for (int i = 0; i < nk; i++) {
        uint32_t bufb = sb + (uint32_t)(i & 1) * BUF_B;
        if (i + 1 < nk) {
            uint32_t nb = sb + (uint32_t)((i + 1) & 1) * BUF_B;
            LOAD_CHUNK((i + 1) * BK, nb);
            CP_COMMIT();
            CP_WAIT(1);
        } else {
            CP_WAIT(0);
        }
        __syncthreads();

        #pragma unroll
        for (int ks = 0; ks < 4; ks++) {
            uint32_t ahf[4][4], alf[4][4];
            #pragma unroll
            for (int mt = 0; mt < 4; mt++) {
                int row = warp_m * 64 + mt * 16 + a_r;
                uint32_t cb = ks * 32 + a_cb;
                uint32_t off = row * 128 + (cb ^ ((row * 16) & 0x70));
                LDMX4(ahf[mt], bufb + off);
                LDMX4(alf[mt], bufb + A_TILE_B + off);
            }
            uint32_t bhf[8][2], blf[8][2];
            #pragma unroll
            for (int p = 0; p < 4; p++) {
                int row = warp_n * 64 + p * 16 + b_r;
                uint32_t cb = ks * 32 + b_cb;
                uint32_t off = row * 128 + (cb ^ ((row * 16) & 0x70));
                uint32_t r[4];
                LDMX4(r, bufb + 2 * A_TILE_B + off);
                bhf[2*p][0] = r[0]; bhf[2*p][1] = r[1];
                bhf[2*p+1][0] = r[2]; bhf[2*p+1][1] = r[3];
                LDMX4(r, bufb + 2 * A_TILE_B + B_TILE_B + off);
                blf[2*p][0] = r[0]; blf[2*p][1] = r[1];
                blf[2*p+1][0] = r[2]; blf[2*p+1][1] = r[3];
            }
            #pragma unroll
            for (int mt = 0; mt < 4; mt++)
                #pragma unroll
                for (int nt = 0; nt < 8; nt++) {
                    MMA16816(acc[mt][nt], ahf[mt], bhf[nt][0], bhf[nt][1]);
                    MMA16816(acc[mt][nt], ahf[mt], blf[nt][0], blf[nt][1]);
                    MMA16816(acc[mt][nt], alf[mt], bhf[nt][0], bhf[nt][1]);
                }
        }
        __syncthreads();
    }
#undef LOAD_CHUNK

    // Epilogue (template-pruned)
    int g = lane >> 2, tg = lane & 3;
    #pragma unroll
    for (int mt = 0; mt < 4; mt++) {
        #pragma unroll
        for (int nt = 0; nt < 8; nt++) {
            int row0 = bm + warp_m * 64 + mt * 16 + g;
            int col  = bn + warp_n * 64 + nt * 8 + tg * 2;
            float* a = acc[mt][nt];
            #pragma unroll
            for (int half = 0; half < 2; half++) {
                int row = row0 + half * 8;
                float v0 = a[half * 2 + 0], v1 = a[half * 2 + 1];
                size_t idx = coff + (size_t)row * ldc + col;
                if (EPI == EPI_F32) {
                    *(float2*)(Cf + idx) = make_float2(v0, v1);
                } else if (EPI == EPI_SCALE) {
                    *(float2*)(Cf + idx) = make_float2(v0 * scale, v1 * scale);
                } else if (EPI == EPI_HILO) {
                    bf16 h0 = __float2bfloat16(v0), h1 = __float2bfloat16(v1);
                    __nv_bfloat162 hp; hp.x = h0; hp.y = h1;
                    __nv_bfloat162 lp;
                    lp.x = __float2bfloat16(v0 - __bfloat162float(h0));
                    lp.y = __float2bfloat16(v1 - __bfloat162float(h1));
                    *(__nv_bfloat162*)(Ch + idx) = hp;
                    *(__nv_bfloat162*)(Cl + idx) = lp;
                } else if (EPI == EPI_GELU_HILO) {
                    float g0 = gelu_tanh(v0 + bias[col]);
                    float g1 = gelu_tanh(v1 + bias[col + 1]);
                    bf16 h0 = __float2bfloat16(g0), h1 = __float2bfloat16(g1);
                    __nv_bfloat162 hp; hp.x = h0; hp.y = h1;
                    __nv_bfloat162 lp;
                    lp.x = __float2bfloat16(g0 - __bfloat162float(h0));
                    lp.y = __float2bfloat16(g1 - __bfloat162float(h1));
                    *(__nv_bfloat162*)(Ch + idx) = hp;
                    *(__nv_bfloat162*)(Cl + idx) = lp;
                } else if (EPI == EPI_ROPE_HILO) {
                    int d = col & (DH - 1);
                    if (d < 64) {
                        float s = ropetab[row * 64 + d];
                        float c = ropetab[row * 64 + d + 1];
                        float n0 = v0 * c - v1 * s;
                        float n1 = v1 * c + v0 * s;
                        v0 = n0; v1 = n1;
                    }
                    bf16 h0 = __float2bfloat16(v0), h1 = __float2bfloat16(v1);
                    __nv_bfloat162 hp; hp.x = h0; hp.y = h1;
                    __nv_bfloat162 lp;
                    lp.x = __float2bfloat16(v0 - __bfloat162float(h0));
                    lp.y = __float2bfloat16(v1 - __bfloat162float(h1));
                    *(__nv_bfloat162*)(Ch + idx) = hp;
                    *(__nv_bfloat162*)(Cl + idx) = lp;
                } else { // EPI_BIAS_ADD
                    float2 av = *(const float2*)(addv + idx);
                    *(float2*)(Cf + idx) = make_float2(v0 + bias[col] + av.x,
                                                       v1 + bias[col + 1] + av.y);
                }
            }
        }
    }
}

// ---------------------------------------------------------------------------
// Split-K reduce: out = p0+p1+p2+p3 + b2[col] + attnout   (float4 per thread)
// ---------------------------------------------------------------------------
__global__ void splitk_reduce_kernel(const float* __restrict__ part,
                                     const float* __restrict__ bias,
                                     const float* __restrict__ addv,
                                     float* __restrict__ out)
{
    size_t i4 = (size_t)blockIdx.x * 256 + threadIdx.x;   // float4 index
    size_t i = i4 * 4;
    const size_t S = (size_t)SEQ * DM;
    float4 p0 = *(const float4*)(part + i);
    float4 p1 = *(const float4*)(part + S + i);
    float4 p2 = *(const float4*)(part + 2 * S + i);
    float4 p3 = *(const float4*)(part + 3 * S + i);
    float4 av = *(const float4*)(addv + i);
    float4 bv = *(const float4*)(bias + (i & (DM - 1)));
    float4 r;
    r.x = p0.x + p1.x + p2.x + p3.x + av.x + bv.x;
    r.y = p0.y + p1.y + p2.y + p3.y + av.y + bv.y;
    r.z = p0.z + p1.z + p2.z + p3.z + av.z + bv.z;
    r.w = p0.w + p1.w + p2.w + p3.w + av.w + bv.w;
    *(float4*)(out + i) = r;
}

// ---------------------------------------------------------------------------
// RoPE sin/cos table (fp64): tab[t*64+2i]=sin, tab[t*64+2i+1]=cos
// ---------------------------------------------------------------------------
__global__ void ropetab_kernel(float* __restrict__ tab)
{
    int idx = blockIdx.x * 256 + threadIdx.x;
    if (idx >= SEQ * 32) return;
    int i = idx & 31, t = idx >> 5;
    double inv = exp(-(double)i * (9.210340371976184 / 32.0));
    double s, c;
    sincos((double)t * inv, &s, &c);
    tab[t * 64 + 2 * i]     = (float)s;
    tab[t * 64 + 2 * i + 1] = (float)c;
}

// ---------------------------------------------------------------------------
// LayerNorm -> hi/lo bf16
// ---------------------------------------------------------------------------
__global__ void ln_kernel(const float* __restrict__ x,
                          const float* __restrict__ scale,
                          const float* __restrict__ offset,
                          bf16* __restrict__ xh, bf16* __restrict__ xl)
{
    __shared__ float red[256];
    int row = blockIdx.x;
    int tid = threadIdx.x;
    const float* xr = x + (size_t)row * DM;

    float s = 0.f;
    for (int i = tid; i < DM; i += 256) s += xr[i];
    red[tid] = s; __syncthreads();
    for (int o = 128; o > 0; o >>= 1) { if (tid < o) red[tid] += red[tid + o]; __syncthreads(); }
    float mean = red[0] / (float)DM;
    __syncthreads();

    float v = 0.f;
    for (int i = tid; i < DM; i += 256) { float d = xr[i] - mean; v += d * d; }
    red[tid] = v; __syncthreads();
    for (int o = 128; o > 0; o >>= 1) { if (tid < o) red[tid] += red[tid + o]; __syncthreads(); }
    float r = rsqrtf(red[0] / (float)DM + 1e-5f);

    for (int i = tid; i < DM; i += 256) {
        float y = scale[i] * r * (xr[i] - mean) + offset[i];
        split_store(y, xh, xl, (size_t)row * DM + i);
    }
}

// ---------------------------------------------------------------------------
// Transpose + hi/lo convert: 64x64 tiles, float4 loads, bf162 stores
// ---------------------------------------------------------------------------
__global__ void transcvt_kernel(const float* __restrict__ in, int R, int C,
                                bf16* __restrict__ oh, bf16* __restrict__ ol)
{
    __shared__ float t[64][65];
    int c0 = blockIdx.x * 64;
    int r0 = blockIdx.y * 64;
    int tid = threadIdx.x;
    #pragma unroll
    for (int p = 0; p < 4; p++) {
        int f = tid + p * 256;
        int row = f >> 4, c4 = (f & 15) * 4;
        float4 v = *(const float4*)(in + (size_t)(r0 + row) * C + c0 + c4);
        t[row][c4 + 0] = v.x; t[row][c4 + 1] = v.y;
        t[row][c4 + 2] = v.z; t[row][c4 + 3] = v.w;
    }
    __syncthreads();
    #pragma unroll
    for (int p = 0; p < 8; p++) {
        int w = tid + p * 256;
        int c = w >> 5, rp = (w & 31) * 2;
        float v0 = t[rp][c], v1 = t[rp + 1][c];
        size_t idx = (size_t)(c0 + c) * R + r0 + rp;
        bf16 h0 = __float2bfloat16(v0), h1 = __float2bfloat16(v1);
        __nv_bfloat162 hp; hp.x = h0; hp.y = h1;
        __nv_bfloat162 lp;
        lp.x = __float2bfloat16(v0 - __bfloat162float(h0));
        lp.y = __float2bfloat16(v1 - __bfloat162float(h1));
        *(__nv_bfloat162*)(oh + idx) = hp;
        *(__nv_bfloat162*)(ol + idx) = lp;
    }
}

// ---------------------------------------------------------------------------
// Causal softmax: row cached in smem, zero-fill to 128-block end
// ---------------------------------------------------------------------------
__global__ void softmax_kernel(const float* __restrict__ logits,
                               const float* __restrict__ attn_bias,
                               bf16* __restrict__ wh, bf16* __restrict__ wl)
{
    __shared__ float rowbuf[SEQ];
    __shared__ float red[256];
    int t = blockIdx.x;
    int h = blockIdx.y;
    int tid = threadIdx.x;
    size_t base = ((size_t)h * SEQ + t) * SEQ;
    const float* brow = attn_bias + (size_t)t * SEQ;
    int n = t + 1;
    int blockend = ((t >> 7) + 1) << 7;

    float m = -INFINITY;
    for (int T = tid; T < n; T += 256) {
        float l = logits[base + T] + brow[T];
        rowbuf[T] = l;
        m = fmaxf(m, l);
    }
    red[tid] = m; __syncthreads();
    for (int o = 128; o > 0; o >>= 1) { if (tid < o) red[tid] = fmaxf(red[tid], red[tid + o]); __syncthreads(); }
    m = red[0]; __syncthreads();

    float s = 0.f;
    for (int T = tid; T < n; T += 256) {
        float e = expf(rowbuf[T] - m);
        rowbuf[T] = e;
        s += e;
    }
    red[tid] = s; __syncthreads();
    for (int o = 128; o > 0; o >>= 1) { if (tid < o) red[tid] += red[tid + o]; __syncthreads(); }
    float inv = 1.0f / red[0];

    for (int T = tid; T < n; T += 256)
        split_store(rowbuf[T] * inv, wh, wl, base + T);
    for (int T = n + tid; T < blockend; T += 256) {
        wh[base + T] = __float2bfloat16(0.f);
        wl[base + T] = __float2bfloat16(0.f);
    }
}

// ---------------------------------------------------------------------------
// Launcher
// ---------------------------------------------------------------------------
extern "C" void kernel_launch(void* const* d_in, const int* in_sizes, int n_in,
                              void* d_out, int out_size)
{
    const float* x         = (const float*)d_in[0];
    const float* attn_bias = (const float*)d_in[1];
    const float* ln_scale  = (const float*)d_in[2];
    const float* ln_offset = (const float*)d_in[3];
    const float* wq        = (const float*)d_in[4];
    const float* wk        = (const float*)d_in[5];
    const float* wv        = (const float*)d_in[6];
    const float* wo        = (const float*)d_in[7];
    const float* w1        = (const float*)d_in[8];
    const float* b1        = (const float*)d_in[9];
    const float* w2        = (const float*)d_in[10];
    const float* b2        = (const float*)d_in[11];
    float* out = (float*)d_out;

    cudaFuncSetAttribute(gemm_bf16x3<EPI_F32, CM_NONE>,       cudaFuncAttributeMaxDynamicSharedMemorySize, GEMM_SMEM);
    cudaFuncSetAttribute(gemm_bf16x3<EPI_ROPE_HILO, CM_NONE>, cudaFuncAttributeMaxDynamicSharedMemorySize, GEMM_SMEM);
    cudaFuncSetAttribute(gemm_bf16x3<EPI_HILO, CM_NONE>,      cudaFuncAttributeMaxDynamicSharedMemorySize, GEMM_SMEM);
    cudaFuncSetAttribute(gemm_bf16x3<EPI_SCALE, CM_LOGITS>,   cudaFuncAttributeMaxDynamicSharedMemorySize, GEMM_SMEM);
    cudaFuncSetAttribute(gemm_bf16x3<EPI_HILO, CM_AV>,        cudaFuncAttributeMaxDynamicSharedMemorySize, GEMM_SMEM);
    cudaFuncSetAttribute(gemm_bf16x3<EPI_GELU_HILO, CM_NONE>, cudaFuncAttributeMaxDynamicSharedMemorySize, GEMM_SMEM);

    bf16 *xnh, *xnl, *qh, *ql, *kh, *kl, *vth, *vtl, *wgh, *wgl, *avh, *avl, *ffh, *ffl;
    bf16 *wqth, *wqtl, *wkth, *wktl, *wvth, *wvtl, *woth, *wotl, *w1th, *w1tl, *w2th, *w2tl;
    float *logits, *attnout, *ropetab, *ffpart;
    cudaGetSymbolAddress((void**)&xnh, g_xnh);   cudaGetSymbolAddress((void**)&xnl, g_xnl);
    cudaGetSymbolAddress((void**)&qh, g_qh);     cudaGetSymbolAddress((void**)&ql, g_ql);
    cudaGetSymbolAddress((void**)&kh, g_kh);     cudaGetSymbolAddress((void**)&kl, g_kl);
    cudaGetSymbolAddress((void**)&vth, g_vth);   cudaGetSymbolAddress((void**)&vtl, g_vtl);
    cudaGetSymbolAddress((void**)&logits, g_logits);
    cudaGetSymbolAddress((void**)&wgh, g_wgh);   cudaGetSymbolAddress((void**)&wgl, g_wgl);
    cudaGetSymbolAddress((void**)&avh, g_avh);   cudaGetSymbolAddress((void**)&avl, g_avl);
    cudaGetSymbolAddress((void**)&attnout, g_attnout);
    cudaGetSymbolAddress((void**)&ffh, g_ffh);   cudaGetSymbolAddress((void**)&ffl, g_ffl);
    cudaGetSymbolAddress((void**)&ffpart, g_ffpart);
    cudaGetSymbolAddress((void**)&ropetab, g_ropetab);
    cudaGetSymbolAddress((void**)&wqth, g_wqth); cudaGetSymbolAddress((void**)&wqtl, g_wqtl);
    cudaGetSymbolAddress((void**)&wkth, g_wkth); cudaGetSymbolAddress((void**)&wktl, g_wktl);
    cudaGetSymbolAddress((void**)&wvth, g_wvth); cudaGetSymbolAddress((void**)&wvtl, g_wvtl);
    cudaGetSymbolAddress((void**)&woth, g_woth); cudaGetSymbolAddress((void**)&wotl, g_wotl);
    cudaGetSymbolAddress((void**)&w1th, g_w1th); cudaGetSymbolAddress((void**)&w1tl, g_w1tl);
    cudaGetSymbolAddress((void**)&w2th, g_w2th); cudaGetSymbolAddress((void**)&w2tl, g_w2tl);

    // rope table + weight prep
    ropetab_kernel<<<(SEQ * 32 + 255) / 256, 256>>>(ropetab);
    transcvt_kernel<<<dim3(DM / 64, DM / 64), 256>>>(wq, DM, DM, wqth, wqtl);
    transcvt_kernel<<<dim3(DM / 64, DM / 64), 256>>>(wk, DM, DM, wkth, wktl);
    transcvt_kernel<<<dim3(DM / 64, DM / 64), 256>>>(wv, DM, DM, wvth, wvtl);
    transcvt_kernel<<<dim3(DM / 64, DM / 64), 256>>>(wo, DM, DM, woth, wotl);
    transcvt_kernel<<<dim3(DFF / 64, DM / 64), 256>>>(w1, DM, DFF, w1th, w1tl);
    transcvt_kernel<<<dim3(DM / 64, DFF / 64), 256>>>(w2, DFF, DM, w2th, w2tl);

    ln_kernel<<<SEQ, 256>>>(x, ln_scale, ln_offset, xnh, xnl);

    // Q, K (rope fused) projections
    dim3 gProj(DM / BN, SEQ / BM, 1);
    gemm_bf16x3<EPI_ROPE_HILO, CM_NONE><<<gProj, 256, GEMM_SMEM>>>(
        xnh, xnl, DM, 0, wqth, wqtl, DM, 0, DM,
        nullptr, qh, ql, DM, 0, nullptr, nullptr, 1.f, ropetab);
    gemm_bf16x3<EPI_ROPE_HILO, CM_NONE><<<gProj, 256, GEMM_SMEM>>>(
        xnh, xnl, DM, 0, wkth, wktl, DM, 0, DM,
        nullptr, kh, kl, DM, 0, nullptr, nullptr, 1.f, ropetab);

    // vt[DM,SEQ] = wv^T @ xn^T computed directly: A=wvt, B=xn
    dim3 gVT(SEQ / BN, DM / BM, 1);
    gemm_bf16x3<EPI_HILO, CM_NONE><<<gVT, 256, GEMM_SMEM>>>(
        wvth, wvtl, DM, 0, xnh, xnl, DM, 0, DM,
        nullptr, vth, vtl, SEQ, 0, nullptr, nullptr, 1.f, nullptr);

    // logits[h] = q_h @ k_h^T / 16 (skip fully masked tiles)
    dim3 gLog(SEQ / BN, SEQ / BM, NH);
    gemm_bf16x3<EPI_SCALE, CM_LOGITS><<<gLog, 256, GEMM_SMEM>>>(
        qh, ql, DM, DH, kh, kl, DM, DH, DH,
        logits, nullptr, nullptr, SEQ, (unsigned long long)SEQ * SEQ,
        nullptr, nullptr, 0.0625f, nullptr);

    softmax_kernel<<<dim3(SEQ, NH), 256>>>(logits, attn_bias, wgh, wgl);

    // attn_vec[h] = W_h @ v_h  (variable K, longest-first)
    dim3 gAV(DH / BN, SEQ / BM, NH);
    gemm_bf16x3<EPI_HILO, CM_AV><<<gAV, 256, GEMM_SMEM>>>(
        wgh, wgl, SEQ, (unsigned long long)SEQ * SEQ,
        vth, vtl, SEQ, (unsigned long long)DH * SEQ, SEQ,
        nullptr, avh, avl, DM, DH, nullptr, nullptr, 1.f, nullptr);

    gemm_bf16x3<EPI_F32, CM_NONE><<<gProj, 256, GEMM_SMEM>>>(
        avh, avl, DM, 0, woth, wotl, DM, 0, DM,
        attnout, nullptr, nullptr, DM, 0, nullptr, nullptr, 1.f, nullptr);

    dim3 gFF1(DFF / BN, SEQ / BM, 1);
    gemm_bf16x3<EPI_GELU_HILO, CM_NONE><<<gFF1, 256, GEMM_SMEM>>>(
        xnh, xnl, DM, 0, w1th, w1tl, DM, 0, DM,
        nullptr, ffh, ffl, DFF, 0, b1, nullptr, 1.f, nullptr);

    // FF2 split-K over z=4: partial[z] = ff[:, z*4096:(z+1)*4096] @ w2t[:, same]^T
    dim3 gFF2(DM / BN, SEQ / BM, 4);
    gemm_bf16x3<EPI_F32, CM_NONE><<<gFF2, 256, GEMM_SMEM>>>(
        ffh, ffl, DFF, 4096ull, w2th, w2tl, DFF, 4096ull, 4096,
        ffpart, nullptr, nullptr, DM, (unsigned long long)SEQ * DM,
        nullptr, nullptr, 1.f, nullptr);

    // out = sum(partials) + b2 + attnout
    splitk_reduce_kernel<<<(SEQ * DM / 4) / 256, 256>>>(ffpart, b2, attnout, out);
}

// round 11
// speedup vs baseline: 1.1560x; 1.0188x over previous
#include <cuda_runtime.h>
#include <cuda_bf16.h>
#include <math.h>
#include <stdint.h>

typedef __nv_bfloat16 bf16;

#define SEQ 2048
#define DM  4096
#define NH  16
#define DH  256
#define DFF 16384

// GEMM tiling: CTA 128x256, BK=64, 8 warps (2x4), warp tile 64x64, 2-stage
#define BM 128
#define BN 256
#define BK 64
#define A_TILE_B 16384
#define B_TILE_B 32768
#define BUF_B    (2 * A_TILE_B + 2 * B_TILE_B)   // 96KB
#define GEMM_SMEM (2 * BUF_B)                    // 192KB

// ---------------------------------------------------------------------------
// Device-global scratch
// ---------------------------------------------------------------------------
__device__ bf16 g_xnh[SEQ*DM], g_xnl[SEQ*DM];
__device__ bf16 g_qh[SEQ*DM], g_ql[SEQ*DM], g_kh[SEQ*DM], g_kl[SEQ*DM];
__device__ bf16 g_vth[(size_t)DM*SEQ], g_vtl[(size_t)DM*SEQ];
__device__ float g_logits[(size_t)NH*SEQ*SEQ];
__device__ bf16 g_wgh[(size_t)NH*SEQ*SEQ], g_wgl[(size_t)NH*SEQ*SEQ];
__device__ bf16 g_avh[SEQ*DM], g_avl[SEQ*DM];
__device__ bf16 g_ffh[(size_t)SEQ*DFF], g_ffl[(size_t)SEQ*DFF];
__device__ float g_part[(size_t)4*SEQ*DM];       // shared split-K partials (Q/K/vt)
__device__ float g_wopart[(size_t)4*SEQ*DM];     // WO partials
__device__ float g_ffpart[(size_t)4*SEQ*DM];     // FF2 partials
__device__ float g_ropetab[SEQ * 64];
__device__ bf16 g_wqth[(size_t)DM*DM],  g_wqtl[(size_t)DM*DM];
__device__ bf16 g_wkth[(size_t)DM*DM],  g_wktl[(size_t)DM*DM];
__device__ bf16 g_wvth[(size_t)DM*DM],  g_wvtl[(size_t)DM*DM];
__device__ bf16 g_woth[(size_t)DM*DM],  g_wotl[(size_t)DM*DM];
__device__ bf16 g_w1th[(size_t)DFF*DM], g_w1tl[(size_t)DFF*DM];
__device__ bf16 g_w2th[(size_t)DM*DFF], g_w2tl[(size_t)DM*DFF];

// ---------------------------------------------------------------------------
// PTX helpers
// ---------------------------------------------------------------------------
__device__ __forceinline__ uint32_t smem_u32(const void* p) {
    uint32_t r;
    asm("{ .reg .u64 t; cvta.to.shared.u64 t, %1; cvt.u32.u64 %0, t; }" : "=r"(r) : "l"(p));
    return r;
}
__device__ __forceinline__ void cp16(uint32_t dst, const void* src) {
    asm volatile("cp.async.cg.shared.global [%0], [%1], 16;" :: "r"(dst), "l"(src));
}
#define CP_COMMIT() asm volatile("cp.async.commit_group;")
#define CP_WAIT(n)  asm volatile("cp.async.wait_group %0;" :: "n"(n))

#define LDMX4(r, a) \
    asm volatile("ldmatrix.sync.aligned.m8n8.x4.shared.b16 {%0,%1,%2,%3}, [%4];" \
        : "=r"((r)[0]), "=r"((r)[1]), "=r"((r)[2]), "=r"((r)[3]) : "r"(a))

#define MMA16816(c, a, b0, b1) \
    asm volatile("mma.sync.aligned.m16n8k16.row.col.f32.bf16.bf16.f32 " \
        "{%0,%1,%2,%3}, {%4,%5,%6,%7}, {%8,%9}, {%0,%1,%2,%3};" \
        : "+f"((c)[0]), "+f"((c)[1]), "+f"((c)[2]), "+f"((c)[3]) \
        : "r"((a)[0]), "r"((a)[1]), "r"((a)[2]), "r"((a)[3]), \
          "r"(b0), "r"(b1))

__device__ __forceinline__ void split_store(float v, bf16* ph, bf16* pl, size_t idx) {
    bf16 h = __float2bfloat16(v);
    ph[idx] = h;
    pl[idx] = __float2bfloat16(v - __bfloat162float(h));
}
__device__ __forceinline__ void hilo2_store(float v0, float v1, bf16* ph, bf16* pl, size_t idx) {
    bf16 h0 = __float2bfloat16(v0), h1 = __float2bfloat16(v1);
    __nv_bfloat162 hp; hp.x = h0; hp.y = h1;
    __nv_bfloat162 lp;
    lp.x = __float2bfloat16(v0 - __bfloat162float(h0));
    lp.y = __float2bfloat16(v1 - __bfloat162float(h1));
    *(__nv_bfloat162*)(ph + idx) = hp;
    *(__nv_bfloat162*)(pl + idx) = lp;
}

// Epilogues (compile-time)
#define EPI_F32       0
#define EPI_SCALE     1
#define EPI_HILO      2
#define EPI_GELU_HILO 3
// Causal modes (compile-time)
#define CM_NONE   0
#define CM_LOGITS 1
#define CM_AV     2

__device__ __forceinline__ float gelu_tanh(float v) {
    const float c = 0.7978845608028654f;
    float t = tanhf(c * (v + 0.044715f * v * v * v));
    return 0.5f * v * (1.0f + t);
}

// ---------------------------------------------------------------------------
// Split-bf16 tensor-core GEMM: C[M,N] = A @ B^T, template-specialized epilogue
// ---------------------------------------------------------------------------
template<int EPI, int CMODE>
__global__ void __launch_bounds__(256, 1) gemm_bf16x3(
    const bf16* __restrict__ Ah, const bf16* __restrict__ Al, int lda, unsigned long long sA,
    const bf16* __restrict__ Bh, const bf16* __restrict__ Bl, int ldb, unsigned long long sB,
    int K,
    float* __restrict__ Cf, bf16* __restrict__ Ch, bf16* __restrict__ Cl,
    int ldc, unsigned long long sC,
    const float* __restrict__ bias, float scale)
{
    int bmi = (CMODE == CM_AV) ? ((int)gridDim.y - 1 - (int)blockIdx.y) : (int)blockIdx.y;
    int bm = bmi * BM;
    int bn = blockIdx.x * BN;
    if (CMODE == CM_LOGITS && bn >= bm + BM) return;

    Ah += (size_t)blockIdx.z * sA;  Al += (size_t)blockIdx.z * sA;
    Bh += (size_t)blockIdx.z * sB;  Bl += (size_t)blockIdx.z * sB;
    size_t coff = (size_t)blockIdx.z * sC;

    extern __shared__ char smem[];
    uint32_t sb = smem_u32(smem);
    int tid = threadIdx.x;
    int wid = tid >> 5, lane = tid & 31;
    int warp_m = wid >> 2, warp_n = wid & 3;

    int a_r  = ((lane >> 3) & 1) * 8 + (lane & 7);
    int a_cb = (lane >> 4) * 16;
    int b_r  = (lane >> 4) * 8 + (lane & 7);
    int b_cb = ((lane >> 3) & 1) * 16;

    float acc[4][8][4];
    #pragma unroll
    for (int i = 0; i < 4; i++)
        #pragma unroll
        for (int j = 0; j < 8; j++)
            #pragma unroll
            for (int e = 0; e < 4; e++) acc[i][j][e] = 0.f;

#define LOAD_CHUNK(k0, bufb) do {                                              \
        _Pragma("unroll")                                                      \
        for (int t = 0; t < 4; t++) {                                          \
            int ch = tid + t * 256;                                            \
            int row = ch >> 3, c = ch & 7;                                     \
            uint32_t off = row * 128 + ((c * 16) ^ ((row * 16) & 0x70));       \
            cp16((bufb) + off,            Ah + (size_t)(bm + row) * lda + (k0) + c * 8); \
            cp16((bufb) + A_TILE_B + off, Al + (size_t)(bm + row) * lda + (k0) + c * 8); \
        }                                                                      \
        _Pragma("unroll")                                                      \
        for (int t = 0; t < 8; t++) {                                          \
            int ch = tid + t * 256;                                            \
            int row = ch >> 3, c = ch & 7;                                     \
            uint32_t off = row * 128 + ((c * 16) ^ ((row * 16) & 0x70));       \
            cp16((bufb) + 2*A_TILE_B + off,            Bh + (size_t)(bn + row) * ldb + (k0) + c * 8); \
            cp16((bufb) + 2*A_TILE_B + B_TILE_B + off, Bl + (size_t)(bn + row) * ldb + (k0) + c * 8); \
        }                                                                      \
    } while (0)

    int Keff = (CMODE == CM_AV) ? (bm + BM) : K;
    int nk = Keff / BK;

    LOAD_CHUNK(0, sb);
    CP_COMMIT();

    for (int i = 0; i < nk; i++) {
        uint32_t bufb = sb + (uint32_t)(i & 1) * BUF_B;
        if (i + 1 < nk) {
            uint32_t nb = sb + (uint32_t)((i + 1) & 1) * BUF_B;
            LOAD_CHUNK((i + 1) * BK, nb);
            CP_COMMIT();
            CP_WAIT(1);
        } else {
            CP_WAIT(0);
        }
        __syncthreads();

        #pragma unroll
        for (int ks = 0; ks < 4; ks++) {
            uint32_t ahf[4][4], alf[4][4];
            #pragma unroll
            for (int mt = 0; mt < 4; mt++) {
                int row = warp_m * 64 + mt * 16 + a_r;
                uint32_t cb = ks * 32 + a_cb;
                uint32_t off = row * 128 + (cb ^ ((row * 16) & 0x70));
                LDMX4(ahf[mt], bufb + off);
                LDMX4(alf[mt], bufb + A_TILE_B + off);
            }
            uint32_t bhf[8][2], blf[8][2];
            #pragma unroll
            for (int p = 0; p < 4; p++) {
                int row = warp_n * 64 + p * 16 + b_r;
                uint32_t cb = ks * 32 + b_cb;
                uint32_t off = row * 128 + (cb ^ ((row * 16) & 0x70));
                uint32_t r[4];
                LDMX4(r, bufb + 2 * A_TILE_B + off);
                bhf[2*p][0] = r[0]; bhf[2*p][1] = r[1];
                bhf[2*p+1][0] = r[2]; bhf[2*p+1][1] = r[3];
                LDMX4(r, bufb + 2 * A_TILE_B + B_TILE_B + off);
                blf[2*p][0] = r[0]; blf[2*p][1] = r[1];
                blf[2*p+1][0] = r[2]; blf[2*p+1][1] = r[3];
            }
            #pragma unroll
            for (int mt = 0; mt < 4; mt++)
                #pragma unroll
                for (int nt = 0; nt < 8; nt++) {
                    MMA16816(acc[mt][nt], ahf[mt], bhf[nt][0], bhf[nt][1]);
                    MMA16816(acc[mt][nt], ahf[mt], blf[nt][0], blf[nt][1]);
                    MMA16816(acc[mt][nt], alf[mt], bhf[nt][0], bhf[nt][1]);
                }
        }
        __syncthreads();
    }
#undef LOAD_CHUNK

    // Epilogue (template-pruned)
    int g = lane >> 2, tg = lane & 3;
    #pragma unroll
    for (int mt = 0; mt < 4; mt++) {
        #pragma unroll
        for (int nt = 0; nt < 8; nt++) {
            int row0 = bm + warp_m * 64 + mt * 16 + g;
            int col  = bn + warp_n * 64 + nt * 8 + tg * 2;
            float* a = acc[mt][nt];
            #pragma unroll
            for (int half = 0; half < 2; half++) {
                int row = row0 + half * 8;
                float v0 = a[half * 2 + 0], v1 = a[half * 2 + 1];
                size_t idx = coff + (size_t)row * ldc + col;
                if (EPI == EPI_F32) {
                    *(float2*)(Cf + idx) = make_float2(v0, v1);
                } else if (EPI == EPI_SCALE) {
                    *(float2*)(Cf + idx) = make_float2(v0 * scale, v1 * scale);
                } else if (EPI == EPI_HILO) {
                    hilo2_store(v0, v1, Ch, Cl, idx);
                } else if (EPI == EPI_GELU_HILO) {
                    float g0 = gelu_tanh(v0 + bias[col]);
                    float g1 = gelu_tanh(v1 + bias[col + 1]);
                    hilo2_store(g0, g1, Ch, Cl, idx);
                }
            }
        }
    }
}

// ---------------------------------------------------------------------------
// Split-K reduce: sum 4 partials, apply rope, hi/lo split (for Q and K)
// Element pairs (even col, odd col); rope on d = col & 255 < 64.
// ---------------------------------------------------------------------------
__global__ void reduce_rope_hilo_kernel(const float* __restrict__ part,
                                        const float* __restrict__ ropetab,
                                        bf16* __restrict__ oh, bf16* __restrict__ ol)
{
    size_t i2 = (size_t)blockIdx.x * 256 + threadIdx.x;   // float2 index
    size_t i = i2 * 2;
    const size_t S = (size_t)SEQ * DM;
    float2 p0 = *(const float2*)(part + i);
    float2 p1 = *(const float2*)(part + S + i);
    float2 p2 = *(const float2*)(part + 2 * S + i);
    float2 p3 = *(const float2*)(part + 3 * S + i);
    float v0 = p0.x + p1.x + p2.x + p3.x;
    float v1 = p0.y + p1.y + p2.y + p3.y;
    int col = (int)(i & (DM - 1));
    int row = (int)(i >> 12);       // i / DM
    int d = col & (DH - 1);
    if (d < 64) {
        float s = ropetab[row * 64 + d];
        float c = ropetab[row * 64 + d + 1];
        float n0 = v0 * c - v1 * s;
        float n1 = v1 * c + v0 * s;
        v0 = n0; v1 = n1;
    }
    hilo2_store(v0, v1, oh, ol, i);
}

// ---------------------------------------------------------------------------
// Split-K reduce: sum 4 partials, hi/lo split (for vt)
// ---------------------------------------------------------------------------
__global__ void reduce_hilo_kernel(const float* __restrict__ part,
                                   bf16* __restrict__ oh, bf16* __restrict__ ol)
{
    size_t i2 = (size_t)blockIdx.x * 256 + threadIdx.x;
    size_t i = i2 * 2;
    const size_t S = (size_t)SEQ * DM;
    float2 p0 = *(const float2*)(part + i);
    float2 p1 = *(const float2*)(part + S + i);
    float2 p2 = *(const float2*)(part + 2 * S + i);
    float2 p3 = *(const float2*)(part + 3 * S + i);
    hilo2_store(p0.x + p1.x + p2.x + p3.x, p0.y + p1.y + p2.y + p3.y, oh, ol, i);
}

// ---------------------------------------------------------------------------
// Final reduce: out = sum4(ffpart) + sum4(wopart) + b2[col]
// ---------------------------------------------------------------------------
__global__ void reduce_final_kernel(const float* __restrict__ ffp,
                                    const float* __restrict__ wop,
                                    const float* __restrict__ bias,
                                    float* __restrict__ out)
{
    size_t i4 = (size_t)blockIdx.x * 256 + threadIdx.x;
    size_t i = i4 * 4;
    const size_t S = (size_t)SEQ * DM;
    float4 r = *(const float4*)(bias + (i & (DM - 1)));
    #pragma unroll
    for (int z = 0; z < 4; z++) {
        float4 a = *(const float4*)(ffp + z * S + i);
        float4 b = *(const float4*)(wop + z * S + i);
        r.x += a.x + b.x; r.y += a.y + b.y;
        r.z += a.z + b.z; r.w += a.w + b.w;
    }
    *(float4*)(out + i) = r;
}

// ---------------------------------------------------------------------------
// RoPE sin/cos table (fp64): tab[t*64+2i]=sin, tab[t*64+2i+1]=cos
// ---------------------------------------------------------------------------
__global__ void ropetab_kernel(float* __restrict__ tab)
{
    int idx = blockIdx.x * 256 + threadIdx.x;
    if (idx >= SEQ * 32) return;
    int i = idx & 31, t = idx >> 5;
    double inv = exp(-(double)i * (9.210340371976184 / 32.0));
    double s, c;
    sincos((double)t * inv, &s, &c);
    tab[t * 64 + 2 * i]     = (float)s;
    tab[t * 64 + 2 * i + 1] = (float)c;
}

// ---------------------------------------------------------------------------
// LayerNorm -> hi/lo bf16
// ---------------------------------------------------------------------------
__global__ void ln_kernel(const float* __restrict__ x,
                          const float* __restrict__ scale,
                          const float* __restrict__ offset,
                          bf16* __restrict__ xh, bf16* __restrict__ xl)
{
    __shared__ float red[256];
    int row = blockIdx.x;
    int tid = threadIdx.x;
    const float* xr = x + (size_t)row * DM;

    float s = 0.f;
    for (int i = tid; i < DM; i += 256) s += xr[i];
    red[tid] = s; __syncthreads();
    for (int o = 128; o > 0; o >>= 1) { if (tid < o) red[tid] += red[tid + o]; __syncthreads(); }
    float mean = red[0] / (float)DM;
    __syncthreads();

    float v = 0.f;
    for (int i = tid; i < DM; i += 256) { float d = xr[i] - mean; v += d * d; }
    red[tid] = v; __syncthreads();
    for (int o = 128; o > 0; o >>= 1) { if (tid < o) red[tid] += red[tid + o]; __syncthreads(); }
    float r = rsqrtf(red[0] / (float)DM + 1e-5f);

    for (int i = tid; i < DM; i += 256) {
        float y = scale[i] * r * (xr[i] - mean) + offset[i];
        split_store(y, xh, xl, (size_t)row * DM + i);
    }
}

// ---------------------------------------------------------------------------
// Transpose + hi/lo convert: 64x64 tiles, float4 loads, bf162 stores
// ---------------------------------------------------------------------------
__global__ void transcvt_kernel(const float* __restrict__ in, int R, int C,
                                bf16* __restrict__ oh, bf16* __restrict__ ol)
{
    __shared__ float t[64][65];
    int c0 = blockIdx.x * 64;
    int r0 = blockIdx.y * 64;
    int tid = threadIdx.x;
    #pragma unroll
    for (int p = 0; p < 4; p++) {
        int f = tid + p * 256;
        int row = f >> 4, c4 = (f & 15) * 4;
        float4 v = *(const float4*)(in + (size_t)(r0 + row) * C + c0 + c4);
        t[row][c4 + 0] = v.x; t[row][c4 + 1] = v.y;
        t[row][c4 + 2] = v.z; t[row][c4 + 3] = v.w;
    }
    __syncthreads();
    #pragma unroll
    for (int p = 0; p < 8; p++) {
        int w = tid + p * 256;
        int c = w >> 5, rp = (w & 31) * 2;
        float v0 = t[rp][c], v1 = t[rp + 1][c];
        size_t idx = (size_t)(c0 + c) * R + r0 + rp;
        hilo2_store(v0, v1, oh, ol, idx);
    }
}

// ---------------------------------------------------------------------------
// Causal softmax: row cached in smem, zero-fill to 128-block end
// ---------------------------------------------------------------------------
__global__ void softmax_kernel(const float* __restrict__ logits,
                               const float* __restrict__ attn_bias,
                               bf16* __restrict__ wh, bf16* __restrict__ wl)
{
    __shared__ float rowbuf[SEQ];
    __shared__ float red[256];
    int t = blockIdx.x;
    int h = blockIdx.y;
    int tid = threadIdx.x;
    size_t base = ((size_t)h * SEQ + t) * SEQ;
    const float* brow = attn_bias + (size_t)t * SEQ;
    int n = t + 1;
    int blockend = ((t >> 7) + 1) << 7;

    float m = -INFINITY;
    for (int T = tid; T < n; T += 256) {
        float l = logits[base + T] + brow[T];
        rowbuf[T] = l;
        m = fmaxf(m, l);
    }
    red[tid] = m; __syncthreads();
    for (int o = 128; o > 0; o >>= 1) { if (tid < o) red[tid] = fmaxf(red[tid], red[tid + o]); __syncthreads(); }
    m = red[0]; __syncthreads();

    float s = 0.f;
    for (int T = tid; T < n; T += 256) {
        float e = expf(rowbuf[T] - m);
        rowbuf[T] = e;
        s += e;
    }
    red[tid] = s; __syncthreads();
    for (int o = 128; o > 0; o >>= 1) { if (tid < o) red[tid] += red[tid + o]; __syncthreads(); }
    float inv = 1.0f / red[0];

    for (int T = tid; T < n; T += 256)
        split_store(rowbuf[T] * inv, wh, wl, base + T);
    for (int T = n + tid; T < blockend; T += 256) {
        wh[base + T] = __float2bfloat16(0.f);
        wl[base + T] = __float2bfloat16(0.f);
    }
}

// ---------------------------------------------------------------------------
// Launcher
// ---------------------------------------------------------------------------
extern "C" void kernel_launch(void* const* d_in, const int* in_sizes, int n_in,
                              void* d_out, int out_size)
{
    const float* x         = (const float*)d_in[0];
    const float* attn_bias = (const float*)d_in[1];
    const float* ln_scale  = (const float*)d_in[2];
    const float* ln_offset = (const float*)d_in[3];
    const float* wq        = (const float*)d_in[4];
    const float* wk        = (const float*)d_in[5];
    const float* wv        = (const float*)d_in[6];
    const float* wo        = (const float*)d_in[7];
    const float* w1        = (const float*)d_in[8];
    const float* b1        = (const float*)d_in[9];
    const float* w2        = (const float*)d_in[10];
    const float* b2        = (const float*)d_in[11];
    float* out = (float*)d_out;

    cudaFuncSetAttribute(gemm_bf16x3<EPI_F32, CM_NONE>,       cudaFuncAttributeMaxDynamicSharedMemorySize, GEMM_SMEM);
    cudaFuncSetAttribute(gemm_bf16x3<EPI_SCALE, CM_LOGITS>,   cudaFuncAttributeMaxDynamicSharedMemorySize, GEMM_SMEM);
    cudaFuncSetAttribute(gemm_bf16x3<EPI_HILO, CM_AV>,        cudaFuncAttributeMaxDynamicSharedMemorySize, GEMM_SMEM);
    cudaFuncSetAttribute(gemm_bf16x3<EPI_GELU_HILO, CM_NONE>, cudaFuncAttributeMaxDynamicSharedMemorySize, GEMM_SMEM);

    bf16 *xnh, *xnl, *qh, *ql, *kh, *kl, *vth, *vtl, *wgh, *wgl, *avh, *avl, *ffh, *ffl;
    bf16 *wqth, *wqtl, *wkth, *wktl, *wvth, *wvtl, *woth, *wotl, *w1th, *w1tl, *w2th, *w2tl;
    float *logits, *ropetab, *part, *wopart, *ffpart;
    cudaGetSymbolAddress((void**)&xnh, g_xnh);   cudaGetSymbolAddress((void**)&xnl, g_xnl);
    cudaGetSymbolAddress((void**)&qh, g_qh);     cudaGetSymbolAddress((void**)&ql, g_ql);
    cudaGetSymbolAddress((void**)&kh, g_kh);     cudaGetSymbolAddress((void**)&kl, g_kl);
    cudaGetSymbolAddress((void**)&vth, g_vth);   cudaGetSymbolAddress((void**)&vtl, g_vtl);
    cudaGetSymbolAddress((void**)&logits, g_logits);
    cudaGetSymbolAddress((void**)&wgh, g_wgh);   cudaGetSymbolAddress((void**)&wgl, g_wgl);
    cudaGetSymbolAddress((void**)&avh, g_avh);   cudaGetSymbolAddress((void**)&avl, g_avl);
    cudaGetSymbolAddress((void**)&ffh, g_ffh);   cudaGetSymbolAddress((void**)&ffl, g_ffl);
    cudaGetSymbolAddress((void**)&part, g_part);
    cudaGetSymbolAddress((void**)&wopart, g_wopart);
    cudaGetSymbolAddress((void**)&ffpart, g_ffpart);
    cudaGetSymbolAddress((void**)&ropetab, g_ropetab);
    cudaGetSymbolAddress((void**)&wqth, g_wqth); cudaGetSymbolAddress((void**)&wqtl, g_wqtl);
    cudaGetSymbolAddress((void**)&wkth, g_wkth); cudaGetSymbolAddress((void**)&wktl, g_wktl);
    cudaGetSymbolAddress((void**)&wvth, g_wvth); cudaGetSymbolAddress((void**)&wvtl, g_wvtl);
    cudaGetSymbolAddress((void**)&woth, g_woth); cudaGetSymbolAddress((void**)&wotl, g_wotl);
    cudaGetSymbolAddress((void**)&w1th, g_w1th); cudaGetSymbolAddress((void**)&w1tl, g_w1tl);
    cudaGetSymbolAddress((void**)&w2th, g_w2th); cudaGetSymbolAddress((void**)&w2tl, g_w2tl);

    const unsigned long long S = (unsigned long long)SEQ * DM;

    // rope table + weight prep
    ropetab_kernel<<<(SEQ * 32 + 255) / 256, 256>>>(ropetab);
    transcvt_kernel<<<dim3(DM / 64, DM / 64), 256>>>(wq, DM, DM, wqth, wqtl);
    transcvt_kernel<<<dim3(DM / 64, DM / 64), 256>>>(wk, DM, DM, wkth, wktl);
    transcvt_kernel<<<dim3(DM / 64, DM / 64), 256>>>(wv, DM, DM, wvth, wvtl);
    transcvt_kernel<<<dim3(DM / 64, DM / 64), 256>>>(wo, DM, DM, woth, wotl);
    transcvt_kernel<<<dim3(DFF / 64, DM / 64), 256>>>(w1, DM, DFF, w1th, w1tl);
    transcvt_kernel<<<dim3(DM / 64, DFF / 64), 256>>>(w2, DFF, DM, w2th, w2tl);

    ln_kernel<<<SEQ, 256>>>(x, ln_scale, ln_offset, xnh, xnl);

    int nred2 = (int)(S / 2 / 256);

    // Q projection: split-K=4 -> partials -> rope+hilo reduce
    dim3 gProj(DM / BN, SEQ / BM, 4);
    gemm_bf16x3<EPI_F32, CM_NONE><<<gProj, 256, GEMM_SMEM>>>(
        xnh, xnl, DM, 1024ull, wqth, wqtl, DM, 1024ull, 1024,
        part, nullptr, nullptr, DM, S, nullptr, 1.f);
    reduce_rope_hilo_kernel<<<nred2, 256>>>(part, ropetab, qh, ql);

    // K projection
    gemm_bf16x3<EPI_F32, CM_NONE><<<gProj, 256, GEMM_SMEM>>>(
        xnh, xnl, DM, 1024ull, wkth, wktl, DM, 1024ull, 1024,
        part, nullptr, nullptr, DM, S, nullptr, 1.f);
    reduce_rope_hilo_kernel<<<nred2, 256>>>(part, ropetab, kh, kl);

    // vt[DM,SEQ] = wv^T @ xn^T: split-K=4
    dim3 gVT(SEQ / BN, DM / BM, 4);
    gemm_bf16x3<EPI_F32, CM_NONE><<<gVT, 256, GEMM_SMEM>>>(
        wvth, wvtl, DM, 1024ull, xnh, xnl, DM, 1024ull, 1024,
        part, nullptr, nullptr, SEQ, S, nullptr, 1.f);
    reduce_hilo_kernel<<<nred2, 256>>>(part, vth, vtl);

    // logits[h] = q_h @ k_h^T / 16 (skip fully masked tiles)
    dim3 gLog(SEQ / BN, SEQ / BM, NH);
    gemm_bf16x3<EPI_SCALE, CM_LOGITS><<<gLog, 256, GEMM_SMEM>>>(
        qh, ql, DM, DH, kh, kl, DM, DH, DH,
        logits, nullptr, nullptr, SEQ, (unsigned long long)SEQ * SEQ,
        nullptr, 0.0625f);

    softmax_kernel<<<dim3(SEQ, NH), 256>>>(logits, attn_bias, wgh, wgl);

    // attn_vec[h] = W_h @ v_h  (variable K, longest-first)
    dim3 gAV(DH / BN, SEQ / BM, NH);
    gemm_bf16x3<EPI_HILO, CM_AV><<<gAV, 256, GEMM_SMEM>>>(
        wgh, wgl, SEQ, (unsigned long long)SEQ * SEQ,
        vth, vtl, SEQ, (unsigned long long)DH * SEQ, SEQ,
        nullptr, avh, avl, DM, DH, nullptr, 1.f);

    // WO: split-K=4 -> wopart (reduced in final)
    gemm_bf16x3<EPI_F32, CM_NONE><<<gProj, 256, GEMM_SMEM>>>(
        avh, avl, DM, 1024ull, woth, wotl, DM, 1024ull, 1024,
        wopart, nullptr, nullptr, DM, S, nullptr, 1.f);

    // FF1: gelu(xn @ w1 + b1) -> hilo
    dim3 gFF1(DFF / BN, SEQ / BM, 1);
    gemm_bf16x3<EPI_GELU_HILO, CM_NONE><<<gFF1, 256, GEMM_SMEM>>>(
        xnh, xnl, DM, 0, w1th, w1tl, DM, 0, DM,
        nullptr, ffh, ffl, DFF, 0, b1, 1.f);

    // FF2: split-K=4 -> ffpart
    dim3 gFF2(DM / BN, SEQ / BM, 4);
    gemm_bf16x3<EPI_F32, CM_NONE><<<gFF2, 256, GEMM_SMEM>>>(
        ffh, ffl, DFF, 4096ull, w2th, w2tl, DFF, 4096ull, 4096,
        ffpart, nullptr, nullptr, DM, S, nullptr, 1.f);

    // out = sum4(ffpart) + sum4(wopart) + b2
    reduce_final_kernel<<<(int)(S / 4 / 256), 256>>>(ffpart, wopart, b2, out);
}

// round 12
// speedup vs baseline: 1.4254x; 1.2331x over previous
#include <cuda_runtime.h>
#include <cuda_bf16.h>
#include <cuda_fp16.h>
#include <math.h>
#include <stdint.h>

typedef __nv_bfloat16 bf16;

#define SEQ 2048
#define DM  4096
#define NH  16
#define DH  256
#define DFF 16384

// GEMM tiling: CTA 128x256, BK=64, 8 warps (2x4), warp tile 64x64, 2-stage
#define BM 128
#define BN 256
#define BK 64
#define A_TILE_B 16384
#define B_TILE_B 32768
#define BUF_B    (2 * A_TILE_B + 2 * B_TILE_B)   // 96KB
#define GEMM_SMEM (2 * BUF_B)                    // 192KB

// ---------------------------------------------------------------------------
// Device-global scratch
// ---------------------------------------------------------------------------
__device__ bf16 g_xnh[SEQ*DM], g_xnl[SEQ*DM];
__device__ __half g_xnh16[SEQ*DM], g_xnl16[SEQ*DM];
__device__ bf16 g_qh[SEQ*DM], g_ql[SEQ*DM], g_kh[SEQ*DM], g_kl[SEQ*DM];
__device__ bf16 g_vth[(size_t)DM*SEQ], g_vtl[(size_t)DM*SEQ];
__device__ float g_logits[(size_t)NH*SEQ*SEQ];
__device__ bf16 g_wgh[(size_t)NH*SEQ*SEQ], g_wgl[(size_t)NH*SEQ*SEQ];
__device__ bf16 g_avh[SEQ*DM], g_avl[SEQ*DM];
__device__ __half g_ffh16[(size_t)SEQ*DFF], g_ffl16[(size_t)SEQ*DFF];
__device__ float g_part[(size_t)4*SEQ*DM];       // shared split-K partials (Q/K/vt)
__device__ float g_wopart[(size_t)4*SEQ*DM];     // WO partials
__device__ float g_ffpart[(size_t)4*SEQ*DM];     // FF2 partials
__device__ float g_ropetab[SEQ * 64];
__device__ bf16 g_wqth[(size_t)DM*DM],  g_wqtl[(size_t)DM*DM];
__device__ bf16 g_wkth[(size_t)DM*DM],  g_wktl[(size_t)DM*DM];
__device__ bf16 g_wvth[(size_t)DM*DM],  g_wvtl[(size_t)DM*DM];
__device__ bf16 g_woth[(size_t)DM*DM],  g_wotl[(size_t)DM*DM];
__device__ __half g_w1t16[(size_t)DFF*DM];       // w1^T single fp16
__device__ __half g_w2t16[(size_t)DM*DFF];       // w2^T single fp16

// ---------------------------------------------------------------------------
// PTX helpers
// ---------------------------------------------------------------------------
__device__ __forceinline__ uint32_t smem_u32(const void* p) {
    uint32_t r;
    asm("{ .reg .u64 t; cvta.to.shared.u64 t, %1; cvt.u32.u64 %0, t; }" : "=r"(r) : "l"(p));
    return r;
}
__device__ __forceinline__ void cp16(uint32_t dst, const void* src) {
    asm volatile("cp.async.cg.shared.global [%0], [%1], 16;" :: "r"(dst), "l"(src));
}
#define CP_COMMIT() asm volatile("cp.async.commit_group;")
#define CP_WAIT(n)  asm volatile("cp.async.wait_group %0;" :: "n"(n))

#define LDMX4(r, a) \
    asm volatile("ldmatrix.sync.aligned.m8n8.x4.shared.b16 {%0,%1,%2,%3}, [%4];" \
        : "=r"((r)[0]), "=r"((r)[1]), "=r"((r)[2]), "=r"((r)[3]) : "r"(a))

// MMA variants selected by operand-type tag
__device__ __forceinline__ void mma_t(float* c, const uint32_t* a, uint32_t b0, uint32_t b1, bf16*) {
    asm volatile("mma.sync.aligned.m16n8k16.row.col.f32.bf16.bf16.f32 "
        "{%0,%1,%2,%3}, {%4,%5,%6,%7}, {%8,%9}, {%0,%1,%2,%3};"
        : "+f"(c[0]), "+f"(c[1]), "+f"(c[2]), "+f"(c[3])
        : "r"(a[0]), "r"(a[1]), "r"(a[2]), "r"(a[3]), "r"(b0), "r"(b1));
}
__device__ __forceinline__ void mma_t(float* c, const uint32_t* a, uint32_t b0, uint32_t b1, __half*) {
    asm volatile("mma.sync.aligned.m16n8k16.row.col.f32.f16.f16.f32 "
        "{%0,%1,%2,%3}, {%4,%5,%6,%7}, {%8,%9}, {%0,%1,%2,%3};"
        : "+f"(c[0]), "+f"(c[1]), "+f"(c[2]), "+f"(c[3])
        : "r"(a[0]), "r"(a[1]), "r"(a[2]), "r"(a[3]), "r"(b0), "r"(b1));
}

__device__ __forceinline__ void split_store(float v, bf16* ph, bf16* pl, size_t idx) {
    bf16 h = __float2bfloat16(v);
    ph[idx] = h;
    pl[idx] = __float2bfloat16(v - __bfloat162float(h));
}
__device__ __forceinline__ void hilo2_store(float v0, float v1, bf16* ph, bf16* pl, size_t idx) {
    bf16 h0 = __float2bfloat16(v0), h1 = __float2bfloat16(v1);
    __nv_bfloat162 hp; hp.x = h0; hp.y = h1;
    __nv_bfloat162 lp;
    lp.x = __float2bfloat16(v0 - __bfloat162float(h0));
    lp.y = __float2bfloat16(v1 - __bfloat162float(h1));
    *(__nv_bfloat162*)(ph + idx) = hp;
    *(__nv_bfloat162*)(pl + idx) = lp;
}
__device__ __forceinline__ void hilo2_store(float v0, float v1, __half* ph, __half* pl, size_t idx) {
    __half h0 = __float2half_rn(v0), h1 = __float2half_rn(v1);
    *(__half2*)(ph + idx) = __halves2half2(h0, h1);
    *(__half2*)(pl + idx) = __halves2half2(__float2half_rn(v0 - __half2float(h0)),
                                           __float2half_rn(v1 - __half2float(h1)));
}

// Epilogues (compile-time)
#define EPI_F32       0
#define EPI_SCALE     1
#define EPI_HILO      2
#define EPI_GELU_HILO 3
// Causal modes (compile-time)
#define CM_NONE   0
#define CM_LOGITS 1
#define CM_AV     2

__device__ __forceinline__ float gelu_tanh(float v) {
    const float c = 0.7978845608028654f;
    float t = tanhf(c * (v + 0.044715f * v * v * v));
    return 0.5f * v * (1.0f + t);
}

// ---------------------------------------------------------------------------
// Split tensor-core GEMM: C[M,N] = A @ B^T.
// NP=3 (bf16): A hi/lo, B hi/lo, passes Ah*Bh + Ah*Bl + Al*Bh.
// NP=2 (fp16): A hi/lo, B single,  passes Ah*Bh + Al*Bh.
// fp32 accumulate; 2-stage cp.async double buffer, BK=64.
// ---------------------------------------------------------------------------
template<typename T, int NP, int EPI, int CMODE>
__global__ void __launch_bounds__(256, 1) gemm_split(
    const T* __restrict__ Ah, const T* __restrict__ Al, int lda, unsigned long long sA,
    const T* __restrict__ Bh, const T* __restrict__ Bl, int ldb, unsigned long long sB,
    int K,
    float* __restrict__ Cf, T* __restrict__ Ch, T* __restrict__ Cl,
    int ldc, unsigned long long sC,
    const float* __restrict__ bias, float scale)
{
    int bmi = (CMODE == CM_AV) ? ((int)gridDim.y - 1 - (int)blockIdx.y) : (int)blockIdx.y;
    int bm = bmi * BM;
    int bn = blockIdx.x * BN;
    if (CMODE == CM_LOGITS && bn >= bm + BM) return;

    Ah += (size_t)blockIdx.z * sA;  Al += (size_t)blockIdx.z * sA;
    Bh += (size_t)blockIdx.z * sB;
    if (NP == 3) Bl += (size_t)blockIdx.z * sB;
    size_t coff = (size_t)blockIdx.z * sC;

    extern __shared__ char smem[];
    uint32_t sb = smem_u32(smem);
    int tid = threadIdx.x;
    int wid = tid >> 5, lane = tid & 31;
    int warp_m = wid >> 2, warp_n = wid & 3;

    int a_r  = ((lane >> 3) & 1) * 8 + (lane & 7);
    int a_cb = (lane >> 4) * 16;
    int b_r  = (lane >> 4) * 8 + (lane & 7);
    int b_cb = ((lane >> 3) & 1) * 16;

    float acc[4][8][4];
    #pragma unroll
    for (int i = 0; i < 4; i++)
        #pragma unroll
        for (int j = 0; j < 8; j++)
            #pragma unroll
            for (int e = 0; e < 4; e++) acc[i][j][e] = 0.f;

#define LOAD_CHUNK(k0, bufb) do {                                              \
        _Pragma("unroll")                                                      \
        for (int t = 0; t < 4; t++) {                                          \
            int ch = tid + t * 256;                                            \
            int row = ch >> 3, c = ch & 7;                                     \
            uint32_t off = row * 128 + ((c * 16) ^ ((row * 16) & 0x70));       \
            cp16((bufb) + off,            Ah + (size_t)(bm + row) * lda + (k0) + c * 8); \
            cp16((bufb) + A_TILE_B + off, Al + (size_t)(bm + row) * lda + (k0) + c * 8); \
        }                                                                      \
        _Pragma("unroll")                                                      \
        for (int t = 0; t < 8; t++) {                                          \
            int ch = tid + t * 256;                                            \
            int row = ch >> 3, c = ch & 7;                                     \
            uint32_t off = row * 128 + ((c * 16) ^ ((row * 16) & 0x70));       \
            cp16((bufb) + 2*A_TILE_B + off, Bh + (size_t)(bn + row) * ldb + (k0) + c * 8); \
            if (NP == 3)                                                       \
                cp16((bufb) + 2*A_TILE_B + B_TILE_B + off, Bl + (size_t)(bn + row) * ldb + (k0) + c * 8); \
        }                                                                      \
    } while (0)

    int Keff = (CMODE == CM_AV) ? (bm + BM) : K;
    int nk = Keff / BK;

    LOAD_CHUNK(0, sb);
    CP_COMMIT();

    for (int i = 0; i < nk; i++) {
        uint32_t bufb = sb + (uint32_t)(i & 1) * BUF_B;
        if (i + 1 < nk) {
            uint32_t nb = sb + (uint32_t)((i + 1) & 1) * BUF_B;
            LOAD_CHUNK((i + 1) * BK, nb);
            CP_COMMIT();
            CP_WAIT(1);
        } else {
            CP_WAIT(0);
        }
        __syncthreads();

        #pragma unroll
        for (int ks = 0; ks < 4; ks++) {
            uint32_t ahf[4][4], alf[4][4];
            #pragma unroll
            for (int mt = 0; mt < 4; mt++) {
                int row = warp_m * 64 + mt * 16 + a_r;
                uint32_t cb = ks * 32 + a_cb;
                uint32_t off = row * 128 + (cb ^ ((row * 16) & 0x70));
                LDMX4(ahf[mt], bufb + off);
                LDMX4(alf[mt], bufb + A_TILE_B + off);
            }
            uint32_t bhf[8][2], blf[8][2];
            #pragma unroll
            for (int p = 0; p < 4; p++) {
                int row = warp_n * 64 + p * 16 + b_r;
                uint32_t cb = ks * 32 + b_cb;
                uint32_t off = row * 128 + (cb ^ ((row * 16) & 0x70));
                uint32_t r[4];
                LDMX4(r, bufb + 2 * A_TILE_B + off);
                bhf[2*p][0] = r[0]; bhf[2*p][1] = r[1];
                bhf[2*p+1][0] = r[2]; bhf[2*p+1][1] = r[3];
                if (NP == 3) {
                    LDMX4(r, bufb + 2 * A_TILE_B + B_TILE_B + off);
                    blf[2*p][0] = r[0]; blf[2*p][1] = r[1];
                    blf[2*p+1][0] = r[2]; blf[2*p+1][1] = r[3];
                }
            }
            #pragma unroll
            for (int mt = 0; mt < 4; mt++)
                #pragma unroll
                for (int nt = 0; nt < 8; nt++) {
                    mma_t(acc[mt][nt], ahf[mt], bhf[nt][0], bhf[nt][1], (T*)nullptr);
                    if (NP == 3)
                        mma_t(acc[mt][nt], ahf[mt], blf[nt][0], blf[nt][1], (T*)nullptr);
                    mma_t(acc[mt][nt], alf[mt], bhf[nt][0], bhf[nt][1], (T*)nullptr);
                }
        }
        __syncthreads();
    }
#undef LOAD_CHUNK

    // Epilogue (template-pruned)
    int g = lane >> 2, tg = lane & 3;
    #pragma unroll
    for (int mt = 0; mt < 4; mt++) {
        #pragma unroll
        for (int nt = 0; nt < 8; nt++) {
            int row0 = bm + warp_m * 64 + mt * 16 + g;
            int col  = bn + warp_n * 64 + nt * 8 + tg * 2;
            float* a = acc[mt][nt];
            #pragma unroll
            for (int half = 0; half < 2; half++) {
                int row = row0 + half * 8;
                float v0 = a[half * 2 + 0], v1 = a[half * 2 + 1];
                size_t idx = coff + (size_t)row * ldc + col;
                if (EPI == EPI_F32) {
                    *(float2*)(Cf + idx) = make_float2(v0, v1);
                } else if (EPI == EPI_SCALE) {
                    *(float2*)(Cf + idx) = make_float2(v0 * scale, v1 * scale);
                } else if (EPI == EPI_HILO) {
                    hilo2_store(v0, v1, Ch, Cl, idx);
                } else if (EPI == EPI_GELU_HILO) {
                    float g0 = gelu_tanh(v0 + bias[col]);
                    float g1 = gelu_tanh(v1 + bias[col + 1]);
                    hilo2_store(g0, g1, Ch, Cl, idx);
                }
            }
        }
    }
}

// ---------------------------------------------------------------------------
// Split-K reduce: sum 4 partials, apply rope, hi/lo split (for Q and K)
// ---------------------------------------------------------------------------
__global__ void reduce_rope_hilo_kernel(const float* __restrict__ part,
                                        const float* __restrict__ ropetab,
                                        bf16* __restrict__ oh, bf16* __restrict__ ol)
{
    size_t i2 = (size_t)blockIdx.x * 256 + threadIdx.x;
    size_t i = i2 * 2;
    const size_t S = (size_t)SEQ * DM;
    float2 p0 = *(const float2*)(part + i);
    float2 p1 = *(const float2*)(part + S + i);
    float2 p2 = *(const float2*)(part + 2 * S + i);
    float2 p3 = *(const float2*)(part + 3 * S + i);
    float v0 = p0.x + p1.x + p2.x + p3.x;
    float v1 = p0.y + p1.y + p2.y + p3.y;
    int col = (int)(i & (DM - 1));
    int row = (int)(i >> 12);
    int d = col & (DH - 1);
    if (d < 64) {
        float s = ropetab[row * 64 + d];
        float c = ropetab[row * 64 + d + 1];
        float n0 = v0 * c - v1 * s;
        float n1 = v1 * c + v0 * s;
        v0 = n0; v1 = n1;
    }
    hilo2_store(v0, v1, oh, ol, i);
}

// ---------------------------------------------------------------------------
// Split-K reduce: sum 4 partials, hi/lo split (for vt)
// ---------------------------------------------------------------------------
__global__ void reduce_hilo_kernel(const float* __restrict__ part,
                                   bf16* __restrict__ oh, bf16* __restrict__ ol)
{
    size_t i2 = (size_t)blockIdx.x * 256 + threadIdx.x;
    size_t i = i2 * 2;
    const size_t S = (size_t)SEQ * DM;
    float2 p0 = *(const float2*)(part + i);
    float2 p1 = *(const float2*)(part + S + i);
    float2 p2 = *(const float2*)(part + 2 * S + i);
    float2 p3 = *(const float2*)(part + 3 * S + i);
    hilo2_store(p0.x + p1.x + p2.x + p3.x, p0.y + p1.y + p2.y + p3.y, oh, ol, i);
}

// ---------------------------------------------------------------------------
// Final reduce: out = sum4(ffpart) + sum4(wopart) + b2[col]
// ---------------------------------------------------------------------------
__global__ void reduce_final_kernel(const float* __restrict__ ffp,
                                    const float* __restrict__ wop,
                                    const float* __restrict__ bias,
                                    float* __restrict__ out)
{
    size_t i4 = (size_t)blockIdx.x * 256 + threadIdx.x;
    size_t i = i4 * 4;
    const size_t S = (size_t)SEQ * DM;
    float4 r = *(const float4*)(bias + (i & (DM - 1)));
    #pragma unroll
    for (int z = 0; z < 4; z++) {
        float4 a = *(const float4*)(ffp + z * S + i);
        float4 b = *(const float4*)(wop + z * S + i);
        r.x += a.x + b.x; r.y += a.y + b.y;
        r.z += a.z + b.z; r.w += a.w + b.w;
    }
    *(float4*)(out + i) = r;
}

// ---------------------------------------------------------------------------
// RoPE sin/cos table (fp64)
// ---------------------------------------------------------------------------
__global__ void ropetab_kernel(float* __restrict__ tab)
{
    int idx = blockIdx.x * 256 + threadIdx.x;
    if (idx >= SEQ * 32) return;
    int i = idx & 31, t = idx >> 5;
    double inv = exp(-(double)i * (9.210340371976184 / 32.0));
    double s, c;
    sincos((double)t * inv, &s, &c);
    tab[t * 64 + 2 * i]     = (float)s;
    tab[t * 64 + 2 * i + 1] = (float)c;
}

// ---------------------------------------------------------------------------
// LayerNorm -> bf16 hi/lo + fp16 hi/lo
// ---------------------------------------------------------------------------
__global__ void ln_kernel(const float* __restrict__ x,
                          const float* __restrict__ scale,
                          const float* __restrict__ offset,
                          bf16* __restrict__ xh, bf16* __restrict__ xl,
                          __half* __restrict__ xh16, __half* __restrict__ xl16)
{
    __shared__ float red[256];
    int row = blockIdx.x;
    int tid = threadIdx.x;
    const float* xr = x + (size_t)row * DM;

    float s = 0.f;
    for (int i = tid; i < DM; i += 256) s += xr[i];
    red[tid] = s; __syncthreads();
    for (int o = 128; o > 0; o >>= 1) { if (tid < o) red[tid] += red[tid + o]; __syncthreads(); }
    float mean = red[0] / (float)DM;
    __syncthreads();

    float v = 0.f;
    for (int i = tid; i < DM; i += 256) { float d = xr[i] - mean; v += d * d; }
    red[tid] = v; __syncthreads();
    for (int o = 128; o > 0; o >>= 1) { if (tid < o) red[tid] += red[tid + o]; __syncthreads(); }
    float r = rsqrtf(red[0] / (float)DM + 1e-5f);

    for (int i = tid; i < DM; i += 256) {
        float y = scale[i] * r * (xr[i] - mean) + offset[i];
        size_t idx = (size_t)row * DM + i;
        split_store(y, xh, xl, idx);
        __half h = __float2half_rn(y);
        xh16[idx] = h;
        xl16[idx] = __float2half_rn(y - __half2float(h));
    }
}

// ---------------------------------------------------------------------------
// Transpose + bf16 hi/lo convert: 64x64 tiles
// ---------------------------------------------------------------------------
__global__ void transcvt_kernel(const float* __restrict__ in, int R, int C,
                                bf16* __restrict__ oh, bf16* __restrict__ ol)
{
    __shared__ float t[64][65];
    int c0 = blockIdx.x * 64;
    int r0 = blockIdx.y * 64;
    int tid = threadIdx.x;
    #pragma unroll
    for (int p = 0; p < 4; p++) {
        int f = tid + p * 256;
        int row = f >> 4, c4 = (f & 15) * 4;
        float4 v = *(const float4*)(in + (size_t)(r0 + row) * C + c0 + c4);
        t[row][c4 + 0] = v.x; t[row][c4 + 1] = v.y;
        t[row][c4 + 2] = v.z; t[row][c4 + 3] = v.w;
    }
    __syncthreads();
    #pragma unroll
    for (int p = 0; p < 8; p++) {
        int w = tid + p * 256;
        int c = w >> 5, rp = (w & 31) * 2;
        float v0 = t[rp][c], v1 = t[rp + 1][c];
        size_t idx = (size_t)(c0 + c) * R + r0 + rp;
        hilo2_store(v0, v1, oh, ol, idx);
    }
}

// ---------------------------------------------------------------------------
// Transpose + single fp16 convert (for w1, w2)
// ---------------------------------------------------------------------------
__global__ void transcvt_f16_kernel(const float* __restrict__ in, int R, int C,
                                    __half* __restrict__ o)
{
    __shared__ float t[64][65];
    int c0 = blockIdx.x * 64;
    int r0 = blockIdx.y * 64;
    int tid = threadIdx.x;
    #pragma unroll
    for (int p = 0; p < 4; p++) {
        int f = tid + p * 256;
        int row = f >> 4, c4 = (f & 15) * 4;
        float4 v = *(const float4*)(in + (size_t)(r0 + row) * C + c0 + c4);
        t[row][c4 + 0] = v.x; t[row][c4 + 1] = v.y;
        t[row][c4 + 2] = v.z; t[row][c4 + 3] = v.w;
    }
    __syncthreads();
    #pragma unroll
    for (int p = 0; p < 8; p++) {
        int w = tid + p * 256;
        int c = w >> 5, rp = (w & 31) * 2;
        float v0 = t[rp][c], v1 = t[rp + 1][c];
        size_t idx = (size_t)(c0 + c) * R + r0 + rp;
        *(__half2*)(o + idx) = __halves2half2(__float2half_rn(v0), __float2half_rn(v1));
    }
}

// ---------------------------------------------------------------------------
// Causal softmax: row cached in smem, zero-fill to 128-block end
// ---------------------------------------------------------------------------
__global__ void softmax_kernel(const float* __restrict__ logits,
                               const float* __restrict__ attn_bias,
                               bf16* __restrict__ wh, bf16* __restrict__ wl)
{
    __shared__ float rowbuf[SEQ];
    __shared__ float red[256];
    int t = blockIdx.x;
    int h = blockIdx.y;
    int tid = threadIdx.x;
    size_t base = ((size_t)h * SEQ + t) * SEQ;
    const float* brow = attn_bias + (size_t)t * SEQ;
    int n = t + 1;
    int blockend = ((t >> 7) + 1) << 7;

    float m = -INFINITY;
    for (int T = tid; T < n; T += 256) {
        float l = logits[base + T] + brow[T];
        rowbuf[T] = l;
        m = fmaxf(m, l);
    }
    red[tid] = m; __syncthreads();
    for (int o = 128; o > 0; o >>= 1) { if (tid < o) red[tid] = fmaxf(red[tid], red[tid + o]); __syncthreads(); }
    m = red[0]; __syncthreads();

    float s = 0.f;
    for (int T = tid; T < n; T += 256) {
        float e = expf(rowbuf[T] - m);
        rowbuf[T] = e;
        s += e;
    }
    red[tid] = s; __syncthreads();
    for (int o = 128; o > 0; o >>= 1) { if (tid < o) red[tid] += red[tid + o]; __syncthreads(); }
    float inv = 1.0f / red[0];

    for (int T = tid; T < n; T += 256)
        split_store(rowbuf[T] * inv, wh, wl, base + T);
    for (int T = n + tid; T < blockend; T += 256) {
        wh[base + T] = __float2bfloat16(0.f);
        wl[base + T] = __float2bfloat16(0.f);
    }
}

// ---------------------------------------------------------------------------
// Launcher
// ---------------------------------------------------------------------------
extern "C" void kernel_launch(void* const* d_in, const int* in_sizes, int n_in,
                              void* d_out, int out_size)
{
    const float* x         = (const float*)d_in[0];
    const float* attn_bias = (const float*)d_in[1];
    const float* ln_scale  = (const float*)d_in[2];
    const float* ln_offset = (const float*)d_in[3];
    const float* wq        = (const float*)d_in[4];
    const float* wk        = (const float*)d_in[5];
    const float* wv        = (const float*)d_in[6];
    const float* wo        = (const float*)d_in[7];
    const float* w1        = (const float*)d_in[8];
    const float* b1        = (const float*)d_in[9];
    const float* w2        = (const float*)d_in[10];
    const float* b2        = (const float*)d_in[11];
    float* out = (float*)d_out;

    cudaFuncSetAttribute((const void*)gemm_split<bf16, 3, EPI_F32, CM_NONE>,        cudaFuncAttributeMaxDynamicSharedMemorySize, GEMM_SMEM);
    cudaFuncSetAttribute((const void*)gemm_split<bf16, 3, EPI_SCALE, CM_LOGITS>,    cudaFuncAttributeMaxDynamicSharedMemorySize, GEMM_SMEM);
    cudaFuncSetAttribute((const void*)gemm_split<bf16, 3, EPI_HILO, CM_AV>,         cudaFuncAttributeMaxDynamicSharedMemorySize, GEMM_SMEM);
    cudaFuncSetAttribute((const void*)gemm_split<__half, 2, EPI_GELU_HILO, CM_NONE>, cudaFuncAttributeMaxDynamicSharedMemorySize, GEMM_SMEM);
    cudaFuncSetAttribute((const void*)gemm_split<__half, 2, EPI_F32, CM_NONE>,      cudaFuncAttributeMaxDynamicSharedMemorySize, GEMM_SMEM);

    bf16 *xnh, *xnl, *qh, *ql, *kh, *kl, *vth, *vtl, *wgh, *wgl, *avh, *avl;
    bf16 *wqth, *wqtl, *wkth, *wktl, *wvth, *wvtl, *woth, *wotl;
    __half *xnh16, *xnl16, *ffh16, *ffl16, *w1t16, *w2t16;
    float *logits, *ropetab, *part, *wopart, *ffpart;
    cudaGetSymbolAddress((void**)&xnh, g_xnh);     cudaGetSymbolAddress((void**)&xnl, g_xnl);
    cudaGetSymbolAddress((void**)&xnh16, g_xnh16); cudaGetSymbolAddress((void**)&xnl16, g_xnl16);
    cudaGetSymbolAddress((void**)&qh, g_qh);       cudaGetSymbolAddress((void**)&ql, g_ql);
    cudaGetSymbolAddress((void**)&kh, g_kh);       cudaGetSymbolAddress((void**)&kl, g_kl);
    cudaGetSymbolAddress((void**)&vth, g_vth);     cudaGetSymbolAddress((void**)&vtl, g_vtl);
    cudaGetSymbolAddress((void**)&logits, g_logits);
    cudaGetSymbolAddress((void**)&wgh, g_wgh);     cudaGetSymbolAddress((void**)&wgl, g_wgl);
    cudaGetSymbolAddress((void**)&avh, g_avh);     cudaGetSymbolAddress((void**)&avl, g_avl);
    cudaGetSymbolAddress((void**)&ffh16, g_ffh16); cudaGetSymbolAddress((void**)&ffl16, g_ffl16);
    cudaGetSymbolAddress((void**)&part, g_part);
    cudaGetSymbolAddress((void**)&wopart, g_wopart);
    cudaGetSymbolAddress((void**)&ffpart, g_ffpart);
    cudaGetSymbolAddress((void**)&ropetab, g_ropetab);
    cudaGetSymbolAddress((void**)&wqth, g_wqth);   cudaGetSymbolAddress((void**)&wqtl, g_wqtl);
    cudaGetSymbolAddress((void**)&wkth, g_wkth);   cudaGetSymbolAddress((void**)&wktl, g_wktl);
    cudaGetSymbolAddress((void**)&wvth, g_wvth);   cudaGetSymbolAddress((void**)&wvtl, g_wvtl);
    cudaGetSymbolAddress((void**)&woth, g_woth);   cudaGetSymbolAddress((void**)&wotl, g_wotl);
    cudaGetSymbolAddress((void**)&w1t16, g_w1t16);
    cudaGetSymbolAddress((void**)&w2t16, g_w2t16);

    const unsigned long long S = (unsigned long long)SEQ * DM;

    // rope table + weight prep
    ropetab_kernel<<<(SEQ * 32 + 255) / 256, 256>>>(ropetab);
    transcvt_kernel<<<dim3(DM / 64, DM / 64), 256>>>(wq, DM, DM, wqth, wqtl);
    transcvt_kernel<<<dim3(DM / 64, DM / 64), 256>>>(wk, DM, DM, wkth, wktl);
    transcvt_kernel<<<dim3(DM / 64, DM / 64), 256>>>(wv, DM, DM, wvth, wvtl);
    transcvt_kernel<<<dim3(DM / 64, DM / 64), 256>>>(wo, DM, DM, woth, wotl);
    transcvt_f16_kernel<<<dim3(DFF / 64, DM / 64), 256>>>(w1, DM, DFF, w1t16);
    transcvt_f16_kernel<<<dim3(DM / 64, DFF / 64), 256>>>(w2, DFF, DM, w2t16);

    ln_kernel<<<SEQ, 256>>>(x, ln_scale, ln_offset, xnh, xnl, xnh16, xnl16);

    int nred2 = (int)(S / 2 / 256);

    // Q projection: split-K=4 -> partials -> rope+hilo reduce
    dim3 gProj(DM / BN, SEQ / BM, 4);
    gemm_split<bf16, 3, EPI_F32, CM_NONE><<<gProj, 256, GEMM_SMEM>>>(
        xnh, xnl, DM, 1024ull, wqth, wqtl, DM, 1024ull, 1024,
        part, nullptr, nullptr, DM, S, nullptr, 1.f);
    reduce_rope_hilo_kernel<<<nred2, 256>>>(part, ropetab, qh, ql);

    // K projection
    gemm_split<bf16, 3, EPI_F32, CM_NONE><<<gProj, 256, GEMM_SMEM>>>(
        xnh, xnl, DM, 1024ull, wkth, wktl, DM, 1024ull, 1024,
        part, nullptr, nullptr, DM, S, nullptr, 1.f);
    reduce_rope_hilo_kernel<<<nred2, 256>>>(part, ropetab, kh, kl);

    // vt[DM,SEQ] = wv^T @ xn^T: split-K=4
    dim3 gVT(SEQ / BN, DM / BM, 4);
    gemm_split<bf16, 3, EPI_F32, CM_NONE><<<gVT, 256, GEMM_SMEM>>>(
        wvth, wvtl, DM, 1024ull, xnh, xnl, DM, 1024ull, 1024,
        part, nullptr, nullptr, SEQ, S, nullptr, 1.f);
    reduce_hilo_kernel<<<nred2, 256>>>(part, vth, vtl);

    // logits[h] = q_h @ k_h^T / 16 (skip fully masked tiles)
    dim3 gLog(SEQ / BN, SEQ / BM, NH);
    gemm_split<bf16, 3, EPI_SCALE, CM_LOGITS><<<gLog, 256, GEMM_SMEM>>>(
        qh, ql, DM, DH, kh, kl, DM, DH, DH,
        logits, nullptr, nullptr, SEQ, (unsigned long long)SEQ * SEQ,
        nullptr, 0.0625f);

    softmax_kernel<<<dim3(SEQ, NH), 256>>>(logits, attn_bias, wgh, wgl);

    // attn_vec[h] = W_h @ v_h  (variable K, longest-first)
    dim3 gAV(DH / BN, SEQ / BM, NH);
    gemm_split<bf16, 3, EPI_HILO, CM_AV><<<gAV, 256, GEMM_SMEM>>>(
        wgh, wgl, SEQ, (unsigned long long)SEQ * SEQ,
        vth, vtl, SEQ, (unsigned long long)DH * SEQ, SEQ,
        nullptr, avh, avl, DM, DH, nullptr, 1.f);

    // WO: split-K=4 -> wopart (reduced in final)
    gemm_split<bf16, 3, EPI_F32, CM_NONE><<<gProj, 256, GEMM_SMEM>>>(
        avh, avl, DM, 1024ull, woth, wotl, DM, 1024ull, 1024,
        wopart, nullptr, nullptr, DM, S, nullptr, 1.f);

    // FF1: gelu(xn @ w1 + b1) -> fp16 hilo (fp16 2-pass: A hi/lo, B single)
    dim3 gFF1(DFF / BN, SEQ / BM, 1);
    gemm_split<__half, 2, EPI_GELU_HILO, CM_NONE><<<gFF1, 256, GEMM_SMEM>>>(
        xnh16, xnl16, DM, 0, w1t16, nullptr, DM, 0, DM,
        nullptr, ffh16, ffl16, DFF, 0, b1, 1.f);

    // FF2: split-K=4 -> ffpart (fp16 2-pass)
    dim3 gFF2(DM / BN, SEQ / BM, 4);
    gemm_split<__half, 2, EPI_F32, CM_NONE><<<gFF2, 256, GEMM_SMEM>>>(
        ffh16, ffl16, DFF, 4096ull, w2t16, nullptr, DFF, 4096ull, 4096,
        ffpart, nullptr, nullptr, DM, S, nullptr, 1.f);

    // out = sum4(ffpart) + sum4(wopart) + b2
    reduce_final_kernel<<<(int)(S / 4 / 256), 256>>>(ffpart, wopart, b2, out);
}

// round 13
// speedup vs baseline: 1.5257x; 1.0704x over previous
#include <cuda_runtime.h>
#include <cuda_bf16.h>
#include <cuda_fp16.h>
#include <math.h>
#include <stdint.h>

typedef __nv_bfloat16 bf16;

#define SEQ 2048
#define DM  4096
#define NH  16
#define DH  256
#define DFF 16384

// GEMM tiling: CTA 128x256, BK=64, 8 warps (2x4), warp tile 64x64, 2-stage
#define BM 128
#define BN 256
#define BK 64
#define A_TILE_B 16384
#define B_TILE_B 32768
#define BUF_B    (2 * A_TILE_B + 2 * B_TILE_B)   // 96KB
#define GEMM_SMEM (2 * BUF_B)                    // 192KB

// ---------------------------------------------------------------------------
// Device-global scratch
// ---------------------------------------------------------------------------
__device__ bf16 g_xnh[SEQ*DM], g_xnl[SEQ*DM];
__device__ __half g_xnh16[SEQ*DM], g_xnl16[SEQ*DM];
__device__ bf16 g_qh[SEQ*DM], g_ql[SEQ*DM], g_kh[SEQ*DM], g_kl[SEQ*DM];
__device__ __half g_vth16[(size_t)DM*SEQ];
__device__ float g_logits[(size_t)NH*SEQ*SEQ];
__device__ __half g_wgh16[(size_t)NH*SEQ*SEQ], g_wgl16[(size_t)NH*SEQ*SEQ];
__device__ __half g_avh16[SEQ*DM], g_avl16[SEQ*DM];
__device__ __half g_ffh16[(size_t)SEQ*DFF], g_ffl16[(size_t)SEQ*DFF];
__device__ float g_part[(size_t)4*SEQ*DM];       // shared split-K partials (Q/K/vt)
__device__ float g_wopart[(size_t)4*SEQ*DM];     // WO partials
__device__ float g_ffpart[(size_t)4*SEQ*DM];     // FF2 partials
__device__ float g_ropetab[SEQ * 64];
__device__ bf16 g_wqth[(size_t)DM*DM],  g_wqtl[(size_t)DM*DM];
__device__ bf16 g_wkth[(size_t)DM*DM],  g_wktl[(size_t)DM*DM];
__device__ __half g_wvth16[(size_t)DM*DM], g_wvtl16[(size_t)DM*DM];
__device__ __half g_wot16[(size_t)DM*DM];
__device__ __half g_w1t16[(size_t)DFF*DM];
__device__ __half g_w2t16[(size_t)DM*DFF];

// ---------------------------------------------------------------------------
// PTX helpers
// ---------------------------------------------------------------------------
__device__ __forceinline__ uint32_t smem_u32(const void* p) {
    uint32_t r;
    asm("{ .reg .u64 t; cvta.to.shared.u64 t, %1; cvt.u32.u64 %0, t; }" : "=r"(r) : "l"(p));
    return r;
}
__device__ __forceinline__ void cp16(uint32_t dst, const void* src) {
    asm volatile("cp.async.cg.shared.global [%0], [%1], 16;" :: "r"(dst), "l"(src));
}
#define CP_COMMIT() asm volatile("cp.async.commit_group;")
#define CP_WAIT(n)  asm volatile("cp.async.wait_group %0;" :: "n"(n))

#define LDMX4(r, a) \
    asm volatile("ldmatrix.sync.aligned.m8n8.x4.shared.b16 {%0,%1,%2,%3}, [%4];" \
        : "=r"((r)[0]), "=r"((r)[1]), "=r"((r)[2]), "=r"((r)[3]) : "r"(a))

// MMA variants selected by operand-type tag
__device__ __forceinline__ void mma_t(float* c, const uint32_t* a, uint32_t b0, uint32_t b1, bf16*) {
    asm volatile("mma.sync.aligned.m16n8k16.row.col.f32.bf16.bf16.f32 "
        "{%0,%1,%2,%3}, {%4,%5,%6,%7}, {%8,%9}, {%0,%1,%2,%3};"
        : "+f"(c[0]), "+f"(c[1]), "+f"(c[2]), "+f"(c[3])
        : "r"(a[0]), "r"(a[1]), "r"(a[2]), "r"(a[3]), "r"(b0), "r"(b1));
}
__device__ __forceinline__ void mma_t(float* c, const uint32_t* a, uint32_t b0, uint32_t b1, __half*) {
    asm volatile("mma.sync.aligned.m16n8k16.row.col.f32.f16.f16.f32 "
        "{%0,%1,%2,%3}, {%4,%5,%6,%7}, {%8,%9}, {%0,%1,%2,%3};"
        : "+f"(c[0]), "+f"(c[1]), "+f"(c[2]), "+f"(c[3])
        : "r"(a[0]), "r"(a[1]), "r"(a[2]), "r"(a[3]), "r"(b0), "r"(b1));
}

__device__ __forceinline__ void split_store(float v, bf16* ph, bf16* pl, size_t idx) {
    bf16 h = __float2bfloat16(v);
    ph[idx] = h;
    pl[idx] = __float2bfloat16(v - __bfloat162float(h));
}
__device__ __forceinline__ void split_store(float v, __half* ph, __half* pl, size_t idx) {
    __half h = __float2half_rn(v);
    ph[idx] = h;
    pl[idx] = __float2half_rn(v - __half2float(h));
}
__device__ __forceinline__ void hilo2_store(float v0, float v1, bf16* ph, bf16* pl, size_t idx) {
    bf16 h0 = __float2bfloat16(v0), h1 = __float2bfloat16(v1);
    __nv_bfloat162 hp; hp.x = h0; hp.y = h1;
    __nv_bfloat162 lp;
    lp.x = __float2bfloat16(v0 - __bfloat162float(h0));
    lp.y = __float2bfloat16(v1 - __bfloat162float(h1));
    *(__nv_bfloat162*)(ph + idx) = hp;
    *(__nv_bfloat162*)(pl + idx) = lp;
}
__device__ __forceinline__ void hilo2_store(float v0, float v1, __half* ph, __half* pl, size_t idx) {
    __half h0 = __float2half_rn(v0), h1 = __float2half_rn(v1);
    *(__half2*)(ph + idx) = __halves2half2(h0, h1);
    *(__half2*)(pl + idx) = __halves2half2(__float2half_rn(v0 - __half2float(h0)),
                                           __float2half_rn(v1 - __half2float(h1)));
}

// Epilogues (compile-time)
#define EPI_F32       0
#define EPI_SCALE     1
#define EPI_HILO      2
#define EPI_GELU_HILO 3
// Causal modes (compile-time)
#define CM_NONE   0
#define CM_LOGITS 1
#define CM_AV     2

__device__ __forceinline__ float gelu_tanh(float v) {
    const float c = 0.7978845608028654f;
    float t = tanhf(c * (v + 0.044715f * v * v * v));
    return 0.5f * v * (1.0f + t);
}

// ---------------------------------------------------------------------------
// Split tensor-core GEMM: C[M,N] = A @ B^T.
// NP=3 (bf16): A hi/lo, B hi/lo, passes Ah*Bh + Ah*Bl + Al*Bh.
// NP=2 (fp16): A hi/lo, B single,  passes Ah*Bh + Al*Bh.
// fp32 accumulate; 2-stage cp.async double buffer, BK=64.
// ---------------------------------------------------------------------------
template<typename T, int NP, int EPI, int CMODE>
__global__ void __launch_bounds__(256, 1) gemm_split(
    const T* __restrict__ Ah, const T* __restrict__ Al, int lda, unsigned long long sA,
    const T* __restrict__ Bh, const T* __restrict__ Bl, int ldb, unsigned long long sB,
    int K,
    float* __restrict__ Cf, T* __restrict__ Ch, T* __restrict__ Cl,
    int ldc, unsigned long long sC,
    const float* __restrict__ bias, float scale)
{
    int bmi = (CMODE == CM_AV) ? ((int)gridDim.y - 1 - (int)blockIdx.y) : (int)blockIdx.y;
    int bm = bmi * BM;
    int bn = blockIdx.x * BN;
    if (CMODE == CM_LOGITS && bn >= bm + BM) return;

    Ah += (size_t)blockIdx.z * sA;  Al += (size_t)blockIdx.z * sA;
    Bh += (size_t)blockIdx.z * sB;
    if (NP == 3) Bl += (size_t)blockIdx.z * sB;
    size_t coff = (size_t)blockIdx.z * sC;

    extern __shared__ char smem[];
    uint32_t sb = smem_u32(smem);
    int tid = threadIdx.x;
    int wid = tid >> 5, lane = tid & 31;
    int warp_m = wid >> 2, warp_n = wid & 3;

    int a_r  = ((lane >> 3) & 1) * 8 + (lane & 7);
    int a_cb = (lane >> 4) * 16;
    int b_r  = (lane >> 4) * 8 + (lane & 7);
    int b_cb = ((lane >> 3) & 1) * 16;

    float acc[4][8][4];
    #pragma unroll
    for (int i = 0; i < 4; i++)
        #pragma unroll
        for (int j = 0; j < 8; j++)
            #pragma unroll
            for (int e = 0; e < 4; e++) acc[i][j][e] = 0.f;

#define LOAD_CHUNK(k0, bufb) do {                                              \
        _Pragma("unroll")                                                      \
        for (int t = 0; t < 4; t++) {                                          \
            int ch = tid + t * 256;                                            \
            int row = ch >> 3, c = ch & 7;                                     \
            uint32_t off = row * 128 + ((c * 16) ^ ((row * 16) & 0x70));       \
            cp16((bufb) + off,            Ah + (size_t)(bm + row) * lda + (k0) + c * 8); \
            cp16((bufb) + A_TILE_B + off, Al + (size_t)(bm + row) * lda + (k0) + c * 8); \
        }                                                                      \
        _Pragma("unroll")                                                      \
        for (int t = 0; t < 8; t++) {                                          \
            int ch = tid + t * 256;                                            \
            int row = ch >> 3, c = ch & 7;                                     \
            uint32_t off = row * 128 + ((c * 16) ^ ((row * 16) & 0x70));       \
            cp16((bufb) + 2*A_TILE_B + off, Bh + (size_t)(bn + row) * ldb + (k0) + c * 8); \
            if (NP == 3)                                                       \
                cp16((bufb) + 2*A_TILE_B + B_TILE_B + off, Bl + (size_t)(bn + row) * ldb + (k0) + c * 8); \
        }                                                                      \
    } while (0)

    int Keff = (CMODE == CM_AV) ? (bm + BM) : K;
    int nk = Keff / BK;

    LOAD_CHUNK(0, sb);
    CP_COMMIT();

    for (int i = 0; i < nk; i++) {
        uint32_t bufb = sb + (uint32_t)(i & 1) * BUF_B;
        if (i + 1 < nk) {
            uint32_t nb = sb + (uint32_t)((i + 1) & 1) * BUF_B;
            LOAD_CHUNK((i + 1) * BK, nb);
            CP_COMMIT();
            CP_WAIT(1);
        } else {
            CP_WAIT(0);
        }
        __syncthreads();

        #pragma unroll
        for (int ks = 0; ks < 4; ks++) {
            uint32_t ahf[4][4], alf[4][4];
            #pragma unroll
            for (int mt = 0; mt < 4; mt++) {
                int row = warp_m * 64 + mt * 16 + a_r;
                uint32_t cb = ks * 32 + a_cb;
                uint32_t off = row * 128 + (cb ^ ((row * 16) & 0x70));
                LDMX4(ahf[mt], bufb + off);
                LDMX4(alf[mt], bufb + A_TILE_B + off);
            }
            uint32_t bhf[8][2], blf[8][2];
            #pragma unroll
            for (int p = 0; p < 4; p++) {
                int row = warp_n * 64 + p * 16 + b_r;
                uint32_t cb = ks * 32 + b_cb;
                uint32_t off = row * 128 + (cb ^ ((row * 16) & 0x70));
                uint32_t r[4];
                LDMX4(r, bufb + 2 * A_TILE_B + off);
                bhf[2*p][0] = r[0]; bhf[2*p][1] = r[1];
                bhf[2*p+1][0] = r[2]; bhf[2*p+1][1] = r[3];
                if (NP == 3) {
                    LDMX4(r, bufb + 2 * A_TILE_B + B_TILE_B + off);
                    blf[2*p][0] = r[0]; blf[2*p][1] = r[1];
                    blf[2*p+1][0] = r[2]; blf[2*p+1][1] = r[3];
                }
            }
            #pragma unroll
            for (int mt = 0; mt < 4; mt++)
                #pragma unroll
                for (int nt = 0; nt < 8; nt++) {
                    mma_t(acc[mt][nt], ahf[mt], bhf[nt][0], bhf[nt][1], (T*)nullptr);
                    if (NP == 3)
                        mma_t(acc[mt][nt], ahf[mt], blf[nt][0], blf[nt][1], (T*)nullptr);
                    mma_t(acc[mt][nt], alf[mt], bhf[nt][0], bhf[nt][1], (T*)nullptr);
                }
        }
        __syncthreads();
    }
#undef LOAD_CHUNK

    // Epilogue (template-pruned)
    int g = lane >> 2, tg = lane & 3;
    #pragma unroll
    for (int mt = 0; mt < 4; mt++) {
        #pragma unroll
        for (int nt = 0; nt < 8; nt++) {
            int row0 = bm + warp_m * 64 + mt * 16 + g;
            int col  = bn + warp_n * 64 + nt * 8 + tg * 2;
            float* a = acc[mt][nt];
            #pragma unroll
            for (int half = 0; half < 2; half++) {
                int row = row0 + half * 8;
                float v0 = a[half * 2 + 0], v1 = a[half * 2 + 1];
                size_t idx = coff + (size_t)row * ldc + col;
                if (EPI == EPI_F32) {
                    *(float2*)(Cf + idx) = make_float2(v0, v1);
                } else if (EPI == EPI_SCALE) {
                    *(float2*)(Cf + idx) = make_float2(v0 * scale, v1 * scale);
                } else if (EPI == EPI_HILO) {
                    hilo2_store(v0, v1, Ch, Cl, idx);
                } else if (EPI == EPI_GELU_HILO) {
                    float g0 = gelu_tanh(v0 + bias[col]);
                    float g1 = gelu_tanh(v1 + bias[col + 1]);
                    hilo2_store(g0, g1, Ch, Cl, idx);
                }
            }
        }
    }
}

// ---------------------------------------------------------------------------
// Split-K reduce: sum 4 partials, apply rope, bf16 hi/lo split (Q, K)
// ---------------------------------------------------------------------------
__global__ void reduce_rope_hilo_kernel(const float* __restrict__ part,
                                        const float* __restrict__ ropetab,
                                        bf16* __restrict__ oh, bf16* __restrict__ ol)
{
    size_t i2 = (size_t)blockIdx.x * 256 + threadIdx.x;
    size_t i = i2 * 2;
    const size_t S = (size_t)SEQ * DM;
    float2 p0 = *(const float2*)(part + i);
    float2 p1 = *(const float2*)(part + S + i);
    float2 p2 = *(const float2*)(part + 2 * S + i);
    float2 p3 = *(const float2*)(part + 3 * S + i);
    float v0 = p0.x + p1.x + p2.x + p3.x;
    float v1 = p0.y + p1.y + p2.y + p3.y;
    int col = (int)(i & (DM - 1));
    int row = (int)(i >> 12);
    int d = col & (DH - 1);
    if (d < 64) {
        float s = ropetab[row * 64 + d];
        float c = ropetab[row * 64 + d + 1];
        float n0 = v0 * c - v1 * s;
        float n1 = v1 * c + v0 * s;
        v0 = n0; v1 = n1;
    }
    hilo2_store(v0, v1, oh, ol, i);
}

// ---------------------------------------------------------------------------
// Split-K reduce: sum 4 partials -> single fp16 (vt)
// ---------------------------------------------------------------------------
__global__ void reduce_f16_kernel(const float* __restrict__ part,
                                  __half* __restrict__ o)
{
    size_t i2 = (size_t)blockIdx.x * 256 + threadIdx.x;
    size_t i = i2 * 2;
    const size_t S = (size_t)SEQ * DM;
    float2 p0 = *(const float2*)(part + i);
    float2 p1 = *(const float2*)(part + S + i);
    float2 p2 = *(const float2*)(part + 2 * S + i);
    float2 p3 = *(const float2*)(part + 3 * S + i);
    *(__half2*)(o + i) = __halves2half2(
        __float2half_rn(p0.x + p1.x + p2.x + p3.x),
        __float2half_rn(p0.y + p1.y + p2.y + p3.y));
}

// ---------------------------------------------------------------------------
// Final reduce: out = sum4(ffpart) + sum4(wopart) + b2[col]
// ---------------------------------------------------------------------------
__global__ void reduce_final_kernel(const float* __restrict__ ffp,
                                    const float* __restrict__ wop,
                                    const float* __restrict__ bias,
                                    float* __restrict__ out)
{
    size_t i4 = (size_t)blockIdx.x * 256 + threadIdx.x;
    size_t i = i4 * 4;
    const size_t S = (size_t)SEQ * DM;
    float4 r = *(const float4*)(bias + (i & (DM - 1)));
    #pragma unroll
    for (int z = 0; z < 4; z++) {
        float4 a = *(const float4*)(ffp + z * S + i);
        float4 b = *(const float4*)(wop + z * S + i);
        r.x += a.x + b.x; r.y += a.y + b.y;
        r.z += a.z + b.z; r.w += a.w + b.w;
    }
    *(float4*)(out + i) = r;
}

// ---------------------------------------------------------------------------
// RoPE sin/cos table (fp64)
// ---------------------------------------------------------------------------
__global__ void ropetab_kernel(float* __restrict__ tab)
{
    int idx = blockIdx.x * 256 + threadIdx.x;
    if (idx >= SEQ * 32) return;
    int i = idx & 31, t = idx >> 5;
    double inv = exp(-(double)i * (9.210340371976184 / 32.0));
    double s, c;
    sincos((double)t * inv, &s, &c);
    tab[t * 64 + 2 * i]     = (float)s;
    tab[t * 64 + 2 * i + 1] = (float)c;
}

// ---------------------------------------------------------------------------
// LayerNorm -> bf16 hi/lo + fp16 hi/lo
// ---------------------------------------------------------------------------
__global__ void ln_kernel(const float* __restrict__ x,
                          const float* __restrict__ scale,
                          const float* __restrict__ offset,
                          bf16* __restrict__ xh, bf16* __restrict__ xl,
                          __half* __restrict__ xh16, __half* __restrict__ xl16)
{
    __shared__ float red[256];
    int row = blockIdx.x;
    int tid = threadIdx.x;
    const float* xr = x + (size_t)row * DM;

    float s = 0.f;
    for (int i = tid; i < DM; i += 256) s += xr[i];
    red[tid] = s; __syncthreads();
    for (int o = 128; o > 0; o >>= 1) { if (tid < o) red[tid] += red[tid + o]; __syncthreads(); }
    float mean = red[0] / (float)DM;
    __syncthreads();

    float v = 0.f;
    for (int i = tid; i < DM; i += 256) { float d = xr[i] - mean; v += d * d; }
    red[tid] = v; __syncthreads();
    for (int o = 128; o > 0; o >>= 1) { if (tid < o) red[tid] += red[tid + o]; __syncthreads(); }
    float r = rsqrtf(red[0] / (float)DM + 1e-5f);

    for (int i = tid; i < DM; i += 256) {
        float y = scale[i] * r * (xr[i] - mean) + offset[i];
        size_t idx = (size_t)row * DM + i;
        split_store(y, xh, xl, idx);
        split_store(y, xh16, xl16, idx);
    }
}

// ---------------------------------------------------------------------------
// Transpose + bf16 hi/lo convert: 64x64 tiles
// ---------------------------------------------------------------------------
__global__ void transcvt_kernel(const float* __restrict__ in, int R, int C,
                                bf16* __restrict__ oh, bf16* __restrict__ ol)
{
    __shared__ float t[64][65];
    int c0 = blockIdx.x * 64;
    int r0 = blockIdx.y * 64;
    int tid = threadIdx.x;
    #pragma unroll
    for (int p = 0; p < 4; p++) {
        int f = tid + p * 256;
        int row = f >> 4, c4 = (f & 15) * 4;
        float4 v = *(const float4*)(in + (size_t)(r0 + row) * C + c0 + c4);
        t[row][c4 + 0] = v.x; t[row][c4 + 1] = v.y;
        t[row][c4 + 2] = v.z; t[row][c4 + 3] = v.w;
    }
    __syncthreads();
    #pragma unroll
    for (int p = 0; p < 8; p++) {
        int w = tid + p * 256;
        int c = w >> 5, rp = (w & 31) * 2;
        float v0 = t[rp][c], v1 = t[rp + 1][c];
        size_t idx = (size_t)(c0 + c) * R + r0 + rp;
        hilo2_store(v0, v1, oh, ol, idx);
    }
}

// ---------------------------------------------------------------------------
// Transpose + fp16 hi/lo convert (for wv)
// ---------------------------------------------------------------------------
__global__ void transcvt_f16hilo_kernel(const float* __restrict__ in, int R, int C,
                                        __half* __restrict__ oh, __half* __restrict__ ol)
{
    __shared__ float t[64][65];
    int c0 = blockIdx.x * 64;
    int r0 = blockIdx.y * 64;
    int tid = threadIdx.x;
    #pragma unroll
    for (int p = 0; p < 4; p++) {
        int f = tid + p * 256;
        int row = f >> 4, c4 = (f & 15) * 4;
        float4 v = *(const float4*)(in + (size_t)(r0 + row) * C + c0 + c4);
        t[row][c4 + 0] = v.x; t[row][c4 + 1] = v.y;
        t[row][c4 + 2] = v.z; t[row][c4 + 3] = v.w;
    }
    __syncthreads();
    #pragma unroll
    for (int p = 0; p < 8; p++) {
        int w = tid + p * 256;
        int c = w >> 5, rp = (w & 31) * 2;
        float v0 = t[rp][c], v1 = t[rp + 1][c];
        size_t idx = (size_t)(c0 + c) * R + r0 + rp;
        hilo2_store(v0, v1, oh, ol, idx);
    }
}

// ---------------------------------------------------------------------------
// Transpose + single fp16 convert (for wo, w1, w2)
// ---------------------------------------------------------------------------
__global__ void transcvt_f16_kernel(const float* __restrict__ in, int R, int C,
                                    __half* __restrict__ o)
{
    __shared__ float t[64][65];
    int c0 = blockIdx.x * 64;
    int r0 = blockIdx.y * 64;
    int tid = threadIdx.x;
    #pragma unroll
    for (int p = 0; p < 4; p++) {
        int f = tid + p * 256;
        int row = f >> 4, c4 = (f & 15) * 4;
        float4 v = *(const float4*)(in + (size_t)(r0 + row) * C + c0 + c4);
        t[row][c4 + 0] = v.x; t[row][c4 + 1] = v.y;
        t[row][c4 + 2] = v.z; t[row][c4 + 3] = v.w;
    }
    __syncthreads();
    #pragma unroll
    for (int p = 0; p < 8; p++) {
        int w = tid + p * 256;
        int c = w >> 5, rp = (w & 31) * 2;
        float v0 = t[rp][c], v1 = t[rp + 1][c];
        size_t idx = (size_t)(c0 + c) * R + r0 + rp;
        *(__half2*)(o + idx) = __halves2half2(__float2half_rn(v0), __float2half_rn(v1));
    }
}

// ---------------------------------------------------------------------------
// Causal softmax -> fp16 hi/lo weights, zero-fill to 128-block end
// ---------------------------------------------------------------------------
__global__ void softmax_kernel(const float* __restrict__ logits,
                               const float* __restrict__ attn_bias,
                               __half* __restrict__ wh, __half* __restrict__ wl)
{
    __shared__ float rowbuf[SEQ];
    __shared__ float red[256];
    int t = blockIdx.x;
    int h = blockIdx.y;
    int tid = threadIdx.x;
    size_t base = ((size_t)h * SEQ + t) * SEQ;
    const float* brow = attn_bias + (size_t)t * SEQ;
    int n = t + 1;
    int blockend = ((t >> 7) + 1) << 7;

    float m = -INFINITY;
    for (int T = tid; T < n; T += 256) {
        float l = logits[base + T] + brow[T];
        rowbuf[T] = l;
        m = fmaxf(m, l);
    }
    red[tid] = m; __syncthreads();
    for (int o = 128; o > 0; o >>= 1) { if (tid < o) red[tid] = fmaxf(red[tid], red[tid + o]); __syncthreads(); }
    m = red[0]; __syncthreads();

    float s = 0.f;
    for (int T = tid; T < n; T += 256) {
        float e = expf(rowbuf[T] - m);
        rowbuf[T] = e;
        s += e;
    }
    red[tid] = s; __syncthreads();
    for (int o = 128; o > 0; o >>= 1) { if (tid < o) red[tid] += red[tid + o]; __syncthreads(); }
    float inv = 1.0f / red[0];

    for (int T = tid; T < n; T += 256)
        split_store(rowbuf[T] * inv, wh, wl, base + T);
    for (int T = n + tid; T < blockend; T += 256) {
        wh[base + T] = __float2half_rn(0.f);
        wl[base + T] = __float2half_rn(0.f);
    }
}

// ---------------------------------------------------------------------------
// Launcher
// ---------------------------------------------------------------------------
extern "C" void kernel_launch(void* const* d_in, const int* in_sizes, int n_in,
                              void* d_out, int out_size)
{
    const float* x         = (const float*)d_in[0];
    const float* attn_bias = (const float*)d_in[1];
    const float* ln_scale  = (const float*)d_in[2];
    const float* ln_offset = (const float*)d_in[3];
    const float* wq        = (const float*)d_in[4];
    const float* wk        = (const float*)d_in[5];
    const float* wv        = (const float*)d_in[6];
    const float* wo        = (const float*)d_in[7];
    const float* w1        = (const float*)d_in[8];
    const float* b1        = (const float*)d_in[9];
    const float* w2        = (const float*)d_in[10];
    const float* b2        = (const float*)d_in[11];
    float* out = (float*)d_out;

    cudaFuncSetAttribute((const void*)gemm_split<bf16, 3, EPI_F32, CM_NONE>,         cudaFuncAttributeMaxDynamicSharedMemorySize, GEMM_SMEM);
    cudaFuncSetAttribute((const void*)gemm_split<bf16, 3, EPI_SCALE, CM_LOGITS>,     cudaFuncAttributeMaxDynamicSharedMemorySize, GEMM_SMEM);
    cudaFuncSetAttribute((const void*)gemm_split<__half, 2, EPI_F32, CM_NONE>,       cudaFuncAttributeMaxDynamicSharedMemorySize, GEMM_SMEM);
    cudaFuncSetAttribute((const void*)gemm_split<__half, 2, EPI_HILO, CM_AV>,        cudaFuncAttributeMaxDynamicSharedMemorySize, GEMM_SMEM);
    cudaFuncSetAttribute((const void*)gemm_split<__half, 2, EPI_GELU_HILO, CM_NONE>, cudaFuncAttributeMaxDynamicSharedMemorySize, GEMM_SMEM);

    bf16 *xnh, *xnl, *qh, *ql, *kh, *kl;
    bf16 *wqth, *wqtl, *wkth, *wktl;
    __half *xnh16, *xnl16, *vth16, *wgh16, *wgl16, *avh16, *avl16, *ffh16, *ffl16;
    __half *wvth16, *wvtl16, *wot16, *w1t16, *w2t16;
    float *logits, *ropetab, *part, *wopart, *ffpart;
    cudaGetSymbolAddress((void**)&xnh, g_xnh);     cudaGetSymbolAddress((void**)&xnl, g_xnl);
    cudaGetSymbolAddress((void**)&xnh16, g_xnh16); cudaGetSymbolAddress((void**)&xnl16, g_xnl16);
    cudaGetSymbolAddress((void**)&qh, g_qh);       cudaGetSymbolAddress((void**)&ql, g_ql);
    cudaGetSymbolAddress((void**)&kh, g_kh);       cudaGetSymbolAddress((void**)&kl, g_kl);
    cudaGetSymbolAddress((void**)&vth16, g_vth16);
    cudaGetSymbolAddress((void**)&logits, g_logits);
    cudaGetSymbolAddress((void**)&wgh16, g_wgh16); cudaGetSymbolAddress((void**)&wgl16, g_wgl16);
    cudaGetSymbolAddress((void**)&avh16, g_avh16); cudaGetSymbolAddress((void**)&avl16, g_avl16);
    cudaGetSymbolAddress((void**)&ffh16, g_ffh16); cudaGetSymbolAddress((void**)&ffl16, g_ffl16);
    cudaGetSymbolAddress((void**)&part, g_part);
    cudaGetSymbolAddress((void**)&wopart, g_wopart);
    cudaGetSymbolAddress((void**)&ffpart, g_ffpart);
    cudaGetSymbolAddress((void**)&ropetab, g_ropetab);
    cudaGetSymbolAddress((void**)&wqth, g_wqth);   cudaGetSymbolAddress((void**)&wqtl, g_wqtl);
    cudaGetSymbolAddress((void**)&wkth, g_wkth);   cudaGetSymbolAddress((void**)&wktl, g_wktl);
    cudaGetSymbolAddress((void**)&wvth16, g_wvth16); cudaGetSymbolAddress((void**)&wvtl16, g_wvtl16);
    cudaGetSymbolAddress((void**)&wot16, g_wot16);
    cudaGetSymbolAddress((void**)&w1t16, g_w1t16);
    cudaGetSymbolAddress((void**)&w2t16, g_w2t16);

    const unsigned long long S = (unsigned long long)SEQ * DM;

    // rope table + weight prep
    ropetab_kernel<<<(SEQ * 32 + 255) / 256, 256>>>(ropetab);
    transcvt_kernel<<<dim3(DM / 64, DM / 64), 256>>>(wq, DM, DM, wqth, wqtl);
    transcvt_kernel<<<dim3(DM / 64, DM / 64), 256>>>(wk, DM, DM, wkth, wktl);
    transcvt_f16hilo_kernel<<<dim3(DM / 64, DM / 64), 256>>>(wv, DM, DM, wvth16, wvtl16);
    transcvt_f16_kernel<<<dim3(DM / 64, DM / 64), 256>>>(wo, DM, DM, wot16);
    transcvt_f16_kernel<<<dim3(DFF / 64, DM / 64), 256>>>(w1, DM, DFF, w1t16);
    transcvt_f16_kernel<<<dim3(DM / 64, DFF / 64), 256>>>(w2, DFF, DM, w2t16);

    ln_kernel<<<SEQ, 256>>>(x, ln_scale, ln_offset, xnh, xnl, xnh16, xnl16);

    int nred2 = (int)(S / 2 / 256);

    // Q projection: bf16 3-pass, split-K=4 -> rope+hilo reduce
    dim3 gProj(DM / BN, SEQ / BM, 4);
    gemm_split<bf16, 3, EPI_F32, CM_NONE><<<gProj, 256, GEMM_SMEM>>>(
        xnh, xnl, DM, 1024ull, wqth, wqtl, DM, 1024ull, 1024,
        part, nullptr, nullptr, DM, S, nullptr, 1.f);
    reduce_rope_hilo_kernel<<<nred2, 256>>>(part, ropetab, qh, ql);

    // K projection: bf16 3-pass
    gemm_split<bf16, 3, EPI_F32, CM_NONE><<<gProj, 256, GEMM_SMEM>>>(
        xnh, xnl, DM, 1024ull, wkth, wktl, DM, 1024ull, 1024,
        part, nullptr, nullptr, DM, S, nullptr, 1.f);
    reduce_rope_hilo_kernel<<<nred2, 256>>>(part, ropetab, kh, kl);

    // vt[DM,SEQ] = wv^T @ xn^T: fp16 2-pass, split-K=4 -> single fp16
    dim3 gVT(SEQ / BN, DM / BM, 4);
    gemm_split<__half, 2, EPI_F32, CM_NONE><<<gVT, 256, GEMM_SMEM>>>(
        wvth16, wvtl16, DM, 1024ull, xnh16, nullptr, DM, 1024ull, 1024,
        part, nullptr, nullptr, SEQ, S, nullptr, 1.f);
    reduce_f16_kernel<<<nred2, 256>>>(part, vth16);

    // logits[h] = q_h @ k_h^T / 16: bf16 3-pass (skip fully masked tiles)
    dim3 gLog(SEQ / BN, SEQ / BM, NH);
    gemm_split<bf16, 3, EPI_SCALE, CM_LOGITS><<<gLog, 256, GEMM_SMEM>>>(
        qh, ql, DM, DH, kh, kl, DM, DH, DH,
        logits, nullptr, nullptr, SEQ, (unsigned long long)SEQ * SEQ,
        nullptr, 0.0625f);

    softmax_kernel<<<dim3(SEQ, NH), 256>>>(logits, attn_bias, wgh16, wgl16);

    // attn_vec[h] = W_h @ v_h: fp16 2-pass (variable K, longest-first)
    dim3 gAV(DH / BN, SEQ / BM, NH);
    gemm_split<__half, 2, EPI_HILO, CM_AV><<<gAV, 256, GEMM_SMEM>>>(
        wgh16, wgl16, SEQ, (unsigned long long)SEQ * SEQ,
        vth16, nullptr, SEQ, (unsigned long long)DH * SEQ, SEQ,
        nullptr, avh16, avl16, DM, DH, nullptr, 1.f);

    // WO: fp16 2-pass, split-K=4 -> wopart (reduced in final)
    gemm_split<__half, 2, EPI_F32, CM_NONE><<<gProj, 256, GEMM_SMEM>>>(
        avh16, avl16, DM, 1024ull, wot16, nullptr, DM, 1024ull, 1024,
        wopart, nullptr, nullptr, DM, S, nullptr, 1.f);

    // FF1: gelu(xn @ w1 + b1) -> fp16 hilo (fp16 2-pass)
    dim3 gFF1(DFF / BN, SEQ / BM, 1);
    gemm_split<__half, 2, EPI_GELU_HILO, CM_NONE><<<gFF1, 256, GEMM_SMEM>>>(
        xnh16, xnl16, DM, 0, w1t16, nullptr, DM, 0, DM,
        nullptr, ffh16, ffl16, DFF, 0, b1, 1.f);

    // FF2: fp16 2-pass, split-K=4 -> ffpart
    dim3 gFF2(DM / BN, SEQ / BM, 4);
    gemm_split<__half, 2, EPI_F32, CM_NONE><<<gFF2, 256, GEMM_SMEM>>>(
        ffh16, ffl16, DFF, 4096ull, w2t16, nullptr, DFF, 4096ull, 4096,
        ffpart, nullptr, nullptr, DM, S, nullptr, 1.f);

    // out = sum4(ffpart) + sum4(wopart) + b2
    reduce_final_kernel<<<(int)(S / 4 / 256), 256>>>(ffpart, wopart, b2, out);
}

// round 14
// speedup vs baseline: 1.6298x; 1.0682x over previous
#include <cuda_runtime.h>
#include <cuda_bf16.h>
#include <cuda_fp16.h>
#include <math.h>
#include <stdint.h>

typedef __nv_bfloat16 bf16;

#define SEQ 2048
#define DM  4096
#define NH  16
#define DH  256
#define DFF 16384

// GEMM tiling: CTA 128x256, BK=64, 8 warps (2x4), warp tile 64x64, 2-stage
#define BM 128
#define BN 256
#define BK 64
#define A_TILE_B 16384
#define B_TILE_B 32768
#define BUF_B    (2 * A_TILE_B + 2 * B_TILE_B)   // 96KB
#define GEMM_SMEM (2 * BUF_B)                    // 192KB

// ---------------------------------------------------------------------------
// Device-global scratch
// ---------------------------------------------------------------------------
__device__ __half g_xnh16[SEQ*DM], g_xnl16[SEQ*DM];
__device__ bf16 g_qh[SEQ*DM], g_ql[SEQ*DM], g_kh[SEQ*DM], g_kl[SEQ*DM];
__device__ __half g_vth16[(size_t)DM*SEQ];
__device__ float g_logits[(size_t)NH*SEQ*SEQ];
__device__ __half g_wgh16[(size_t)NH*SEQ*SEQ], g_wgl16[(size_t)NH*SEQ*SEQ];
__device__ __half g_avh16[SEQ*DM], g_avl16[SEQ*DM];
__device__ __half g_ffh16[(size_t)SEQ*DFF], g_ffl16[(size_t)SEQ*DFF];
__device__ float g_part[(size_t)4*SEQ*DM];       // shared split-K partials (Q/K/vt)
__device__ float g_wopart[(size_t)4*SEQ*DM];     // WO partials
__device__ float g_ffpart[(size_t)4*SEQ*DM];     // FF2 partials
__device__ float g_ropetab[SEQ * 64];
__device__ __half g_wqt16[(size_t)DM*DM];
__device__ __half g_wkt16[(size_t)DM*DM];
__device__ __half g_wvth16[(size_t)DM*DM], g_wvtl16[(size_t)DM*DM];
__device__ __half g_wot16[(size_t)DM*DM];
__device__ __half g_w1t16[(size_t)DFF*DM];
__device__ __half g_w2t16[(size_t)DM*DFF];

// ---------------------------------------------------------------------------
// PTX helpers
// ---------------------------------------------------------------------------
__device__ __forceinline__ uint32_t smem_u32(const void* p) {
    uint32_t r;
    asm("{ .reg .u64 t; cvta.to.shared.u64 t, %1; cvt.u32.u64 %0, t; }" : "=r"(r) : "l"(p));
    return r;
}
__device__ __forceinline__ void cp16(uint32_t dst, const void* src) {
    asm volatile("cp.async.cg.shared.global [%0], [%1], 16;" :: "r"(dst), "l"(src));
}
#define CP_COMMIT() asm volatile("cp.async.commit_group;")
#define CP_WAIT(n)  asm volatile("cp.async.wait_group %0;" :: "n"(n))

#define LDMX4(r, a) \
    asm volatile("ldmatrix.sync.aligned.m8n8.x4.shared.b16 {%0,%1,%2,%3}, [%4];" \
        : "=r"((r)[0]), "=r"((r)[1]), "=r"((r)[2]), "=r"((r)[3]) : "r"(a))

// MMA variants selected by operand-type tag
__device__ __forceinline__ void mma_t(float* c, const uint32_t* a, uint32_t b0, uint32_t b1, bf16*) {
    asm volatile("mma.sync.aligned.m16n8k16.row.col.f32.bf16.bf16.f32 "
        "{%0,%1,%2,%3}, {%4,%5,%6,%7}, {%8,%9}, {%0,%1,%2,%3};"
        : "+f"(c[0]), "+f"(c[1]), "+f"(c[2]), "+f"(c[3])
        : "r"(a[0]), "r"(a[1]), "r"(a[2]), "r"(a[3]), "r"(b0), "r"(b1));
}
__device__ __forceinline__ void mma_t(float* c, const uint32_t* a, uint32_t b0, uint32_t b1, __half*) {
    asm volatile("mma.sync.aligned.m16n8k16.row.col.f32.f16.f16.f32 "
        "{%0,%1,%2,%3}, {%4,%5,%6,%7}, {%8,%9}, {%0,%1,%2,%3};"
        : "+f"(c[0]), "+f"(c[1]), "+f"(c[2]), "+f"(c[3])
        : "r"(a[0]), "r"(a[1]), "r"(a[2]), "r"(a[3]), "r"(b0), "r"(b1));
}

__device__ __forceinline__ void split_store(float v, __half* ph, __half* pl, size_t idx) {
    __half h = __float2half_rn(v);
    ph[idx] = h;
    pl[idx] = __float2half_rn(v - __half2float(h));
}
__device__ __forceinline__ void hilo2_store(float v0, float v1, bf16* ph, bf16* pl, size_t idx) {
    bf16 h0 = __float2bfloat16(v0), h1 = __float2bfloat16(v1);
    __nv_bfloat162 hp; hp.x = h0; hp.y = h1;
    __nv_bfloat162 lp;
    lp.x = __float2bfloat16(v0 - __bfloat162float(h0));
    lp.y = __float2bfloat16(v1 - __bfloat162float(h1));
    *(__nv_bfloat162*)(ph + idx) = hp;
    *(__nv_bfloat162*)(pl + idx) = lp;
}
__device__ __forceinline__ void hilo2_store(float v0, float v1, __half* ph, __half* pl, size_t idx) {
    __half h0 = __float2half_rn(v0), h1 = __float2half_rn(v1);
    *(__half2*)(ph + idx) = __halves2half2(h0, h1);
    *(__half2*)(pl + idx) = __halves2half2(__float2half_rn(v0 - __half2float(h0)),
                                           __float2half_rn(v1 - __half2float(h1)));
}

// Epilogues (compile-time)
#define EPI_F32       0
#define EPI_SCALE     1
#define EPI_HILO      2
#define EPI_GELU_HILO 3
// Causal modes (compile-time)
#define CM_NONE   0
#define CM_LOGITS 1
#define CM_AV     2

__device__ __forceinline__ float gelu_tanh(float v) {
    const float c = 0.7978845608028654f;
    float t = tanhf(c * (v + 0.044715f * v * v * v));
    return 0.5f * v * (1.0f + t);
}

// ---------------------------------------------------------------------------
// Split tensor-core GEMM: C[M,N] = A @ B^T.
// NP=3: A hi/lo, B hi/lo, passes Ah*Bh + Ah*Bl + Al*Bh.
// NP=2: A hi/lo, B single,  passes Ah*Bh + Al*Bh.
// fp32 accumulate; 2-stage cp.async double buffer, BK=64.
// ---------------------------------------------------------------------------
template<typename T, int NP, int EPI, int CMODE>
__global__ void __launch_bounds__(256, 1) gemm_split(
    const T* __restrict__ Ah, const T* __restrict__ Al, int lda, unsigned long long sA,
    const T* __restrict__ Bh, const T* __restrict__ Bl, int ldb, unsigned long long sB,
    int K,
    float* __restrict__ Cf, T* __restrict__ Ch, T* __restrict__ Cl,
    int ldc, unsigned long long sC,
    const float* __restrict__ bias, float scale)
{
    int bmi = (CMODE == CM_AV) ? ((int)gridDim.y - 1 - (int)blockIdx.y) : (int)blockIdx.y;
    int bm = bmi * BM;
    int bn = blockIdx.x * BN;
    if (CMODE == CM_LOGITS && bn >= bm + BM) return;

    Ah += (size_t)blockIdx.z * sA;  Al += (size_t)blockIdx.z * sA;
    Bh += (size_t)blockIdx.z * sB;
    if (NP == 3) Bl += (size_t)blockIdx.z * sB;
    size_t coff = (size_t)blockIdx.z * sC;

    extern __shared__ char smem[];
    uint32_t sb = smem_u32(smem);
    int tid = threadIdx.x;
    int wid = tid >> 5, lane = tid & 31;
    int warp_m = wid >> 2, warp_n = wid & 3;

    int a_r  = ((lane >> 3) & 1) * 8 + (lane & 7);
    int a_cb = (lane >> 4) * 16;
    int b_r  = (lane >> 4) * 8 + (lane & 7);
    int b_cb = ((lane >> 3) & 1) * 16;

    float acc[4][8][4];
    #pragma unroll
    for (int i = 0; i < 4; i++)
        #pragma unroll
        for (int j = 0; j < 8; j++)
            #pragma unroll
            for (int e = 0; e < 4; e++) acc[i][j][e] = 0.f;

#define LOAD_CHUNK(k0, bufb) do {                                              \
        _Pragma("unroll")                                                      \
        for (int t = 0; t < 4; t++) {                                          \
            int ch = tid + t * 256;                                            \
            int row = ch >> 3, c = ch & 7;                                     \
            uint32_t off = row * 128 + ((c * 16) ^ ((row * 16) & 0x70));       \
            cp16((bufb) + off,            Ah + (size_t)(bm + row) * lda + (k0) + c * 8); \
            cp16((bufb) + A_TILE_B + off, Al + (size_t)(bm + row) * lda + (k0) + c * 8); \
        }                                                                      \
        _Pragma("unroll")                                                      \
        for (int t = 0; t < 8; t++) {                                          \
            int ch = tid + t * 256;                                            \
            int row = ch >> 3, c = ch & 7;                                     \
            uint32_t off = row * 128 + ((c * 16) ^ ((row * 16) & 0x70));       \
            cp16((bufb) + 2*A_TILE_B + off, Bh + (size_t)(bn + row) * ldb + (k0) + c * 8); \
            if (NP == 3)                                                       \
                cp16((bufb) + 2*A_TILE_B + B_TILE_B + off, Bl + (size_t)(bn + row) * ldb + (k0) + c * 8); \
        }                                                                      \
    } while (0)

    int Keff = (CMODE == CM_AV) ? (bm + BM) : K;
    int nk = Keff / BK;

    LOAD_CHUNK(0, sb);
    CP_COMMIT();

    for (int i = 0; i < nk; i++) {
        uint32_t bufb = sb + (uint32_t)(i & 1) * BUF_B;
        if (i + 1 < nk) {
            uint32_t nb = sb + (uint32_t)((i + 1) & 1) * BUF_B;
            LOAD_CHUNK((i + 1) * BK, nb);
            CP_COMMIT();
            CP_WAIT(1);
        } else {
            CP_WAIT(0);
        }
        __syncthreads();

        #pragma unroll
        for (int ks = 0; ks < 4; ks++) {
            uint32_t ahf[4][4], alf[4][4];
            #pragma unroll
            for (int mt = 0; mt < 4; mt++) {
                int row = warp_m * 64 + mt * 16 + a_r;
                uint32_t cb = ks * 32 + a_cb;
                uint32_t off = row * 128 + (cb ^ ((row * 16) & 0x70));
                LDMX4(ahf[mt], bufb + off);
                LDMX4(alf[mt], bufb + A_TILE_B + off);
            }
            uint32_t bhf[8][2], blf[8][2];
            #pragma unroll
            for (int p = 0; p < 4; p++) {
                int row = warp_n * 64 + p * 16 + b_r;
                uint32_t cb = ks * 32 + b_cb;
                uint32_t off = row * 128 + (cb ^ ((row * 16) & 0x70));
                uint32_t r[4];
                LDMX4(r, bufb + 2 * A_TILE_B + off);
                bhf[2*p][0] = r[0]; bhf[2*p][1] = r[1];
                bhf[2*p+1][0] = r[2]; bhf[2*p+1][1] = r[3];
                if (NP == 3) {
                    LDMX4(r, bufb + 2 * A_TILE_B + B_TILE_B + off);
                    blf[2*p][0] = r[0]; blf[2*p][1] = r[1];
                    blf[2*p+1][0] = r[2]; blf[2*p+1][1] = r[3];
                }
            }
            #pragma unroll
            for (int mt = 0; mt < 4; mt++)
                #pragma unroll
                for (int nt = 0; nt < 8; nt++) {
                    mma_t(acc[mt][nt], ahf[mt], bhf[nt][0], bhf[nt][1], (T*)nullptr);
                    if (NP == 3)
                        mma_t(acc[mt][nt], ahf[mt], blf[nt][0], blf[nt][1], (T*)nullptr);
                    mma_t(acc[mt][nt], alf[mt], bhf[nt][0], bhf[nt][1], (T*)nullptr);
                }
        }
        __syncthreads();
    }
#undef LOAD_CHUNK

    // Epilogue (template-pruned)
    int g = lane >> 2, tg = lane & 3;
    #pragma unroll
    for (int mt = 0; mt < 4; mt++) {
        #pragma unroll
        for (int nt = 0; nt < 8; nt++) {
            int row0 = bm + warp_m * 64 + mt * 16 + g;
            int col  = bn + warp_n * 64 + nt * 8 + tg * 2;
            float* a = acc[mt][nt];
            #pragma unroll
            for (int half = 0; half < 2; half++) {
                int row = row0 + half * 8;
                float v0 = a[half * 2 + 0], v1 = a[half * 2 + 1];
                size_t idx = coff + (size_t)row * ldc + col;
                if (EPI == EPI_F32) {
                    *(float2*)(Cf + idx) = make_float2(v0, v1);
                } else if (EPI == EPI_SCALE) {
                    *(float2*)(Cf + idx) = make_float2(v0 * scale, v1 * scale);
                } else if (EPI == EPI_HILO) {
                    hilo2_store(v0, v1, Ch, Cl, idx);
                } else if (EPI == EPI_GELU_HILO) {
                    float g0 = gelu_tanh(v0 + bias[col]);
                    float g1 = gelu_tanh(v1 + bias[col + 1]);
                    hilo2_store(g0, g1, Ch, Cl, idx);
                }
            }
        }
    }
}

// ---------------------------------------------------------------------------
// Split-K reduce: sum 4 partials, apply rope, bf16 hi/lo split (Q, K)
// ---------------------------------------------------------------------------
__global__ void reduce_rope_hilo_kernel(const float* __restrict__ part,
                                        const float* __restrict__ ropetab,
                                        bf16* __restrict__ oh, bf16* __restrict__ ol)
{
    size_t i2 = (size_t)blockIdx.x * 256 + threadIdx.x;
    size_t i = i2 * 2;
    const size_t S = (size_t)SEQ * DM;
    float2 p0 = *(const float2*)(part + i);
    float2 p1 = *(const float2*)(part + S + i);
    float2 p2 = *(const float2*)(part + 2 * S + i);
    float2 p3 = *(const float2*)(part + 3 * S + i);
    float v0 = p0.x + p1.x + p2.x + p3.x;
    float v1 = p0.y + p1.y + p2.y + p3.y;
    int col = (int)(i & (DM - 1));
    int row = (int)(i >> 12);
    int d = col & (DH - 1);
    if (d < 64) {
        float s = ropetab[row * 64 + d];
        float c = ropetab[row * 64 + d + 1];
        float n0 = v0 * c - v1 * s;
        float n1 = v1 * c + v0 * s;
        v0 = n0; v1 = n1;
    }
    hilo2_store(v0, v1, oh, ol, i);
}

// ---------------------------------------------------------------------------
// Split-K reduce: sum 4 partials -> single fp16 (vt)
// ---------------------------------------------------------------------------
__global__ void reduce_f16_kernel(const float* __restrict__ part,
                                  __half* __restrict__ o)
{
    size_t i2 = (size_t)blockIdx.x * 256 + threadIdx.x;
    size_t i = i2 * 2;
    const size_t S = (size_t)SEQ * DM;
    float2 p0 = *(const float2*)(part + i);
    float2 p1 = *(const float2*)(part + S + i);
    float2 p2 = *(const float2*)(part + 2 * S + i);
    float2 p3 = *(const float2*)(part + 3 * S + i);
    *(__half2*)(o + i) = __halves2half2(
        __float2half_rn(p0.x + p1.x + p2.x + p3.x),
        __float2half_rn(p0.y + p1.y + p2.y + p3.y));
}

// ---------------------------------------------------------------------------
// Final reduce: out = sum4(ffpart) + sum4(wopart) + b2[col]
// ---------------------------------------------------------------------------
__global__ void reduce_final_kernel(const float* __restrict__ ffp,
                                    const float* __restrict__ wop,
                                    const float* __restrict__ bias,
                                    float* __restrict__ out)
{
    size_t i4 = (size_t)blockIdx.x * 256 + threadIdx.x;
    size_t i = i4 * 4;
    const size_t S = (size_t)SEQ * DM;
    float4 r = *(const float4*)(bias + (i & (DM - 1)));
    #pragma unroll
    for (int z = 0; z < 4; z++) {
        float4 a = *(const float4*)(ffp + z * S + i);
        float4 b = *(const float4*)(wop + z * S + i);
        r.x += a.x + b.x; r.y += a.y + b.y;
        r.z += a.z + b.z; r.w += a.w + b.w;
    }
    *(float4*)(out + i) = r;
}

// ---------------------------------------------------------------------------
// RoPE sin/cos table (fp64)
// ---------------------------------------------------------------------------
__global__ void ropetab_kernel(float* __restrict__ tab)
{
    int idx = blockIdx.x * 256 + threadIdx.x;
    if (idx >= SEQ * 32) return;
    int i = idx & 31, t = idx >> 5;
    double inv = exp(-(double)i * (9.210340371976184 / 32.0));
    double s, c;
    sincos((double)t * inv, &s, &c);
    tab[t * 64 + 2 * i]     = (float)s;
    tab[t * 64 + 2 * i + 1] = (float)c;
}

// ---------------------------------------------------------------------------
// LayerNorm -> fp16 hi/lo
// ---------------------------------------------------------------------------
__global__ void ln_kernel(const float* __restrict__ x,
                          const float* __restrict__ scale,
                          const float* __restrict__ offset,
                          __half* __restrict__ xh16, __half* __restrict__ xl16)
{
    __shared__ float red[256];
    int row = blockIdx.x;
    int tid = threadIdx.x;
    const float* xr = x + (size_t)row * DM;

    float s = 0.f;
    for (int i = tid; i < DM; i += 256) s += xr[i];
    red[tid] = s; __syncthreads();
    for (int o = 128; o > 0; o >>= 1) { if (tid < o) red[tid] += red[tid + o]; __syncthreads(); }
    float mean = red[0] / (float)DM;
    __syncthreads();

    float v = 0.f;
    for (int i = tid; i < DM; i += 256) { float d = xr[i] - mean; v += d * d; }
    red[tid] = v; __syncthreads();
    for (int o = 128; o > 0; o >>= 1) { if (tid < o) red[tid] += red[tid + o]; __syncthreads(); }
    float r = rsqrtf(red[0] / (float)DM + 1e-5f);

    for (int i = tid; i < DM; i += 256) {
        float y = scale[i] * r * (xr[i] - mean) + offset[i];
        split_store(y, xh16, xl16, (size_t)row * DM + i);
    }
}

// ---------------------------------------------------------------------------
// Transpose + fp16 hi/lo convert (for wv)
// ---------------------------------------------------------------------------
__global__ void transcvt_f16hilo_kernel(const float* __restrict__ in, int R, int C,
                                        __half* __restrict__ oh, __half* __restrict__ ol)
{
    __shared__ float t[64][65];
    int c0 = blockIdx.x * 64;
    int r0 = blockIdx.y * 64;
    int tid = threadIdx.x;
    #pragma unroll
    for (int p = 0; p < 4; p++) {
        int f = tid + p * 256;
        int row = f >> 4, c4 = (f & 15) * 4;
        float4 v = *(const float4*)(in + (size_t)(r0 + row) * C + c0 + c4);
        t[row][c4 + 0] = v.x; t[row][c4 + 1] = v.y;
        t[row][c4 + 2] = v.z; t[row][c4 + 3] = v.w;
    }
    __syncthreads();
    #pragma unroll
    for (int p = 0; p < 8; p++) {
        int w = tid + p * 256;
        int c = w >> 5, rp = (w & 31) * 2;
        float v0 = t[rp][c], v1 = t[rp + 1][c];
        size_t idx = (size_t)(c0 + c) * R + r0 + rp;
        hilo2_store(v0, v1, oh, ol, idx);
    }
}

// ---------------------------------------------------------------------------
// Transpose + single fp16 convert (for wq, wk, wo, w1, w2)
// ---------------------------------------------------------------------------
__global__ void transcvt_f16_kernel(const float* __restrict__ in, int R, int C,
                                    __half* __restrict__ o)
{
    __shared__ float t[64][65];
    int c0 = blockIdx.x * 64;
    int r0 = blockIdx.y * 64;
    int tid = threadIdx.x;
    #pragma unroll
    for (int p = 0; p < 4; p++) {
        int f = tid + p * 256;
        int row = f >> 4, c4 = (f & 15) * 4;
        float4 v = *(const float4*)(in + (size_t)(r0 + row) * C + c0 + c4);
        t[row][c4 + 0] = v.x; t[row][c4 + 1] = v.y;
        t[row][c4 + 2] = v.z; t[row][c4 + 3] = v.w;
    }
    __syncthreads();
    #pragma unroll
    for (int p = 0; p < 8; p++) {
        int w = tid + p * 256;
        int c = w >> 5, rp = (w & 31) * 2;
        float v0 = t[rp][c], v1 = t[rp + 1][c];
        size_t idx = (size_t)(c0 + c) * R + r0 + rp;
        *(__half2*)(o + idx) = __halves2half2(__float2half_rn(v0), __float2half_rn(v1));
    }
}

// ---------------------------------------------------------------------------
// Causal softmax -> fp16 hi/lo weights, zero-fill to 128-block end
// ---------------------------------------------------------------------------
__global__ void softmax_kernel(const float* __restrict__ logits,
                               const float* __restrict__ attn_bias,
                               __half* __restrict__ wh, __half* __restrict__ wl)
{
    __shared__ float rowbuf[SEQ];
    __shared__ float red[256];
    int t = blockIdx.x;
    int h = blockIdx.y;
    int tid = threadIdx.x;
    size_t base = ((size_t)h * SEQ + t) * SEQ;
    const float* brow = attn_bias + (size_t)t * SEQ;
    int n = t + 1;
    int blockend = ((t >> 7) + 1) << 7;

    float m = -INFINITY;
    for (int T = tid; T < n; T += 256) {
        float l = logits[base + T] + brow[T];
        rowbuf[T] = l;
        m = fmaxf(m, l);
    }
    red[tid] = m; __syncthreads();
    for (int o = 128; o > 0; o >>= 1) { if (tid < o) red[tid] = fmaxf(red[tid], red[tid + o]); __syncthreads(); }
    m = red[0]; __syncthreads();

    float s = 0.f;
    for (int T = tid; T < n; T += 256) {
        float e = expf(rowbuf[T] - m);
        rowbuf[T] = e;
        s += e;
    }
    red[tid] = s; __syncthreads();
    for (int o = 128; o > 0; o >>= 1) { if (tid < o) red[tid] += red[tid + o]; __syncthreads(); }
    float inv = 1.0f / red[0];

    for (int T = tid; T < n; T += 256)
        split_store(rowbuf[T] * inv, wh, wl, base + T);
    for (int T = n + tid; T < blockend; T += 256) {
        wh[base + T] = __float2half_rn(0.f);
        wl[base + T] = __float2half_rn(0.f);
    }
}

// ---------------------------------------------------------------------------
// Launcher
// ---------------------------------------------------------------------------
extern "C" void kernel_launch(void* const* d_in, const int* in_sizes, int n_in,
                              void* d_out, int out_size)
{
    const float* x         = (const float*)d_in[0];
    const float* attn_bias = (const float*)d_in[1];
    const float* ln_scale  = (const float*)d_in[2];
    const float* ln_offset = (const float*)d_in[3];
    const float* wq        = (const float*)d_in[4];
    const float* wk        = (const float*)d_in[5];
    const float* wv        = (const float*)d_in[6];
    const float* wo        = (const float*)d_in[7];
    const float* w1        = (const float*)d_in[8];
    const float* b1        = (const float*)d_in[9];
    const float* w2        = (const float*)d_in[10];
    const float* b2        = (const float*)d_in[11];
    float* out = (float*)d_out;

    cudaFuncSetAttribute((const void*)gemm_split<bf16, 3, EPI_SCALE, CM_LOGITS>,     cudaFuncAttributeMaxDynamicSharedMemorySize, GEMM_SMEM);
    cudaFuncSetAttribute((const void*)gemm_split<__half, 2, EPI_F32, CM_NONE>,       cudaFuncAttributeMaxDynamicSharedMemorySize, GEMM_SMEM);
    cudaFuncSetAttribute((const void*)gemm_split<__half, 2, EPI_HILO, CM_AV>,        cudaFuncAttributeMaxDynamicSharedMemorySize, GEMM_SMEM);
    cudaFuncSetAttribute((const void*)gemm_split<__half, 2, EPI_GELU_HILO, CM_NONE>, cudaFuncAttributeMaxDynamicSharedMemorySize, GEMM_SMEM);

    bf16 *qh, *ql, *kh, *kl;
    __half *xnh16, *xnl16, *vth16, *wgh16, *wgl16, *avh16, *avl16, *ffh16, *ffl16;
    __half *wqt16, *wkt16, *wvth16, *wvtl16, *wot16, *w1t16, *w2t16;
    float *logits, *ropetab, *part, *wopart, *ffpart;
    cudaGetSymbolAddress((void**)&xnh16, g_xnh16); cudaGetSymbolAddress((void**)&xnl16, g_xnl16);
    cudaGetSymbolAddress((void**)&qh, g_qh);       cudaGetSymbolAddress((void**)&ql, g_ql);
    cudaGetSymbolAddress((void**)&kh, g_kh);       cudaGetSymbolAddress((void**)&kl, g_kl);
    cudaGetSymbolAddress((void**)&vth16, g_vth16);
    cudaGetSymbolAddress((void**)&logits, g_logits);
    cudaGetSymbolAddress((void**)&wgh16, g_wgh16); cudaGetSymbolAddress((void**)&wgl16, g_wgl16);
    cudaGetSymbolAddress((void**)&avh16, g_avh16); cudaGetSymbolAddress((void**)&avl16, g_avl16);
    cudaGetSymbolAddress((void**)&ffh16, g_ffh16); cudaGetSymbolAddress((void**)&ffl16, g_ffl16);
    cudaGetSymbolAddress((void**)&part, g_part);
    cudaGetSymbolAddress((void**)&wopart, g_wopart);
    cudaGetSymbolAddress((void**)&ffpart, g_ffpart);
    cudaGetSymbolAddress((void**)&ropetab, g_ropetab);
    cudaGetSymbolAddress((void**)&wqt16, g_wqt16);
    cudaGetSymbolAddress((void**)&wkt16, g_wkt16);
    cudaGetSymbolAddress((void**)&wvth16, g_wvth16); cudaGetSymbolAddress((void**)&wvtl16, g_wvtl16);
    cudaGetSymbolAddress((void**)&wot16, g_wot16);
    cudaGetSymbolAddress((void**)&w1t16, g_w1t16);
    cudaGetSymbolAddress((void**)&w2t16, g_w2t16);

    const unsigned long long S = (unsigned long long)SEQ * DM;

    // rope table + weight prep
    ropetab_kernel<<<(SEQ * 32 + 255) / 256, 256>>>(ropetab);
    transcvt_f16_kernel<<<dim3(DM / 64, DM / 64), 256>>>(wq, DM, DM, wqt16);
    transcvt_f16_kernel<<<dim3(DM / 64, DM / 64), 256>>>(wk, DM, DM, wkt16);
    transcvt_f16hilo_kernel<<<dim3(DM / 64, DM / 64), 256>>>(wv, DM, DM, wvth16, wvtl16);
    transcvt_f16_kernel<<<dim3(DM / 64, DM / 64), 256>>>(wo, DM, DM, wot16);
    transcvt_f16_kernel<<<dim3(DFF / 64, DM / 64), 256>>>(w1, DM, DFF, w1t16);
    transcvt_f16_kernel<<<dim3(DM / 64, DFF / 64), 256>>>(w2, DFF, DM, w2t16);

    ln_kernel<<<SEQ, 256>>>(x, ln_scale, ln_offset, xnh16, xnl16);

    int nred2 = (int)(S / 2 / 256);

    // Q projection: fp16 2-pass, split-K=4 -> rope+hilo reduce (emits bf16 hi/lo)
    dim3 gProj(DM / BN, SEQ / BM, 4);
    gemm_split<__half, 2, EPI_F32, CM_NONE><<<gProj, 256, GEMM_SMEM>>>(
        xnh16, xnl16, DM, 1024ull, wqt16, nullptr, DM, 1024ull, 1024,
        part, nullptr, nullptr, DM, S, nullptr, 1.f);
    reduce_rope_hilo_kernel<<<nred2, 256>>>(part, ropetab, qh, ql);

    // K projection: fp16 2-pass
    gemm_split<__half, 2, EPI_F32, CM_NONE><<<gProj, 256, GEMM_SMEM>>>(
        xnh16, xnl16, DM, 1024ull, wkt16, nullptr, DM, 1024ull, 1024,
        part, nullptr, nullptr, DM, S, nullptr, 1.f);
    reduce_rope_hilo_kernel<<<nred2, 256>>>(part, ropetab, kh, kl);

    // vt[DM,SEQ] = wv^T @ xn^T: fp16 2-pass (A=wv hi/lo, B=xn single hi), split-K=4
    dim3 gVT(SEQ / BN, DM / BM, 4);
    gemm_split<__half, 2, EPI_F32, CM_NONE><<<gVT, 256, GEMM_SMEM>>>(
        wvth16, wvtl16, DM, 1024ull, xnh16, nullptr, DM, 1024ull, 1024,
        part, nullptr, nullptr, SEQ, S, nullptr, 1.f);
    reduce_f16_kernel<<<nred2, 256>>>(part, vth16);

    // logits[h] = q_h @ k_h^T / 16: bf16 3-pass (skip fully masked tiles)
    dim3 gLog(SEQ / BN, SEQ / BM, NH);
    gemm_split<bf16, 3, EPI_SCALE, CM_LOGITS><<<gLog, 256, GEMM_SMEM>>>(
        qh, ql, DM, DH, kh, kl, DM, DH, DH,
        logits, nullptr, nullptr, SEQ, (unsigned long long)SEQ * SEQ,
        nullptr, 0.0625f);

    softmax_kernel<<<dim3(SEQ, NH), 256>>>(logits, attn_bias, wgh16, wgl16);

    // attn_vec[h] = W_h @ v_h: fp16 2-pass (variable K, longest-first)
    dim3 gAV(DH / BN, SEQ / BM, NH);
    gemm_split<__half, 2, EPI_HILO, CM_AV><<<gAV, 256, GEMM_SMEM>>>(
        wgh16, wgl16, SEQ, (unsigned long long)SEQ * SEQ,
        vth16, nullptr, SEQ, (unsigned long long)DH * SEQ, SEQ,
        nullptr, avh16, avl16, DM, DH, nullptr, 1.f);

    // WO: fp16 2-pass, split-K=4 -> wopart (reduced in final)
    gemm_split<__half, 2, EPI_F32, CM_NONE><<<gProj, 256, GEMM_SMEM>>>(
        avh16, avl16, DM, 1024ull, wot16, nullptr, DM, 1024ull, 1024,
        wopart, nullptr, nullptr, DM, S, nullptr, 1.f);

    // FF1: gelu(xn @ w1 + b1) -> fp16 hilo (fp16 2-pass)
    dim3 gFF1(DFF / BN, SEQ / BM, 1);
    gemm_split<__half, 2, EPI_GELU_HILO, CM_NONE><<<gFF1, 256, GEMM_SMEM>>>(
        xnh16, xnl16, DM, 0, w1t16, nullptr, DM, 0, DM,
        nullptr, ffh16, ffl16, DFF, 0, b1, 1.f);

    // FF2: fp16 2-pass, split-K=4 -> ffpart
    dim3 gFF2(DM / BN, SEQ / BM, 4);
    gemm_split<__half, 2, EPI_F32, CM_NONE><<<gFF2, 256, GEMM_SMEM>>>(
        ffh16, ffl16, DFF, 4096ull, w2t16, nullptr, DFF, 4096ull, 4096,
        ffpart, nullptr, nullptr, DM, S, nullptr, 1.f);

    // out = sum4(ffpart) + sum4(wopart) + b2
    reduce_final_kernel<<<(int)(S / 4 / 256), 256>>>(ffpart, wopart, b2, out);
}

// round 15
// speedup vs baseline: 2.1230x; 1.3026x over previous
#include <cuda_runtime.h>
#include <cuda_bf16.h>
#include <cuda_fp16.h>
#include <math.h>
#include <stdint.h>

typedef __nv_bfloat16 bf16;

#define SEQ 2048
#define DM  4096
#define NH  16
#define DH  256
#define DFF 16384

// GEMM tiling: CTA 128x256, BK=64, 8 warps (2x4), warp tile 64x64, 2-stage
#define BM 128
#define BN 256
#define BK 64
#define A_TILE_B 16384
#define B_TILE_B 32768
#define BUF_B    (2 * A_TILE_B + 2 * B_TILE_B)   // 96KB
#define GEMM_SMEM (2 * BUF_B)                    // 192KB

// ---------------------------------------------------------------------------
// Device-global scratch
// ---------------------------------------------------------------------------
__device__ __half g_xnh16[SEQ*DM], g_xnl16[SEQ*DM];
__device__ bf16 g_qh[SEQ*DM], g_ql[SEQ*DM], g_kh[SEQ*DM], g_kl[SEQ*DM];
__device__ __half g_vth16[(size_t)DM*SEQ];
__device__ float g_logits[(size_t)NH*SEQ*SEQ];
__device__ __half g_wgh16[(size_t)NH*SEQ*SEQ], g_wgl16[(size_t)NH*SEQ*SEQ];
__device__ __half g_avh16[SEQ*DM], g_avl16[SEQ*DM];
__device__ __half g_ff16[(size_t)SEQ*DFF];
__device__ float g_part[(size_t)4*SEQ*DM];       // shared split-K partials (Q/K/vt)
__device__ float g_wopart[(size_t)4*SEQ*DM];     // WO partials
__device__ float g_ffpart[(size_t)4*SEQ*DM];     // FF2 partials
__device__ float g_ropetab[SEQ * 64];
__device__ __half g_wqt16[(size_t)DM*DM];
__device__ __half g_wkt16[(size_t)DM*DM];
__device__ __half g_wvth16[(size_t)DM*DM], g_wvtl16[(size_t)DM*DM];
__device__ __half g_wot16[(size_t)DM*DM];
__device__ __half g_w1t16[(size_t)DFF*DM];
__device__ __half g_w2t16[(size_t)DM*DFF];

// ---------------------------------------------------------------------------
// PTX helpers
// ---------------------------------------------------------------------------
__device__ __forceinline__ uint32_t smem_u32(const void* p) {
    uint32_t r;
    asm("{ .reg .u64 t; cvta.to.shared.u64 t, %1; cvt.u32.u64 %0, t; }" : "=r"(r) : "l"(p));
    return r;
}
__device__ __forceinline__ void cp16(uint32_t dst, const void* src) {
    asm volatile("cp.async.cg.shared.global [%0], [%1], 16;" :: "r"(dst), "l"(src));
}
#define CP_COMMIT() asm volatile("cp.async.commit_group;")
#define CP_WAIT(n)  asm volatile("cp.async.wait_group %0;" :: "n"(n))

#define LDMX4(r, a) \
    asm volatile("ldmatrix.sync.aligned.m8n8.x4.shared.b16 {%0,%1,%2,%3}, [%4];" \
        : "=r"((r)[0]), "=r"((r)[1]), "=r"((r)[2]), "=r"((r)[3]) : "r"(a))

// MMA variants selected by operand-type tag
__device__ __forceinline__ void mma_t(float* c, const uint32_t* a, uint32_t b0, uint32_t b1, bf16*) {
    asm volatile("mma.sync.aligned.m16n8k16.row.col.f32.bf16.bf16.f32 "
        "{%0,%1,%2,%3}, {%4,%5,%6,%7}, {%8,%9}, {%0,%1,%2,%3};"
        : "+f"(c[0]), "+f"(c[1]), "+f"(c[2]), "+f"(c[3])
        : "r"(a[0]), "r"(a[1]), "r"(a[2]), "r"(a[3]), "r"(b0), "r"(b1));
}
__device__ __forceinline__ void mma_t(float* c, const uint32_t* a, uint32_t b0, uint32_t b1, __half*) {
    asm volatile("mma.sync.aligned.m16n8k16.row.col.f32.f16.f16.f32 "
        "{%0,%1,%2,%3}, {%4,%5,%6,%7}, {%8,%9}, {%0,%1,%2,%3};"
        : "+f"(c[0]), "+f"(c[1]), "+f"(c[2]), "+f"(c[3])
        : "r"(a[0]), "r"(a[1]), "r"(a[2]), "r"(a[3]), "r"(b0), "r"(b1));
}

__device__ __forceinline__ void split_store(float v, __half* ph, __half* pl, size_t idx) {
    __half h = __float2half_rn(v);
    ph[idx] = h;
    pl[idx] = __float2half_rn(v - __half2float(h));
}
__device__ __forceinline__ void hilo2_store(float v0, float v1, bf16* ph, bf16* pl, size_t idx) {
    bf16 h0 = __float2bfloat16(v0), h1 = __float2bfloat16(v1);
    __nv_bfloat162 hp; hp.x = h0; hp.y = h1;
    __nv_bfloat162 lp;
    lp.x = __float2bfloat16(v0 - __bfloat162float(h0));
    lp.y = __float2bfloat16(v1 - __bfloat162float(h1));
    *(__nv_bfloat162*)(ph + idx) = hp;
    *(__nv_bfloat162*)(pl + idx) = lp;
}
__device__ __forceinline__ void hilo2_store(float v0, float v1, __half* ph, __half* pl, size_t idx) {
    __half h0 = __float2half_rn(v0), h1 = __float2half_rn(v1);
    *(__half2*)(ph + idx) = __halves2half2(h0, h1);
    *(__half2*)(pl + idx) = __halves2half2(__float2half_rn(v0 - __half2float(h0)),
                                           __float2half_rn(v1 - __half2float(h1)));
}

// Epilogues (compile-time)
#define EPI_F32       0
#define EPI_SCALE     1
#define EPI_HILO      2
#define EPI_GELU_HILO 3
#define EPI_GELU_F16  4
// Causal modes (compile-time)
#define CM_NONE   0
#define CM_LOGITS 1
#define CM_AV     2

__device__ __forceinline__ float gelu_tanh(float v) {
    const float c = 0.7978845608028654f;
    float t = tanhf(c * (v + 0.044715f * v * v * v));
    return 0.5f * v * (1.0f + t);
}

// ---------------------------------------------------------------------------
// Split tensor-core GEMM: C[M,N] = A @ B^T.
// NP=3: A hi/lo, B hi/lo  (Ah*Bh + Ah*Bl + Al*Bh)
// NP=2: A hi/lo, B single (Ah*Bh + Al*Bh)
// NP=1: A single, B single (Ah*Bh)
// fp32 accumulate; 2-stage cp.async double buffer, BK=64.
// ---------------------------------------------------------------------------
template<typename T, int NP, int EPI, int CMODE>
__global__ void __launch_bounds__(256, 1) gemm_split(
    const T* __restrict__ Ah, const T* __restrict__ Al, int lda, unsigned long long sA,
    const T* __restrict__ Bh, const T* __restrict__ Bl, int ldb, unsigned long long sB,
    int K,
    float* __restrict__ Cf, T* __restrict__ Ch, T* __restrict__ Cl,
    int ldc, unsigned long long sC,
    const float* __restrict__ bias, float scale)
{
    int bmi = (CMODE == CM_AV) ? ((int)gridDim.y - 1 - (int)blockIdx.y) : (int)blockIdx.y;
    int bm = bmi * BM;
    int bn = blockIdx.x * BN;
    if (CMODE == CM_LOGITS && bn >= bm + BM) return;

    Ah += (size_t)blockIdx.z * sA;
    if (NP >= 2) Al += (size_t)blockIdx.z * sA;
    Bh += (size_t)blockIdx.z * sB;
    if (NP == 3) Bl += (size_t)blockIdx.z * sB;
    size_t coff = (size_t)blockIdx.z * sC;

    extern __shared__ char smem[];
    uint32_t sb = smem_u32(smem);
    int tid = threadIdx.x;
    int wid = tid >> 5, lane = tid & 31;
    int warp_m = wid >> 2, warp_n = wid & 3;

    int a_r  = ((lane >> 3) & 1) * 8 + (lane & 7);
    int a_cb = (lane >> 4) * 16;
    int b_r  = (lane >> 4) * 8 + (lane & 7);
    int b_cb = ((lane >> 3) & 1) * 16;

    float acc[4][8][4];
    #pragma unroll
    for (int i = 0; i < 4; i++)
        #pragma unroll
        for (int j = 0; j < 8; j++)
            #pragma unroll
            for (int e = 0; e < 4; e++) acc[i][j][e] = 0.f;

#define LOAD_CHUNK(k0, bufb) do {                                              \
        _Pragma("unroll")                                                      \
        for (int t = 0; t < 4; t++) {                                          \
            int ch = tid + t * 256;                                            \
            int row = ch >> 3, c = ch & 7;                                     \
            uint32_t off = row * 128 + ((c * 16) ^ ((row * 16) & 0x70));       \
            cp16((bufb) + off, Ah + (size_t)(bm + row) * lda + (k0) + c * 8);  \
            if (NP >= 2)                                                       \
                cp16((bufb) + A_TILE_B + off, Al + (size_t)(bm + row) * lda + (k0) + c * 8); \
        }                                                                      \
        _Pragma("unroll")                                                      \
        for (int t = 0; t < 8; t++) {                                          \
            int ch = tid + t * 256;                                            \
            int row = ch >> 3, c = ch & 7;                                     \
            uint32_t off = row * 128 + ((c * 16) ^ ((row * 16) & 0x70));       \
            cp16((bufb) + 2*A_TILE_B + off, Bh + (size_t)(bn + row) * ldb + (k0) + c * 8); \
            if (NP == 3)                                                       \
                cp16((bufb) + 2*A_TILE_B + B_TILE_B + off, Bl + (size_t)(bn + row) * ldb + (k0) + c * 8); \
        }                                                                      \
    } while (0)

    int Keff = (CMODE == CM_AV) ? (bm + BM) : K;
    int nk = Keff / BK;

    LOAD_CHUNK(0, sb);
    CP_COMMIT();

    for (int i = 0; i < nk; i++) {
        uint32_t bufb = sb + (uint32_t)(i & 1) * BUF_B;
        if (i + 1 < nk) {
            uint32_t nb = sb + (uint32_t)((i + 1) & 1) * BUF_B;
            LOAD_CHUNK((i + 1) * BK, nb);
            CP_COMMIT();
            CP_WAIT(1);
        } else {
            CP_WAIT(0);
        }
        __syncthreads();

        #pragma unroll
        for (int ks = 0; ks < 4; ks++) {
            uint32_t ahf[4][4], alf[4][4];
            #pragma unroll
            for (int mt = 0; mt < 4; mt++) {
                int row = warp_m * 64 + mt * 16 + a_r;
                uint32_t cb = ks * 32 + a_cb;
                uint32_t off = row * 128 + (cb ^ ((row * 16) & 0x70));
                LDMX4(ahf[mt], bufb + off);
                if (NP >= 2) LDMX4(alf[mt], bufb + A_TILE_B + off);
            }
            uint32_t bhf[8][2], blf[8][2];
            #pragma unroll
            for (int p = 0; p < 4; p++) {
                int row = warp_n * 64 + p * 16 + b_r;
                uint32_t cb = ks * 32 + b_cb;
                uint32_t off = row * 128 + (cb ^ ((row * 16) & 0x70));
                uint32_t r[4];
                LDMX4(r, bufb + 2 * A_TILE_B + off);
                bhf[2*p][0] = r[0]; bhf[2*p][1] = r[1];
                bhf[2*p+1][0] = r[2]; bhf[2*p+1][1] = r[3];
                if (NP == 3) {
                    LDMX4(r, bufb + 2 * A_TILE_B + B_TILE_B + off);
                    blf[2*p][0] = r[0]; blf[2*p][1] = r[1];
                    blf[2*p+1][0] = r[2]; blf[2*p+1][1] = r[3];
                }
            }
            #pragma unroll
            for (int mt = 0; mt < 4; mt++)
                #pragma unroll
                for (int nt = 0; nt < 8; nt++) {
                    mma_t(acc[mt][nt], ahf[mt], bhf[nt][0], bhf[nt][1], (T*)nullptr);
                    if (NP == 3)
                        mma_t(acc[mt][nt], ahf[mt], blf[nt][0], blf[nt][1], (T*)nullptr);
                    if (NP >= 2)
                        mma_t(acc[mt][nt], alf[mt], bhf[nt][0], bhf[nt][1], (T*)nullptr);
                }
        }
        __syncthreads();
    }
#undef LOAD_CHUNK

    // Epilogue (template-pruned)
    int g = lane >> 2, tg = lane & 3;
    #pragma unroll
    for (int mt = 0; mt < 4; mt++) {
        #pragma unroll
        for (int nt = 0; nt < 8; nt++) {
            int row0 = bm + warp_m * 64 + mt * 16 + g;
            int col  = bn + warp_n * 64 + nt * 8 + tg * 2;
            float* a = acc[mt][nt];
            #pragma unroll
            for (int half = 0; half < 2; half++) {
                int row = row0 + half * 8;
                float v0 = a[half * 2 + 0], v1 = a[half * 2 + 1];
                size_t idx = coff + (size_t)row * ldc + col;
                if (EPI == EPI_F32) {
                    *(float2*)(Cf + idx) = make_float2(v0, v1);
                } else if (EPI == EPI_SCALE) {
                    *(float2*)(Cf + idx) = make_float2(v0 * scale, v1 * scale);
                } else if (EPI == EPI_HILO) {
                    hilo2_store(v0, v1, Ch, Cl, idx);
                } else if (EPI == EPI_GELU_HILO) {
                    float g0 = gelu_tanh(v0 + bias[col]);
                    float g1 = gelu_tanh(v1 + bias[col + 1]);
                    hilo2_store(g0, g1, Ch, Cl, idx);
                } else if (EPI == EPI_GELU_F16) {
                    float g0 = gelu_tanh(v0 + bias[col]);
                    float g1 = gelu_tanh(v1 + bias[col + 1]);
                    *(__half2*)((__half*)Ch + idx) =
                        __halves2half2(__float2half_rn(g0), __float2half_rn(g1));
                }
            }
        }
    }
}

// ---------------------------------------------------------------------------
// Split-K reduce: sum 4 partials, apply rope, bf16 hi/lo split (Q, K)
// ---------------------------------------------------------------------------
__global__ void reduce_rope_hilo_kernel(const float* __restrict__ part,
                                        const float* __restrict__ ropetab,
                                        bf16* __restrict__ oh, bf16* __restrict__ ol)
{
    size_t i2 = (size_t)blockIdx.x * 256 + threadIdx.x;
    size_t i = i2 * 2;
    const size_t S = (size_t)SEQ * DM;
    float2 p0 = *(const float2*)(part + i);
    float2 p1 = *(const float2*)(part + S + i);
    float2 p2 = *(const float2*)(part + 2 * S + i);
    float2 p3 = *(const float2*)(part + 3 * S + i);
    float v0 = p0.x + p1.x + p2.x + p3.x;
    float v1 = p0.y + p1.y + p2.y + p3.y;
    int col = (int)(i & (DM - 1));
    int row = (int)(i >> 12);
    int d = col & (DH - 1);
    if (d < 64) {
        float s = ropetab[row * 64 + d];
        float c = ropetab[row * 64 + d + 1];
        float n0 = v0 * c - v1 * s;
        float n1 = v1 * c + v0 * s;
        v0 = n0; v1 = n1;
    }
    hilo2_store(v0, v1, oh, ol, i);
}

// ---------------------------------------------------------------------------
// Split-K reduce: sum 4 partials -> single fp16 (vt)
// ---------------------------------------------------------------------------
__global__ void reduce_f16_kernel(const float* __restrict__ part,
                                  __half* __restrict__ o)
{
    size_t i2 = (size_t)blockIdx.x * 256 + threadIdx.x;
    size_t i = i2 * 2;
    const size_t S = (size_t)SEQ * DM;
    float2 p0 = *(const float2*)(part + i);
    float2 p1 = *(const float2*)(part + S + i);
    float2 p2 = *(const float2*)(part + 2 * S + i);
    float2 p3 = *(const float2*)(part + 3 * S + i);
    *(__half2*)(o + i) = __halves2half2(
        __float2half_rn(p0.x + p1.x + p2.x + p3.x),
        __float2half_rn(p0.y + p1.y + p2.y + p3.y));
}

// ---------------------------------------------------------------------------
// Final reduce: out = sum4(ffpart) + sum4(wopart) + b2[col]
// ---------------------------------------------------------------------------
__global__ void reduce_final_kernel(const float* __restrict__ ffp,
                                    const float* __restrict__ wop,
                                    const float* __restrict__ bias,
                                    float* __restrict__ out)
{
    size_t i4 = (size_t)blockIdx.x * 256 + threadIdx.x;
    size_t i = i4 * 4;
    const size_t S = (size_t)SEQ * DM;
    float4 r = *(const float4*)(bias + (i & (DM - 1)));
    #pragma unroll
    for (int z = 0; z < 4; z++) {
        float4 a = *(const float4*)(ffp + z * S + i);
        float4 b = *(const float4*)(wop + z * S + i);
        r.x += a.x + b.x; r.y += a.y + b.y;
        r.z += a.z + b.z; r.w += a.w + b.w;
    }
    *(float4*)(out + i) = r;
}

// ---------------------------------------------------------------------------
// RoPE sin/cos table (fp64)
// ---------------------------------------------------------------------------
__global__ void ropetab_kernel(float* __restrict__ tab)
{
    int idx = blockIdx.x * 256 + threadIdx.x;
    if (idx >= SEQ * 32) return;
    int i = idx & 31, t = idx >> 5;
    double inv = exp(-(double)i * (9.210340371976184 / 32.0));
    double s, c;
    sincos((double)t * inv, &s, &c);
    tab[t * 64 + 2 * i]     = (float)s;
    tab[t * 64 + 2 * i + 1] = (float)c;
}

// ---------------------------------------------------------------------------
// LayerNorm -> fp16 hi/lo
// ---------------------------------------------------------------------------
__global__ void ln_kernel(const float* __restrict__ x,
                          const float* __restrict__ scale,
                          const float* __restrict__ offset,
                          __half* __restrict__ xh16, __half* __restrict__ xl16)
{
    __shared__ float red[256];
    int row = blockIdx.x;
    int tid = threadIdx.x;
    const float* xr = x + (size_t)row * DM;

    float s = 0.f;
    for (int i = tid; i < DM; i += 256) s += xr[i];
    red[tid] = s; __syncthreads();
    for (int o = 128; o > 0; o >>= 1) { if (tid < o) red[tid] += red[tid + o]; __syncthreads(); }
    float mean = red[0] / (float)DM;
    __syncthreads();

    float v = 0.f;
    for (int i = tid; i < DM; i += 256) { float d = xr[i] - mean; v += d * d; }
    red[tid] = v; __syncthreads();
    for (int o = 128; o > 0; o >>= 1) { if (tid < o) red[tid] += red[tid + o]; __syncthreads(); }
    float r = rsqrtf(red[0] / (float)DM + 1e-5f);

    for (int i = tid; i < DM; i += 256) {
        float y = scale[i] * r * (xr[i] - mean) + offset[i];
        split_store(y, xh16, xl16, (size_t)row * DM + i);
    }
}

// ---------------------------------------------------------------------------
// Transpose + fp16 hi/lo convert (for wv)
// ---------------------------------------------------------------------------
__global__ void transcvt_f16hilo_kernel(const float* __restrict__ in, int R, int C,
                                        __half* __restrict__ oh, __half* __restrict__ ol)
{
    __shared__ float t[64][65];
    int c0 = blockIdx.x * 64;
    int r0 = blockIdx.y * 64;
    int tid = threadIdx.x;
    #pragma unroll
    for (int p = 0; p < 4; p++) {
        int f = tid + p * 256;
        int row = f >> 4, c4 = (f & 15) * 4;
        float4 v = *(const float4*)(in + (size_t)(r0 + row) * C + c0 + c4);
        t[row][c4 + 0] = v.x; t[row][c4 + 1] = v.y;
        t[row][c4 + 2] = v.z; t[row][c4 + 3] = v.w;
    }
    __syncthreads();
    #pragma unroll
    for (int p = 0; p < 8; p++) {
        int w = tid + p * 256;
        int c = w >> 5, rp = (w & 31) * 2;
        float v0 = t[rp][c], v1 = t[rp + 1][c];
        size_t idx = (size_t)(c0 + c) * R + r0 + rp;
        hilo2_store(v0, v1, oh, ol, idx);
    }
}

// ---------------------------------------------------------------------------
// Transpose + single fp16 convert (for wq, wk, wo, w1, w2)
// ---------------------------------------------------------------------------
__global__ void transcvt_f16_kernel(const float* __restrict__ in, int R, int C,
                                    __half* __restrict__ o)
{
    __shared__ float t[64][65];
    int c0 = blockIdx.x * 64;
    int r0 = blockIdx.y * 64;
    int tid = threadIdx.x;
    #pragma unroll
    for (int p = 0; p < 4; p++) {
        int f = tid + p * 256;
        int row = f >> 4, c4 = (f & 15) * 4;
        float4 v = *(const float4*)(in + (size_t)(r0 + row) * C + c0 + c4);
        t[row][c4 + 0] = v.x; t[row][c4 + 1] = v.y;
        t[row][c4 + 2] = v.z; t[row][c4 + 3] = v.w;
    }
    __syncthreads();
    #pragma unroll
    for (int p = 0; p < 8; p++) {
        int w = tid + p * 256;
        int c = w >> 5, rp = (w & 31) * 2;
        float v0 = t[rp][c], v1 = t[rp + 1][c];
        size_t idx = (size_t)(c0 + c) * R + r0 + rp;
        *(__half2*)(o + idx) = __halves2half2(__float2half_rn(v0), __float2half_rn(v1));
    }
}

// ---------------------------------------------------------------------------
// Causal softmax -> fp16 hi/lo weights, zero-fill to 128-block end
// ---------------------------------------------------------------------------
__global__ void softmax_kernel(const float* __restrict__ logits,
                               const float* __restrict__ attn_bias,
                               __half* __restrict__ wh, __half* __restrict__ wl)
{
    __shared__ float rowbuf[SEQ];
    __shared__ float red[256];
    int t = blockIdx.x;
    int h = blockIdx.y;
    int tid = threadIdx.x;
    size_t base = ((size_t)h * SEQ + t) * SEQ;
    const float* brow = attn_bias + (size_t)t * SEQ;
    int n = t + 1;
    int blockend = ((t >> 7) + 1) << 7;

    float m = -INFINITY;
    for (int T = tid; T < n; T += 256) {
        float l = logits[base + T] + brow[T];
        rowbuf[T] = l;
        m = fmaxf(m, l);
    }
    red[tid] = m; __syncthreads();
    for (int o = 128; o > 0; o >>= 1) { if (tid < o) red[tid] = fmaxf(red[tid], red[tid + o]); __syncthreads(); }
    m = red[0]; __syncthreads();

    float s = 0.f;
    for (int T = tid; T < n; T += 256) {
        float e = expf(rowbuf[T] - m);
        rowbuf[T] = e;
        s += e;
    }
    red[tid] = s; __syncthreads();
    for (int o = 128; o > 0; o >>= 1) { if (tid < o) red[tid] += red[tid + o]; __syncthreads(); }
    float inv = 1.0f / red[0];

    for (int T = tid; T < n; T += 256)
        split_store(rowbuf[T] * inv, wh, wl, base + T);
    for (int T = n + tid; T < blockend; T += 256) {
        wh[base + T] = __float2half_rn(0.f);
        wl[base + T] = __float2half_rn(0.f);
    }
}

// ---------------------------------------------------------------------------
// Launcher
// ---------------------------------------------------------------------------
extern "C" void kernel_launch(void* const* d_in, const int* in_sizes, int n_in,
                              void* d_out, int out_size)
{
    const float* x         = (const float*)d_in[0];
    const float* attn_bias = (const float*)d_in[1];
    const float* ln_scale  = (const float*)d_in[2];
    const float* ln_offset = (const float*)d_in[3];
    const float* wq        = (const float*)d_in[4];
    const float* wk        = (const float*)d_in[5];
    const float* wv        = (const float*)d_in[6];
    const float* wo        = (const float*)d_in[7];
    const float* w1        = (const float*)d_in[8];
    const float* b1        = (const float*)d_in[9];
    const float* w2        = (const float*)d_in[10];
    const float* b2        = (const float*)d_in[11];
    float* out = (float*)d_out;

    cudaFuncSetAttribute((const void*)gemm_split<bf16, 3, EPI_SCALE, CM_LOGITS>,    cudaFuncAttributeMaxDynamicSharedMemorySize, GEMM_SMEM);
    cudaFuncSetAttribute((const void*)gemm_split<__half, 2, EPI_F32, CM_NONE>,      cudaFuncAttributeMaxDynamicSharedMemorySize, GEMM_SMEM);
    cudaFuncSetAttribute((const void*)gemm_split<__half, 2, EPI_HILO, CM_AV>,       cudaFuncAttributeMaxDynamicSharedMemorySize, GEMM_SMEM);
    cudaFuncSetAttribute((const void*)gemm_split<__half, 1, EPI_GELU_F16, CM_NONE>, cudaFuncAttributeMaxDynamicSharedMemorySize, GEMM_SMEM);
    cudaFuncSetAttribute((const void*)gemm_split<__half, 1, EPI_F32, CM_NONE>,      cudaFuncAttributeMaxDynamicSharedMemorySize, GEMM_SMEM);

    bf16 *qh, *ql, *kh, *kl;
    __half *xnh16, *xnl16, *vth16, *wgh16, *wgl16, *avh16, *avl16, *ff16;
    __half *wqt16, *wkt16, *wvth16, *wvtl16, *wot16, *w1t16, *w2t16;
    float *logits, *ropetab, *part, *wopart, *ffpart;
    cudaGetSymbolAddress((void**)&xnh16, g_xnh16); cudaGetSymbolAddress((void**)&xnl16, g_xnl16);
    cudaGetSymbolAddress((void**)&qh, g_qh);       cudaGetSymbolAddress((void**)&ql, g_ql);
    cudaGetSymbolAddress((void**)&kh, g_kh);       cudaGetSymbolAddress((void**)&kl, g_kl);
    cudaGetSymbolAddress((void**)&vth16, g_vth16);
    cudaGetSymbolAddress((void**)&logits, g_logits);
    cudaGetSymbolAddress((void**)&wgh16, g_wgh16); cudaGetSymbolAddress((void**)&wgl16, g_wgl16);
    cudaGetSymbolAddress((void**)&avh16, g_avh16); cudaGetSymbolAddress((void**)&avl16, g_avl16);
    cudaGetSymbolAddress((void**)&ff16, g_ff16);
    cudaGetSymbolAddress((void**)&part, g_part);
    cudaGetSymbolAddress((void**)&wopart, g_wopart);
    cudaGetSymbolAddress((void**)&ffpart, g_ffpart);
    cudaGetSymbolAddress((void**)&ropetab, g_ropetab);
    cudaGetSymbolAddress((void**)&wqt16, g_wqt16);
    cudaGetSymbolAddress((void**)&wkt16, g_wkt16);
    cudaGetSymbolAddress((void**)&wvth16, g_wvth16); cudaGetSymbolAddress((void**)&wvtl16, g_wvtl16);
    cudaGetSymbolAddress((void**)&wot16, g_wot16);
    cudaGetSymbolAddress((void**)&w1t16, g_w1t16);
    cudaGetSymbolAddress((void**)&w2t16, g_w2t16);

    const unsigned long long S = (unsigned long long)SEQ * DM;

    // rope table + weight prep
    ropetab_kernel<<<(SEQ * 32 + 255) / 256, 256>>>(ropetab);
    transcvt_f16_kernel<<<dim3(DM / 64, DM / 64), 256>>>(wq, DM, DM, wqt16);
    transcvt_f16_kernel<<<dim3(DM / 64, DM / 64), 256>>>(wk, DM, DM, wkt16);
    transcvt_f16hilo_kernel<<<dim3(DM / 64, DM / 64), 256>>>(wv, DM, DM, wvth16, wvtl16);
    transcvt_f16_kernel<<<dim3(DM / 64, DM / 64), 256>>>(wo, DM, DM, wot16);
    transcvt_f16_kernel<<<dim3(DFF / 64, DM / 64), 256>>>(w1, DM, DFF, w1t16);
    transcvt_f16_kernel<<<dim3(DM / 64, DFF / 64), 256>>>(w2, DFF, DM, w2t16);

    ln_kernel<<<SEQ, 256>>>(x, ln_scale, ln_offset, xnh16, xnl16);

    int nred2 = (int)(S / 2 / 256);

    // Q projection: fp16 2-pass, split-K=4 -> rope+hilo reduce (emits bf16 hi/lo)
    dim3 gProj(DM / BN, SEQ / BM, 4);
    gemm_split<__half, 2, EPI_F32, CM_NONE><<<gProj, 256, GEMM_SMEM>>>(
        xnh16, xnl16, DM, 1024ull, wqt16, nullptr, DM, 1024ull, 1024,
        part, nullptr, nullptr, DM, S, nullptr, 1.f);
    reduce_rope_hilo_kernel<<<nred2, 256>>>(part, ropetab, qh, ql);

    // K projection: fp16 2-pass
    gemm_split<__half, 2, EPI_F32, CM_NONE><<<gProj, 256, GEMM_SMEM>>>(
        xnh16, xnl16, DM, 1024ull, wkt16, nullptr, DM, 1024ull, 1024,
        part, nullptr, nullptr, DM, S, nullptr, 1.f);
    reduce_rope_hilo_kernel<<<nred2, 256>>>(part, ropetab, kh, kl);

    // vt[DM,SEQ] = wv^T @ xn^T: fp16 2-pass, split-K=4 -> single fp16
    dim3 gVT(SEQ / BN, DM / BM, 4);
    gemm_split<__half, 2, EPI_F32, CM_NONE><<<gVT, 256, GEMM_SMEM>>>(
        wvth16, wvtl16, DM, 1024ull, xnh16, nullptr, DM, 1024ull, 1024,
        part, nullptr, nullptr, SEQ, S, nullptr, 1.f);
    reduce_f16_kernel<<<nred2, 256>>>(part, vth16);

    // logits[h] = q_h @ k_h^T / 16: bf16 3-pass (skip fully masked tiles)
    dim3 gLog(SEQ / BN, SEQ / BM, NH);
    gemm_split<bf16, 3, EPI_SCALE, CM_LOGITS><<<gLog, 256, GEMM_SMEM>>>(
        qh, ql, DM, DH, kh, kl, DM, DH, DH,
        logits, nullptr, nullptr, SEQ, (unsigned long long)SEQ * SEQ,
        nullptr, 0.0625f);

    softmax_kernel<<<dim3(SEQ, NH), 256>>>(logits, attn_bias, wgh16, wgl16);

    // attn_vec[h] = W_h @ v_h: fp16 2-pass (variable K, longest-first)
    dim3 gAV(DH / BN, SEQ / BM, NH);
    gemm_split<__half, 2, EPI_HILO, CM_AV><<<gAV, 256, GEMM_SMEM>>>(
        wgh16, wgl16, SEQ, (unsigned long long)SEQ * SEQ,
        vth16, nullptr, SEQ, (unsigned long long)DH * SEQ, SEQ,
        nullptr, avh16, avl16, DM, DH, nullptr, 1.f);

    // WO: fp16 2-pass, split-K=4 -> wopart (reduced in final)
    gemm_split<__half, 2, EPI_F32, CM_NONE><<<gProj, 256, GEMM_SMEM>>>(
        avh16, avl16, DM, 1024ull, wot16, nullptr, DM, 1024ull, 1024,
        wopart, nullptr, nullptr, DM, S, nullptr, 1.f);

    // FF1: gelu(xn @ w1 + b1) -> single fp16 (1-pass fp16)
    dim3 gFF1(DFF / BN, SEQ / BM, 1);
    gemm_split<__half, 1, EPI_GELU_F16, CM_NONE><<<gFF1, 256, GEMM_SMEM>>>(
        xnh16, nullptr, DM, 0, w1t16, nullptr, DM, 0, DM,
        nullptr, ff16, nullptr, DFF, 0, b1, 1.f);

    // FF2: 1-pass fp16, split-K=4 -> ffpart
    dim3 gFF2(DM / BN, SEQ / BM, 4);
    gemm_split<__half, 1, EPI_F32, CM_NONE><<<gFF2, 256, GEMM_SMEM>>>(
        ff16, nullptr, DFF, 4096ull, w2t16, nullptr, DFF, 4096ull, 4096,
        ffpart, nullptr, nullptr, DM, S, nullptr, 1.f);

    // out = sum4(ffpart) + sum4(wopart) + b2
    reduce_final_kernel<<<(int)(S / 4 / 256), 256>>>(ffpart, wopart, b2, out);
}